// round 8
// baseline (speedup 1.0000x reference)
#include <cuda_runtime.h>
#include <cuda_bf16.h>
#include <cstdint>

// ---------------- problem constants ----------------
#define N_MI   100000
#define N_DI   50000
#define N_E    500000
#define N_L    200000
#define F_MI_C 256
#define F_DI_C 128
#define H_C    128

// ---------------- device scratch ----------------
__device__ float g_hA_mi[(size_t)N_MI * 256];
__device__ float g_hB_mi[(size_t)N_MI * 256];
__device__ float g_hA_di[(size_t)N_DI * 256];
__device__ float g_hB_di[(size_t)N_DI * 256];
__device__ float g_t_mi[(size_t)N_MI * 256];
__device__ float g_t_di[(size_t)N_DI * 256];

__device__ int g_rowptr_di[N_DI + 1];
__device__ int g_rowptr_mi[N_MI + 1];
__device__ int g_col_di[N_E];
__device__ int g_col_mi[N_E];
__device__ int g_cnt_di[N_DI];
__device__ int g_cnt_mi[N_MI];

// ---------------- helpers ----------------
__device__ __forceinline__ uint32_t smem_u32(const void* p) {
    uint32_t a;
    asm("{ .reg .u64 t; cvta.to.shared.u64 t, %1; cvt.u32.u64 %0, t; }"
        : "=r"(a) : "l"(p));
    return a;
}

__device__ __forceinline__ unsigned pack_bf16x2(float x0, float x1) {
    unsigned r;
    asm("cvt.rn.bf16x2.f32 %0, %1, %2;" : "=r"(r) : "f"(x1), "f"(x0));
    return r;
}
__device__ __forceinline__ void split2(float x0, float x1, unsigned& hw, unsigned& lw) {
    hw = pack_bf16x2(x0, x1);
    float h0 = __uint_as_float(hw << 16);
    float h1 = __uint_as_float(hw & 0xffff0000u);
    lw = pack_bf16x2(x0 - h0, x1 - h1);
}

__device__ __forceinline__ void mma_bf16(float* c, const unsigned* a, unsigned b0, unsigned b1) {
    asm volatile(
        "mma.sync.aligned.m16n8k16.row.col.f32.bf16.bf16.f32 "
        "{%0,%1,%2,%3}, {%4,%5,%6,%7}, {%8,%9}, {%0,%1,%2,%3};"
        : "+f"(c[0]), "+f"(c[1]), "+f"(c[2]), "+f"(c[3])
        : "r"(a[0]), "r"(a[1]), "r"(a[2]), "r"(a[3]), "r"(b0), "r"(b1));
}

__device__ __forceinline__ void ldsm_x4(uint32_t addr, unsigned& r0, unsigned& r1,
                                        unsigned& r2, unsigned& r3) {
    asm volatile("ldmatrix.sync.aligned.m8n8.x4.shared.b16 {%0,%1,%2,%3}, [%4];"
                 : "=r"(r0), "=r"(r1), "=r"(r2), "=r"(r3) : "r"(addr));
}

#define STS128(addr, a, b, c, d) \
    asm volatile("st.shared.v4.b32 [%0], {%1,%2,%3,%4};" \
                 :: "r"(addr), "r"(a), "r"(b), "r"(c), "r"(d))

// ---------------- bf16x3 mma.sync GEMM, BM=128 x BN=128, warp tile 64x32 ----------
// C[M,N](ld=N) = A0@B^T (+A1@B1^T k-dual) (+bias)(+addend), opt relu.
// nsplit>0 (and !A1): output col < nsplit from B0 (no bias); col >= nsplit from B1
// (bias indexed col-nsplit). Split resolved per B-row so one CTA may span both.
static constexpr uint32_t PLANE = 16384;           // 128 rows x 128B
static constexpr uint32_t STAGE = 4 * PLANE;       // Ah, Al, Bh, Bl
static constexpr int GSMEM = 2 * (int)STAGE + 128; // 131200

__global__ void __launch_bounds__(256, 1) mma_gemm(
    const float* __restrict__ A0, const float* __restrict__ A1,
    const float* __restrict__ B0, const float* __restrict__ B1, int nsplit,
    const float* __restrict__ bias, const float* __restrict__ addend,
    float* __restrict__ C, int M, int N, int K, int relu) {

    extern __shared__ char smem_raw[];
    const uint32_t base = (smem_u32(smem_raw) + 127u) & ~127u;

    const int tid = threadIdx.x, lane = tid & 31, wid = tid >> 5;
    const int wm = wid & 1, wn = wid >> 1;          // warp tile 64(m) x 32(n)
    const int group = lane >> 2, tig = lane & 3;
    const int m0 = blockIdx.y * 128, n0 = blockIdx.x * 128;

    float acc[4][4][4];
    #pragma unroll
    for (int i = 0; i < 4; ++i)
        #pragma unroll
        for (int j = 0; j < 4; ++j)
            #pragma unroll
            for (int q = 0; q < 4; ++q) acc[i][j][q] = 0.f;

    const int kch = K >> 6;
    const int nch = A1 ? 2 * kch : kch;

    float4 ra[8], rb[8];                 // 4 row-pairs each (8 floats per pair)
    const int prow[4] = { tid >> 3, (256 + tid) >> 3, (512 + tid) >> 3, (768 + tid) >> 3 };
    const int ach = tid & 7;

    // B row pointer: resolves k-dual plane or column-split per global row.
    auto brow_ptr = [&](int r, int p) -> const float* {
        int gcol = n0 + r;
        if (A1) return (p ? B1 : B0) + (size_t)gcol * K;
        if (nsplit > 0 && gcol >= nsplit) return B1 + (size_t)(gcol - nsplit) * K;
        return B0 + (size_t)gcol * K;
    };

    auto prefetch = [&](int c) {
        const int p = (c >= kch) ? 1 : 0;
        const int k0 = (c - p * kch) << 6;
        const float* A = p ? A1 : A0;
        #pragma unroll
        for (int it = 0; it < 4; ++it) {
            int gr = m0 + prow[it];
            const float* ap = A + (size_t)gr * K + k0 + ach * 8;
            if (gr < M) {
                ra[2*it]   = *(const float4*)ap;
                ra[2*it+1] = *(const float4*)(ap + 4);
            } else {
                ra[2*it] = ra[2*it+1] = make_float4(0.f, 0.f, 0.f, 0.f);
            }
        }
        #pragma unroll
        for (int it = 0; it < 4; ++it) {
            const float* bp = brow_ptr(prow[it], p) + k0 + ach * 8;
            rb[2*it]   = *(const float4*)bp;
            rb[2*it+1] = *(const float4*)(bp + 4);
        }
    };

    auto store_stage = [&](int st) {
        const uint32_t sah = base + (uint32_t)st * STAGE;
        const uint32_t sal = sah + PLANE;
        const uint32_t sbh = sah + 2 * PLANE;
        const uint32_t sbl = sah + 3 * PLANE;
        #pragma unroll
        for (int it = 0; it < 4; ++it) {
            int r = prow[it];
            uint32_t off = (uint32_t)(r * 128 + ((ach ^ (r & 7)) << 4));
            unsigned h0,l0,h1,l1,h2,l2,h3,l3;
            split2(ra[2*it].x,   ra[2*it].y,   h0, l0);
            split2(ra[2*it].z,   ra[2*it].w,   h1, l1);
            split2(ra[2*it+1].x, ra[2*it+1].y, h2, l2);
            split2(ra[2*it+1].z, ra[2*it+1].w, h3, l3);
            STS128(sah + off, h0, h1, h2, h3);
            STS128(sal + off, l0, l1, l2, l3);
        }
        #pragma unroll
        for (int it = 0; it < 4; ++it) {
            int r = prow[it];
            uint32_t off = (uint32_t)(r * 128 + ((ach ^ (r & 7)) << 4));
            unsigned h0,l0,h1,l1,h2,l2,h3,l3;
            split2(rb[2*it].x,   rb[2*it].y,   h0, l0);
            split2(rb[2*it].z,   rb[2*it].w,   h1, l1);
            split2(rb[2*it+1].x, rb[2*it+1].y, h2, l2);
            split2(rb[2*it+1].z, rb[2*it+1].w, h3, l3);
            STS128(sbh + off, h0, h1, h2, h3);
            STS128(sbl + off, l0, l1, l2, l3);
        }
    };

    auto mma_stage = [&](int st) {
        const uint32_t sah = base + (uint32_t)st * STAGE;
        const uint32_t sal = sah + PLANE;
        const uint32_t sbh = sah + 2 * PLANE;
        const uint32_t sbl = sah + 3 * PLANE;
        const int lrow = lane & 15, lsel = lane >> 4;
        #pragma unroll
        for (int s = 0; s < 4; ++s) {
            const int ch = 2 * s + lsel;
            unsigned bh[2][4], blo[2][4];
            #pragma unroll
            for (int jl = 0; jl < 2; ++jl) {
                int r = wn * 32 + jl * 16 + lrow;
                uint32_t off = (uint32_t)(r * 128 + ((ch ^ (r & 7)) << 4));
                ldsm_x4(sbh + off, bh[jl][0], bh[jl][1], bh[jl][2], bh[jl][3]);
                ldsm_x4(sbl + off, blo[jl][0], blo[jl][1], blo[jl][2], blo[jl][3]);
            }
            unsigned ah[4][4], al[4][4];
            #pragma unroll
            for (int i = 0; i < 4; ++i) {
                int r = wm * 64 + i * 16 + lrow;
                uint32_t off = (uint32_t)(r * 128 + ((ch ^ (r & 7)) << 4));
                ldsm_x4(sah + off, ah[i][0], ah[i][1], ah[i][2], ah[i][3]);
                ldsm_x4(sal + off, al[i][0], al[i][1], al[i][2], al[i][3]);
            }
            #pragma unroll
            for (int pass = 0; pass < 3; ++pass) {
                #pragma unroll
                for (int i = 0; i < 4; ++i)
                    #pragma unroll
                    for (int j = 0; j < 4; ++j) {
                        const int jl = j >> 1, sel = j & 1;
                        const unsigned* af = (pass == 1) ? al[i] : ah[i];
                        const unsigned* bf = (pass == 2) ? blo[jl] : bh[jl];
                        mma_bf16(acc[i][j], af, bf[sel], bf[sel + 2]);
                    }
            }
        }
    };

    prefetch(0);
    store_stage(0);
    __syncthreads();

    for (int c = 0; c < nch; ++c) {
        if (c + 1 < nch) prefetch(c + 1);
        mma_stage(c & 1);
        if (c + 1 < nch) store_stage((c + 1) & 1);
        __syncthreads();
    }

    // epilogue
    #pragma unroll
    for (int i = 0; i < 4; ++i) {
        int row = m0 + wm * 64 + i * 16 + group;
        #pragma unroll
        for (int j = 0; j < 4; ++j) {
            int nl = wn * 32 + j * 8 + 2 * tig;
            int colg = n0 + nl;
            float b0 = 0.f, b1 = 0.f;
            if (bias) {
                if (nsplit > 0 && !A1) {
                    if (colg >= nsplit) {
                        b0 = __ldg(bias + colg - nsplit);
                        b1 = __ldg(bias + colg - nsplit + 1);
                    }
                } else {
                    b0 = __ldg(bias + colg);
                    b1 = __ldg(bias + colg + 1);
                }
            }
            if (row < M) {
                float v0 = acc[i][j][0] + b0, v1 = acc[i][j][1] + b1;
                if (addend) {
                    const float* ap = addend + (size_t)row * N + colg;
                    v0 += ap[0]; v1 += ap[1];
                }
                if (relu) { v0 = fmaxf(v0, 0.f); v1 = fmaxf(v1, 0.f); }
                *(float2*)(C + (size_t)row * N + colg) = make_float2(v0, v1);
            }
            int row2 = row + 8;
            if (row2 < M) {
                float v0 = acc[i][j][2] + b0, v1 = acc[i][j][3] + b1;
                if (addend) {
                    const float* ap = addend + (size_t)row2 * N + colg;
                    v0 += ap[0]; v1 += ap[1];
                }
                if (relu) { v0 = fmaxf(v0, 0.f); v1 = fmaxf(v1, 0.f); }
                *(float2*)(C + (size_t)row2 * N + colg) = make_float2(v0, v1);
            }
        }
    }
}

// ---------------- CSR build ----------------
__global__ void count_edges(const int* __restrict__ src, const int* __restrict__ dst, int e) {
    int i = blockIdx.x * blockDim.x + threadIdx.x;
    if (i < e) {
        atomicAdd(&g_cnt_mi[src[i]], 1);
        atomicAdd(&g_cnt_di[dst[i]], 1);
    }
}

__global__ void scan2() {
    const int* cnt = blockIdx.x ? g_cnt_mi : g_cnt_di;
    int* rowptr    = blockIdx.x ? g_rowptr_mi : g_rowptr_di;
    int n          = blockIdx.x ? N_MI : N_DI;

    __shared__ int warpsum[32];
    __shared__ int s_running;
    int tid = threadIdx.x, lane = tid & 31, wid = tid >> 5;
    if (tid == 0) s_running = 0;
    __syncthreads();

    for (int base = 0; base < n; base += 1024) {
        int i = base + tid;
        int v = (i < n) ? cnt[i] : 0;
        int x = v;
        #pragma unroll
        for (int off = 1; off < 32; off <<= 1) {
            int t = __shfl_up_sync(0xffffffffu, x, off);
            if (lane >= off) x += t;
        }
        if (lane == 31) warpsum[wid] = x;
        __syncthreads();
        if (wid == 0) {
            int w = warpsum[lane];
            #pragma unroll
            for (int off = 1; off < 32; off <<= 1) {
                int t = __shfl_up_sync(0xffffffffu, w, off);
                if (lane >= off) w += t;
            }
            warpsum[lane] = w;
        }
        __syncthreads();
        int incl = x + (wid ? warpsum[wid - 1] : 0);
        int run = s_running;
        if (i < n) rowptr[i] = run + incl - v;
        __syncthreads();
        if (tid == 1023) s_running = run + warpsum[31];
        __syncthreads();
    }
    if (threadIdx.x == 0) rowptr[n] = s_running;
}

__global__ void fill_edges(const int* __restrict__ src, const int* __restrict__ dst, int e) {
    int i = blockIdx.x * blockDim.x + threadIdx.x;
    if (i < e) {
        int s = src[i], d = dst[i];
        int pd = g_rowptr_di[d] + atomicAdd(&g_cnt_di[d], 1);
        g_col_di[pd] = s;
        int pm = g_rowptr_mi[s] + atomicAdd(&g_cnt_mi[s], 1);
        g_col_mi[pm] = d;
    }
}

// ---------------- aggregation kernels ----------------
__global__ void agg_plain128(const float* __restrict__ x, const int* __restrict__ rowptr,
                             const int* __restrict__ col, float* __restrict__ out, int n) {
    int warp = (blockIdx.x * blockDim.x + threadIdx.x) >> 5;
    int lane = threadIdx.x & 31;
    if (warp >= n) return;
    int s = rowptr[warp], e = rowptr[warp + 1];
    float4 acc = make_float4(0.f, 0.f, 0.f, 0.f);
    int i = s;
    for (; i + 1 < e; i += 2) {
        float4 a = __ldg((const float4*)(x + (size_t)col[i] * 128) + lane);
        float4 b = __ldg((const float4*)(x + (size_t)col[i + 1] * 128) + lane);
        acc.x += a.x + b.x; acc.y += a.y + b.y;
        acc.z += a.z + b.z; acc.w += a.w + b.w;
    }
    if (i < e) {
        float4 a = __ldg((const float4*)(x + (size_t)col[i] * 128) + lane);
        acc.x += a.x; acc.y += a.y; acc.z += a.z; acc.w += a.w;
    }
    float inv = 1.f / fmaxf((float)(e - s), 1.f);
    acc.x *= inv; acc.y *= inv; acc.z *= inv; acc.w *= inv;
    ((float4*)(out + (size_t)warp * 128))[lane] = acc;
}

// L2: out = relu(mean(srcC[:,0:128]) + rootC[:,128:256]); stride 256
__global__ void agg_fused128(const float* __restrict__ srcC, const float* __restrict__ rootC,
                             const int* __restrict__ rowptr, const int* __restrict__ col,
                             float* __restrict__ out, int n) {
    int warp = (blockIdx.x * blockDim.x + threadIdx.x) >> 5;
    int lane = threadIdx.x & 31;
    if (warp >= n) return;
    int s = rowptr[warp], e = rowptr[warp + 1];
    float4 acc = make_float4(0.f, 0.f, 0.f, 0.f);
    int i = s;
    for (; i + 1 < e; i += 2) {
        float4 a = __ldg((const float4*)(srcC + (size_t)col[i] * 256) + lane);
        float4 b = __ldg((const float4*)(srcC + (size_t)col[i + 1] * 256) + lane);
        acc.x += a.x + b.x; acc.y += a.y + b.y;
        acc.z += a.z + b.z; acc.w += a.w + b.w;
    }
    if (i < e) {
        float4 a = __ldg((const float4*)(srcC + (size_t)col[i] * 256) + lane);
        acc.x += a.x; acc.y += a.y; acc.z += a.z; acc.w += a.w;
    }
    float inv = 1.f / fmaxf((float)(e - s), 1.f);
    float4 r = __ldg((const float4*)(rootC + (size_t)warp * 256 + 128) + lane);
    float4 v;
    v.x = fmaxf(acc.x * inv + r.x, 0.f);
    v.y = fmaxf(acc.y * inv + r.y, 0.f);
    v.z = fmaxf(acc.z * inv + r.z, 0.f);
    v.w = fmaxf(acc.w * inv + r.w, 0.f);
    ((float4*)(out + (size_t)warp * 128))[lane] = v;
}

// L3: out = mean(srcC[:,0:64]) + rootC[:,64:128]; stride 128, width 64
__global__ void agg_fused64(const float* __restrict__ srcC, const float* __restrict__ rootC,
                            const int* __restrict__ rowptr, const int* __restrict__ col,
                            float* __restrict__ out, int n) {
    int warp = (blockIdx.x * blockDim.x + threadIdx.x) >> 5;
    int lane = threadIdx.x & 31;
    if (warp >= n) return;
    int s = rowptr[warp], e = rowptr[warp + 1];
    float2 acc = make_float2(0.f, 0.f);
    int i = s;
    for (; i + 1 < e; i += 2) {
        float2 a = __ldg((const float2*)(srcC + (size_t)col[i] * 128) + lane);
        float2 b = __ldg((const float2*)(srcC + (size_t)col[i + 1] * 128) + lane);
        acc.x += a.x + b.x; acc.y += a.y + b.y;
    }
    if (i < e) {
        float2 a = __ldg((const float2*)(srcC + (size_t)col[i] * 128) + lane);
        acc.x += a.x; acc.y += a.y;
    }
    float inv = 1.f / fmaxf((float)(e - s), 1.f);
    float2 r = __ldg((const float2*)(rootC + (size_t)warp * 128 + 64) + lane);
    float2 v = make_float2(acc.x * inv + r.x, acc.y * inv + r.y);
    ((float2*)(out + (size_t)warp * 64))[lane] = v;
}

// ---------------- classifier ----------------
__global__ void dot64(const float* __restrict__ hmi, const float* __restrict__ hdi,
                      const int* __restrict__ lsrc, const int* __restrict__ ldst,
                      float* __restrict__ out, int L) {
    int warp = (blockIdx.x * blockDim.x + threadIdx.x) >> 5;
    int lane = threadIdx.x & 31;
    if (warp >= L) return;
    const float2* a = (const float2*)(hmi + (size_t)lsrc[warp] * 64);
    const float2* b = (const float2*)(hdi + (size_t)ldst[warp] * 64);
    float2 av = a[lane], bv = b[lane];
    float p = av.x * bv.x + av.y * bv.y;
    #pragma unroll
    for (int off = 16; off; off >>= 1) p += __shfl_down_sync(0xffffffffu, p, off);
    if (lane == 0) out[warp] = p;
}

// ---------------- host orchestration ----------------
static inline void gemm(const float* A0, const float* A1,
                        const float* B0, const float* B1, int nsplit,
                        const float* bias, const float* addend,
                        float* C, int M, int N, int K, int relu) {
    mma_gemm<<<dim3(N / 128, (M + 127) / 128), 256, GSMEM>>>(
        A0, A1, B0, B1, nsplit, bias, addend, C, M, N, K, relu);
}

extern "C" void kernel_launch(void* const* d_in, const int* in_sizes, int n_in,
                              void* d_out, int out_size) {
    const float* x_mi   = (const float*)d_in[0];
    const float* x_di   = (const float*)d_in[1];
    const float* W_mi   = (const float*)d_in[2];
    const float* b_mi   = (const float*)d_in[3];
    const float* W_di   = (const float*)d_in[4];
    const float* b_di   = (const float*)d_in[5];
    const float* emb_mi = (const float*)d_in[6];
    const float* emb_di = (const float*)d_in[7];
    const float *Wl[3][2], *bl[3][2], *Wr[3][2];   // [layer][0=md,1=dm]
    for (int i = 0; i < 3; ++i)
        for (int r = 0; r < 2; ++r) {
            int base = 8 + i * 6 + r * 3;
            Wl[i][r] = (const float*)d_in[base];
            bl[i][r] = (const float*)d_in[base + 1];
            Wr[i][r] = (const float*)d_in[base + 2];
        }
    const int* edge_src  = (const int*)d_in[26];
    const int* edge_dst  = (const int*)d_in[27];
    const int* label_src = (const int*)d_in[28];
    const int* label_dst = (const int*)d_in[29];
    float* out = (float*)d_out;

    cudaFuncSetAttribute(mma_gemm, cudaFuncAttributeMaxDynamicSharedMemorySize, GSMEM);

    float *hA_mi, *hB_mi, *hA_di, *hB_di, *t_mi, *t_di;
    int *rp_di, *rp_mi, *col_di, *col_mi, *cnt_di, *cnt_mi;
    cudaGetSymbolAddress((void**)&hA_mi, g_hA_mi);
    cudaGetSymbolAddress((void**)&hB_mi, g_hB_mi);
    cudaGetSymbolAddress((void**)&hA_di, g_hA_di);
    cudaGetSymbolAddress((void**)&hB_di, g_hB_di);
    cudaGetSymbolAddress((void**)&t_mi, g_t_mi);
    cudaGetSymbolAddress((void**)&t_di, g_t_di);
    cudaGetSymbolAddress((void**)&rp_di, g_rowptr_di);
    cudaGetSymbolAddress((void**)&rp_mi, g_rowptr_mi);
    cudaGetSymbolAddress((void**)&col_di, g_col_di);
    cudaGetSymbolAddress((void**)&col_mi, g_col_mi);
    cudaGetSymbolAddress((void**)&cnt_di, g_cnt_di);
    cudaGetSymbolAddress((void**)&cnt_mi, g_cnt_mi);

    const int EB = (N_E + 255) / 256;
    const int AG_DI = (N_DI + 7) / 8;
    const int AG_MI = (N_MI + 7) / 8;

    // ---- CSR build ----
    cudaMemsetAsync(cnt_di, 0, N_DI * sizeof(int));
    cudaMemsetAsync(cnt_mi, 0, N_MI * sizeof(int));
    count_edges<<<EB, 256>>>(edge_src, edge_dst, N_E);
    scan2<<<2, 1024>>>();
    cudaMemsetAsync(cnt_di, 0, N_DI * sizeof(int));
    cudaMemsetAsync(cnt_mi, 0, N_MI * sizeof(int));
    fill_edges<<<EB, 256>>>(edge_src, edge_dst, N_E);

    // ---- input projections: h = x @ W^T + b + emb ----
    gemm(x_mi, nullptr, W_mi, nullptr, 0, b_mi, emb_mi, hA_mi, N_MI, 128, F_MI_C, 0);
    gemm(x_di, nullptr, W_di, nullptr, 0, b_di, emb_di, hA_di, N_DI, 128, F_DI_C, 0);

    // ---- Layer 1 (agg-first, 128 -> 256, relu), k-dual ----
    agg_plain128<<<AG_DI, 256>>>(hA_mi, rp_di, col_di, t_di, N_DI);
    agg_plain128<<<AG_MI, 256>>>(hA_di, rp_mi, col_mi, t_mi, N_MI);
    gemm(t_di, hA_di, Wl[0][0], Wr[0][0], 0, bl[0][0], nullptr, hB_di, N_DI, 256, 128, 1);
    gemm(t_mi, hA_mi, Wl[0][1], Wr[0][1], 0, bl[0][1], nullptr, hB_mi, N_MI, 256, 128, 1);

    // ---- Layer 2 (fused transform+root, 256 -> 128, relu) ----
    gemm(hB_mi, nullptr, Wl[1][0], Wr[1][1], 128, bl[1][1], nullptr, t_mi, N_MI, 256, 256, 0);
    gemm(hB_di, nullptr, Wl[1][1], Wr[1][0], 128, bl[1][0], nullptr, t_di, N_DI, 256, 256, 0);
    agg_fused128<<<AG_DI, 256>>>(t_mi, t_di, rp_di, col_di, hA_di, N_DI);
    agg_fused128<<<AG_MI, 256>>>(t_di, t_mi, rp_mi, col_mi, hA_mi, N_MI);

    // ---- Layer 3 (fused transform+root, 128 -> 64, no relu) ----
    gemm(hA_mi, nullptr, Wl[2][0], Wr[2][1], 64, bl[2][1], nullptr, t_mi, N_MI, 128, 128, 0);
    gemm(hA_di, nullptr, Wl[2][1], Wr[2][0], 64, bl[2][0], nullptr, t_di, N_DI, 128, 128, 0);
    agg_fused64<<<AG_DI, 256>>>(t_mi, t_di, rp_di, col_di, hB_di, N_DI);
    agg_fused64<<<AG_MI, 256>>>(t_di, t_mi, rp_mi, col_mi, hB_mi, N_MI);

    // ---- classifier ----
    dot64<<<(N_L + 7) / 8, 256>>>(hB_mi, hB_di, label_src, label_dst, out, N_L);
}

// round 9
// speedup vs baseline: 1.1254x; 1.1254x over previous
#include <cuda_runtime.h>
#include <cuda_bf16.h>
#include <cstdint>

// ---------------- problem constants ----------------
#define N_MI   100000
#define N_DI   50000
#define N_E    500000
#define N_L    200000

static constexpr int NB_DI = (N_DI + 1023) / 1024;   // 49
static constexpr int NB_MI = (N_MI + 1023) / 1024;   // 98

// ---------------- device scratch ----------------
__device__ float g_hA_mi[(size_t)N_MI * 256];
__device__ float g_hB_mi[(size_t)N_MI * 256];
__device__ float g_hA_di[(size_t)N_DI * 256];
__device__ float g_hB_di[(size_t)N_DI * 256];
__device__ float g_t_mi[(size_t)N_MI * 256];
__device__ float g_t_di[(size_t)N_DI * 256];

__device__ int g_rowptr_di[N_DI + 1];
__device__ int g_rowptr_mi[N_MI + 1];
__device__ int g_col_di[N_E];
__device__ int g_col_mi[N_E];
__device__ int g_cnt_di[N_DI];
__device__ int g_cnt_mi[N_MI];
__device__ int g_bsum_di[NB_DI];
__device__ int g_bsum_mi[NB_MI];

// ---------------- helpers ----------------
__device__ __forceinline__ uint32_t smem_u32(const void* p) {
    uint32_t a;
    asm("{ .reg .u64 t; cvta.to.shared.u64 t, %1; cvt.u32.u64 %0, t; }"
        : "=r"(a) : "l"(p));
    return a;
}

__device__ __forceinline__ unsigned pack_bf16x2(float x0, float x1) {
    unsigned r;
    asm("cvt.rn.bf16x2.f32 %0, %1, %2;" : "=r"(r) : "f"(x1), "f"(x0));
    return r;
}
__device__ __forceinline__ void split2(float x0, float x1, unsigned& hw, unsigned& lw) {
    hw = pack_bf16x2(x0, x1);
    float h0 = __uint_as_float(hw << 16);
    float h1 = __uint_as_float(hw & 0xffff0000u);
    lw = pack_bf16x2(x0 - h0, x1 - h1);
}

__device__ __forceinline__ void mma_bf16(float* c, const unsigned* a, unsigned b0, unsigned b1) {
    asm volatile(
        "mma.sync.aligned.m16n8k16.row.col.f32.bf16.bf16.f32 "
        "{%0,%1,%2,%3}, {%4,%5,%6,%7}, {%8,%9}, {%0,%1,%2,%3};"
        : "+f"(c[0]), "+f"(c[1]), "+f"(c[2]), "+f"(c[3])
        : "r"(a[0]), "r"(a[1]), "r"(a[2]), "r"(a[3]), "r"(b0), "r"(b1));
}

__device__ __forceinline__ void ldsm_x4(uint32_t addr, unsigned& r0, unsigned& r1,
                                        unsigned& r2, unsigned& r3) {
    asm volatile("ldmatrix.sync.aligned.m8n8.x4.shared.b16 {%0,%1,%2,%3}, [%4];"
                 : "=r"(r0), "=r"(r1), "=r"(r2), "=r"(r3) : "r"(addr));
}

#define STS128(addr, a, b, c, d) \
    asm volatile("st.shared.v4.b32 [%0], {%1,%2,%3,%4};" \
                 :: "r"(addr), "r"(a), "r"(b), "r"(c), "r"(d))

// ---------------- paired bf16x3 mma.sync GEMM, BM=64 x BN=64, KC=64 ----------------
// Two independent GEMM problems (same N, possibly different M/K/ptrs) in one launch.
// C[M,N](ld=N) = A0@B0^T (+A1@B1^T k-dual) (+bias)(+addend), opt relu.
// nsplit>0 (and !A1): output col < nsplit from B0 (no bias); col >= nsplit from B1
// (bias indexed col-nsplit).
struct GArgs {
    const float *A0, *A1, *B0, *B1;
    int nsplit;
    const float *bias, *addend;
    float* C;
    int M, N, K, relu;
};

static constexpr uint32_t APL = 64 * 128;          // 8 KB plane (64 rows x 128B)
static constexpr uint32_t STAGE = 4 * APL;         // Ah, Al, Bh, Bl = 32 KB
static constexpr int GSMEM = 2 * (int)STAGE + 128; // 65664 -> 3 CTAs/SM

__global__ void __launch_bounds__(256, 3) mma_gemm2(GArgs g0, GArgs g1, int yb0) {
    const GArgs& g = (blockIdx.y < (unsigned)yb0) ? g0 : g1;
    const int my = (blockIdx.y < (unsigned)yb0) ? blockIdx.y : blockIdx.y - yb0;

    extern __shared__ char smem_raw[];
    const uint32_t base = (smem_u32(smem_raw) + 127u) & ~127u;

    const int tid = threadIdx.x, lane = tid & 31, wid = tid >> 5;
    const int wm = wid & 1, wn = wid >> 1;          // warp tile 32(m) x 16(n)
    const int group = lane >> 2, tig = lane & 3;
    const int m0 = my * 64, n0 = blockIdx.x * 64;
    const int M = g.M, N = g.N, K = g.K;

    float acc[2][2][4];
    #pragma unroll
    for (int i = 0; i < 2; ++i)
        #pragma unroll
        for (int j = 0; j < 2; ++j)
            #pragma unroll
            for (int q = 0; q < 4; ++q) acc[i][j][q] = 0.f;

    const int kch = K >> 6;
    const int nch = g.A1 ? 2 * kch : kch;

    float4 ra[4];                       // A staging: 2 row-sweeps x 8 floats
    const int arow[2] = { tid >> 3, (256 + tid) >> 3 };
    const int ach = tid & 7;

    // B row pointer: resolves k-dual plane or column-split per global row.
    auto brow_ptr = [&](int r, int p) -> const float* {
        int gcol = n0 + r;
        if (g.A1) return (p ? g.B1 : g.B0) + (size_t)gcol * K;
        if (g.nsplit > 0 && gcol >= g.nsplit) return g.B1 + (size_t)(gcol - g.nsplit) * K;
        return g.B0 + (size_t)gcol * K;
    };

    auto prefetchA = [&](int c) {
        const int p = (c >= kch) ? 1 : 0;
        const int k0 = (c - p * kch) << 6;
        const float* A = p ? g.A1 : g.A0;
        #pragma unroll
        for (int it = 0; it < 2; ++it) {
            int gr = m0 + arow[it];
            const float* ap = A + (size_t)gr * K + k0 + ach * 8;
            if (gr < M) {
                ra[2*it]   = *(const float4*)ap;
                ra[2*it+1] = *(const float4*)(ap + 4);
            } else {
                ra[2*it] = ra[2*it+1] = make_float4(0.f, 0.f, 0.f, 0.f);
            }
        }
    };

    auto store_stage = [&](int st, int c) {
        const uint32_t sah = base + (uint32_t)st * STAGE;
        const uint32_t sal = sah + APL;
        const uint32_t sbh = sah + 2 * APL;
        const uint32_t sbl = sah + 3 * APL;
        #pragma unroll
        for (int it = 0; it < 2; ++it) {
            int r = arow[it];
            uint32_t off = (uint32_t)(r * 128 + ((ach ^ (r & 7)) << 4));
            unsigned h0,l0,h1,l1,h2,l2,h3,l3;
            split2(ra[2*it].x,   ra[2*it].y,   h0, l0);
            split2(ra[2*it].z,   ra[2*it].w,   h1, l1);
            split2(ra[2*it+1].x, ra[2*it+1].y, h2, l2);
            split2(ra[2*it+1].z, ra[2*it+1].w, h3, l3);
            STS128(sah + off, h0, h1, h2, h3);
            STS128(sal + off, l0, l1, l2, l3);
        }
        // B loaded inline (weights are L2-resident; saves staging registers)
        const int p = (c >= kch) ? 1 : 0;
        const int k0 = (c - p * kch) << 6;
        #pragma unroll
        for (int it = 0; it < 2; ++it) {
            int r = arow[it];
            const float* bp = brow_ptr(r, p) + k0 + ach * 8;
            float4 b0 = *(const float4*)bp;
            float4 b1 = *(const float4*)(bp + 4);
            uint32_t off = (uint32_t)(r * 128 + ((ach ^ (r & 7)) << 4));
            unsigned h0,l0,h1,l1,h2,l2,h3,l3;
            split2(b0.x, b0.y, h0, l0);
            split2(b0.z, b0.w, h1, l1);
            split2(b1.x, b1.y, h2, l2);
            split2(b1.z, b1.w, h3, l3);
            STS128(sbh + off, h0, h1, h2, h3);
            STS128(sbl + off, l0, l1, l2, l3);
        }
    };

    auto mma_stage = [&](int st) {
        const uint32_t sah = base + (uint32_t)st * STAGE;
        const uint32_t sal = sah + APL;
        const uint32_t sbh = sah + 2 * APL;
        const uint32_t sbl = sah + 3 * APL;
        const int lrow = lane & 15, lsel = lane >> 4;
        #pragma unroll
        for (int s = 0; s < 4; ++s) {
            const int ch = 2 * s + lsel;
            unsigned bh[4], bl[4];
            {
                int r = wn * 16 + lrow;
                uint32_t off = (uint32_t)(r * 128 + ((ch ^ (r & 7)) << 4));
                ldsm_x4(sbh + off, bh[0], bh[1], bh[2], bh[3]);
                ldsm_x4(sbl + off, bl[0], bl[1], bl[2], bl[3]);
            }
            unsigned ah[2][4], al[2][4];
            #pragma unroll
            for (int i = 0; i < 2; ++i) {
                int r = wm * 32 + i * 16 + lrow;
                uint32_t off = (uint32_t)(r * 128 + ((ch ^ (r & 7)) << 4));
                ldsm_x4(sah + off, ah[i][0], ah[i][1], ah[i][2], ah[i][3]);
                ldsm_x4(sal + off, al[i][0], al[i][1], al[i][2], al[i][3]);
            }
            #pragma unroll
            for (int pass = 0; pass < 3; ++pass) {
                #pragma unroll
                for (int i = 0; i < 2; ++i)
                    #pragma unroll
                    for (int j = 0; j < 2; ++j) {
                        const unsigned* af = (pass == 1) ? al[i] : ah[i];
                        const unsigned* bf = (pass == 2) ? bl : bh;
                        mma_bf16(acc[i][j], af, bf[j], bf[j + 2]);
                    }
            }
        }
    };

    prefetchA(0);
    store_stage(0, 0);
    __syncthreads();

    for (int c = 0; c < nch; ++c) {
        if (c + 1 < nch) prefetchA(c + 1);
        mma_stage(c & 1);
        if (c + 1 < nch) store_stage((c + 1) & 1, c + 1);
        __syncthreads();
    }

    // epilogue
    #pragma unroll
    for (int i = 0; i < 2; ++i) {
        int row = m0 + wm * 32 + i * 16 + group;
        #pragma unroll
        for (int j = 0; j < 2; ++j) {
            int colg = n0 + wn * 16 + j * 8 + 2 * tig;
            float b0 = 0.f, b1 = 0.f;
            if (g.bias) {
                if (g.nsplit > 0 && !g.A1) {
                    if (colg >= g.nsplit) {
                        b0 = __ldg(g.bias + colg - g.nsplit);
                        b1 = __ldg(g.bias + colg - g.nsplit + 1);
                    }
                } else {
                    b0 = __ldg(g.bias + colg);
                    b1 = __ldg(g.bias + colg + 1);
                }
            }
            if (row < M) {
                float v0 = acc[i][j][0] + b0, v1 = acc[i][j][1] + b1;
                if (g.addend) {
                    const float* ap = g.addend + (size_t)row * N + colg;
                    v0 += ap[0]; v1 += ap[1];
                }
                if (g.relu) { v0 = fmaxf(v0, 0.f); v1 = fmaxf(v1, 0.f); }
                *(float2*)(g.C + (size_t)row * N + colg) = make_float2(v0, v1);
            }
            int row2 = row + 8;
            if (row2 < M) {
                float v0 = acc[i][j][2] + b0, v1 = acc[i][j][3] + b1;
                if (g.addend) {
                    const float* ap = g.addend + (size_t)row2 * N + colg;
                    v0 += ap[0]; v1 += ap[1];
                }
                if (g.relu) { v0 = fmaxf(v0, 0.f); v1 = fmaxf(v1, 0.f); }
                *(float2*)(g.C + (size_t)row2 * N + colg) = make_float2(v0, v1);
            }
        }
    }
}

// ---------------- CSR build ----------------
__global__ void count_edges(const int* __restrict__ src, const int* __restrict__ dst, int e) {
    int i = blockIdx.x * blockDim.x + threadIdx.x;
    if (i < e) {
        atomicAdd(&g_cnt_mi[src[i]], 1);
        atomicAdd(&g_cnt_di[dst[i]], 1);
    }
}

// Phase 1: per-block exclusive scans + block totals (di blocks first, then mi).
__global__ void scan_p1() {
    const int* cnt; int* rp; int* bsum; int n, b;
    if (blockIdx.x < NB_DI) {
        cnt = g_cnt_di; rp = g_rowptr_di; bsum = g_bsum_di; n = N_DI; b = blockIdx.x;
    } else {
        cnt = g_cnt_mi; rp = g_rowptr_mi; bsum = g_bsum_mi; n = N_MI; b = blockIdx.x - NB_DI;
    }
    __shared__ int warpsum[32];
    int tid = threadIdx.x, lane = tid & 31, wid = tid >> 5;
    int i = b * 1024 + tid;
    int v = (i < n) ? cnt[i] : 0;
    int x = v;
    #pragma unroll
    for (int off = 1; off < 32; off <<= 1) {
        int t = __shfl_up_sync(0xffffffffu, x, off);
        if (lane >= off) x += t;
    }
    if (lane == 31) warpsum[wid] = x;
    __syncthreads();
    if (wid == 0) {
        int w = warpsum[lane];
        #pragma unroll
        for (int off = 1; off < 32; off <<= 1) {
            int t = __shfl_up_sync(0xffffffffu, w, off);
            if (lane >= off) w += t;
        }
        warpsum[lane] = w;
    }
    __syncthreads();
    int excl = x - v + (wid ? warpsum[wid - 1] : 0);
    if (i < n) rp[i] = excl;
    if (tid == 0) bsum[b] = warpsum[31];
}

// Phase 2: exclusive-scan the small block-sum arrays (1 block).
__global__ void scan_p2() {
    if (threadIdx.x == 0) {
        int run = 0;
        for (int i = 0; i < NB_DI; ++i) { int t = g_bsum_di[i]; g_bsum_di[i] = run; run += t; }
    }
    if (threadIdx.x == 1) {
        int run = 0;
        for (int i = 0; i < NB_MI; ++i) { int t = g_bsum_mi[i]; g_bsum_mi[i] = run; run += t; }
    }
}

// Phase 3: add block offsets; set rowptr[n] = E (total edges is exactly N_E).
__global__ void scan_p3() {
    int* rp; const int* bsum; int n, b;
    if (blockIdx.x < NB_DI) {
        rp = g_rowptr_di; bsum = g_bsum_di; n = N_DI; b = blockIdx.x;
    } else {
        rp = g_rowptr_mi; bsum = g_bsum_mi; n = N_MI; b = blockIdx.x - NB_DI;
    }
    int i = b * 1024 + threadIdx.x;
    if (i < n) rp[i] += bsum[b];
    if (b == 0 && threadIdx.x == 0) rp[n] = N_E;
}

__global__ void fill_edges(const int* __restrict__ src, const int* __restrict__ dst, int e) {
    int i = blockIdx.x * blockDim.x + threadIdx.x;
    if (i < e) {
        int s = src[i], d = dst[i];
        int pd = g_rowptr_di[d] + atomicAdd(&g_cnt_di[d], 1);
        g_col_di[pd] = s;
        int pm = g_rowptr_mi[s] + atomicAdd(&g_cnt_mi[s], 1);
        g_col_mi[pm] = d;
    }
}

// ---------------- merged aggregation kernels (di blocks first, then mi) ----------------
static constexpr int AG_DI = (N_DI + 7) / 8;
static constexpr int AG_MI = (N_MI + 7) / 8;

// L1: plain mean, width 128, stride 128
__global__ void agg_plain128_2(const float* __restrict__ x_d, float* __restrict__ o_d,
                               const float* __restrict__ x_m, float* __restrict__ o_m) {
    const float* x; float* out; const int* rowptr; const int* col; int n, blk;
    if (blockIdx.x < AG_DI) {
        x = x_d; out = o_d; rowptr = g_rowptr_di; col = g_col_di; n = N_DI; blk = blockIdx.x;
    } else {
        x = x_m; out = o_m; rowptr = g_rowptr_mi; col = g_col_mi; n = N_MI; blk = blockIdx.x - AG_DI;
    }
    int warp = blk * 8 + (threadIdx.x >> 5);
    int lane = threadIdx.x & 31;
    if (warp >= n) return;
    int s = rowptr[warp], e = rowptr[warp + 1];
    float4 acc = make_float4(0.f, 0.f, 0.f, 0.f);
    int i = s;
    for (; i + 1 < e; i += 2) {
        float4 a = __ldg((const float4*)(x + (size_t)col[i] * 128) + lane);
        float4 b = __ldg((const float4*)(x + (size_t)col[i + 1] * 128) + lane);
        acc.x += a.x + b.x; acc.y += a.y + b.y;
        acc.z += a.z + b.z; acc.w += a.w + b.w;
    }
    if (i < e) {
        float4 a = __ldg((const float4*)(x + (size_t)col[i] * 128) + lane);
        acc.x += a.x; acc.y += a.y; acc.z += a.z; acc.w += a.w;
    }
    float inv = 1.f / fmaxf((float)(e - s), 1.f);
    acc.x *= inv; acc.y *= inv; acc.z *= inv; acc.w *= inv;
    ((float4*)(out + (size_t)warp * 128))[lane] = acc;
}

// L2: out = relu(mean(srcC[:,0:128]) + rootC[:,128:256]); stride 256
__global__ void agg_fused128_2(const float* __restrict__ s_d, const float* __restrict__ r_d,
                               float* __restrict__ o_d,
                               const float* __restrict__ s_m, const float* __restrict__ r_m,
                               float* __restrict__ o_m) {
    const float *srcC, *rootC; float* out; const int *rowptr, *col; int n, blk;
    if (blockIdx.x < AG_DI) {
        srcC = s_d; rootC = r_d; out = o_d; rowptr = g_rowptr_di; col = g_col_di; n = N_DI; blk = blockIdx.x;
    } else {
        srcC = s_m; rootC = r_m; out = o_m; rowptr = g_rowptr_mi; col = g_col_mi; n = N_MI; blk = blockIdx.x - AG_DI;
    }
    int warp = blk * 8 + (threadIdx.x >> 5);
    int lane = threadIdx.x & 31;
    if (warp >= n) return;
    int s = rowptr[warp], e = rowptr[warp + 1];
    float4 acc = make_float4(0.f, 0.f, 0.f, 0.f);
    int i = s;
    for (; i + 1 < e; i += 2) {
        float4 a = __ldg((const float4*)(srcC + (size_t)col[i] * 256) + lane);
        float4 b = __ldg((const float4*)(srcC + (size_t)col[i + 1] * 256) + lane);
        acc.x += a.x + b.x; acc.y += a.y + b.y;
        acc.z += a.z + b.z; acc.w += a.w + b.w;
    }
    if (i < e) {
        float4 a = __ldg((const float4*)(srcC + (size_t)col[i] * 256) + lane);
        acc.x += a.x; acc.y += a.y; acc.z += a.z; acc.w += a.w;
    }
    float inv = 1.f / fmaxf((float)(e - s), 1.f);
    float4 r = __ldg((const float4*)(rootC + (size_t)warp * 256 + 128) + lane);
    float4 v;
    v.x = fmaxf(acc.x * inv + r.x, 0.f);
    v.y = fmaxf(acc.y * inv + r.y, 0.f);
    v.z = fmaxf(acc.z * inv + r.z, 0.f);
    v.w = fmaxf(acc.w * inv + r.w, 0.f);
    ((float4*)(out + (size_t)warp * 128))[lane] = v;
}

// L3: out = mean(srcC[:,0:64]) + rootC[:,64:128]; stride 128, width 64
__global__ void agg_fused64_2(const float* __restrict__ s_d, const float* __restrict__ r_d,
                              float* __restrict__ o_d,
                              const float* __restrict__ s_m, const float* __restrict__ r_m,
                              float* __restrict__ o_m) {
    const float *srcC, *rootC; float* out; const int *rowptr, *col; int n, blk;
    if (blockIdx.x < AG_DI) {
        srcC = s_d; rootC = r_d; out = o_d; rowptr = g_rowptr_di; col = g_col_di; n = N_DI; blk = blockIdx.x;
    } else {
        srcC = s_m; rootC = r_m; out = o_m; rowptr = g_rowptr_mi; col = g_col_mi; n = N_MI; blk = blockIdx.x - AG_DI;
    }
    int warp = blk * 8 + (threadIdx.x >> 5);
    int lane = threadIdx.x & 31;
    if (warp >= n) return;
    int s = rowptr[warp], e = rowptr[warp + 1];
    float2 acc = make_float2(0.f, 0.f);
    int i = s;
    for (; i + 1 < e; i += 2) {
        float2 a = __ldg((const float2*)(srcC + (size_t)col[i] * 128) + lane);
        float2 b = __ldg((const float2*)(srcC + (size_t)col[i + 1] * 128) + lane);
        acc.x += a.x + b.x; acc.y += a.y + b.y;
    }
    if (i < e) {
        float2 a = __ldg((const float2*)(srcC + (size_t)col[i] * 128) + lane);
        acc.x += a.x; acc.y += a.y;
    }
    float inv = 1.f / fmaxf((float)(e - s), 1.f);
    float2 r = __ldg((const float2*)(rootC + (size_t)warp * 128 + 64) + lane);
    float2 v = make_float2(acc.x * inv + r.x, acc.y * inv + r.y);
    ((float2*)(out + (size_t)warp * 64))[lane] = v;
}

// ---------------- classifier ----------------
__global__ void dot64(const float* __restrict__ hmi, const float* __restrict__ hdi,
                      const int* __restrict__ lsrc, const int* __restrict__ ldst,
                      float* __restrict__ out, int L) {
    int warp = (blockIdx.x * blockDim.x + threadIdx.x) >> 5;
    int lane = threadIdx.x & 31;
    if (warp >= L) return;
    const float2* a = (const float2*)(hmi + (size_t)lsrc[warp] * 64);
    const float2* b = (const float2*)(hdi + (size_t)ldst[warp] * 64);
    float2 av = a[lane], bv = b[lane];
    float p = av.x * bv.x + av.y * bv.y;
    #pragma unroll
    for (int off = 16; off; off >>= 1) p += __shfl_down_sync(0xffffffffu, p, off);
    if (lane == 0) out[warp] = p;
}

// ---------------- host orchestration ----------------
static inline void gemm_pair(const GArgs& a, const GArgs& b) {
    int yb0 = (a.M + 63) / 64, yb1 = (b.M + 63) / 64;
    mma_gemm2<<<dim3(a.N / 64, yb0 + yb1), 256, GSMEM>>>(a, b, yb0);
}

extern "C" void kernel_launch(void* const* d_in, const int* in_sizes, int n_in,
                              void* d_out, int out_size) {
    const float* x_mi   = (const float*)d_in[0];
    const float* x_di   = (const float*)d_in[1];
    const float* W_mi   = (const float*)d_in[2];
    const float* b_mi   = (const float*)d_in[3];
    const float* W_di   = (const float*)d_in[4];
    const float* b_di   = (const float*)d_in[5];
    const float* emb_mi = (const float*)d_in[6];
    const float* emb_di = (const float*)d_in[7];
    const float *Wl[3][2], *bl[3][2], *Wr[3][2];   // [layer][0=md,1=dm]
    for (int i = 0; i < 3; ++i)
        for (int r = 0; r < 2; ++r) {
            int base = 8 + i * 6 + r * 3;
            Wl[i][r] = (const float*)d_in[base];
            bl[i][r] = (const float*)d_in[base + 1];
            Wr[i][r] = (const float*)d_in[base + 2];
        }
    const int* edge_src  = (const int*)d_in[26];
    const int* edge_dst  = (const int*)d_in[27];
    const int* label_src = (const int*)d_in[28];
    const int* label_dst = (const int*)d_in[29];
    float* out = (float*)d_out;

    cudaFuncSetAttribute(mma_gemm2, cudaFuncAttributeMaxDynamicSharedMemorySize, GSMEM);

    float *hA_mi, *hB_mi, *hA_di, *hB_di, *t_mi, *t_di;
    int *cnt_di, *cnt_mi;
    cudaGetSymbolAddress((void**)&hA_mi, g_hA_mi);
    cudaGetSymbolAddress((void**)&hB_mi, g_hB_mi);
    cudaGetSymbolAddress((void**)&hA_di, g_hA_di);
    cudaGetSymbolAddress((void**)&hB_di, g_hB_di);
    cudaGetSymbolAddress((void**)&t_mi, g_t_mi);
    cudaGetSymbolAddress((void**)&t_di, g_t_di);
    cudaGetSymbolAddress((void**)&cnt_di, g_cnt_di);
    cudaGetSymbolAddress((void**)&cnt_mi, g_cnt_mi);

    const int EB = (N_E + 255) / 256;

    // ---- CSR build (parallel 3-phase scan) ----
    cudaMemsetAsync(cnt_di, 0, N_DI * sizeof(int));
    cudaMemsetAsync(cnt_mi, 0, N_MI * sizeof(int));
    count_edges<<<EB, 256>>>(edge_src, edge_dst, N_E);
    scan_p1<<<NB_DI + NB_MI, 1024>>>();
    scan_p2<<<1, 32>>>();
    scan_p3<<<NB_DI + NB_MI, 1024>>>();
    cudaMemsetAsync(cnt_di, 0, N_DI * sizeof(int));
    cudaMemsetAsync(cnt_mi, 0, N_MI * sizeof(int));
    fill_edges<<<EB, 256>>>(edge_src, edge_dst, N_E);

    // ---- input projections: h = x @ W^T + b + emb ----
    gemm_pair(
        { x_mi, nullptr, W_mi, nullptr, 0, b_mi, emb_mi, hA_mi, N_MI, 128, 256, 0 },
        { x_di, nullptr, W_di, nullptr, 0, b_di, emb_di, hA_di, N_DI, 128, 128, 0 });

    // ---- Layer 1 (agg-first, 128 -> 256, relu), k-dual ----
    agg_plain128_2<<<AG_DI + AG_MI, 256>>>(hA_mi, t_di, hA_di, t_mi);
    gemm_pair(
        { t_di, hA_di, Wl[0][0], Wr[0][0], 0, bl[0][0], nullptr, hB_di, N_DI, 256, 128, 1 },
        { t_mi, hA_mi, Wl[0][1], Wr[0][1], 0, bl[0][1], nullptr, hB_mi, N_MI, 256, 128, 1 });

    // ---- Layer 2 (fused transform+root, 256 -> 128, relu) ----
    gemm_pair(
        { hB_mi, nullptr, Wl[1][0], Wr[1][1], 128, bl[1][1], nullptr, t_mi, N_MI, 256, 256, 0 },
        { hB_di, nullptr, Wl[1][1], Wr[1][0], 128, bl[1][0], nullptr, t_di, N_DI, 256, 256, 0 });
    agg_fused128_2<<<AG_DI + AG_MI, 256>>>(t_mi, t_di, hA_di, t_di, t_mi, hA_mi);

    // ---- Layer 3 (fused transform+root, 128 -> 64, no relu) ----
    gemm_pair(
        { hA_mi, nullptr, Wl[2][0], Wr[2][1], 64, bl[2][1], nullptr, t_mi, N_MI, 128, 128, 0 },
        { hA_di, nullptr, Wl[2][1], Wr[2][0], 64, bl[2][0], nullptr, t_di, N_DI, 128, 128, 0 });
    agg_fused64_2<<<AG_DI + AG_MI, 256>>>(t_mi, t_di, hB_di, t_di, t_mi, hB_mi);

    // ---- classifier ----
    dot64<<<(N_L + 7) / 8, 256>>>(hB_mi, hB_di, label_src, label_dst, out, N_L);
}

// round 10
// speedup vs baseline: 1.2727x; 1.1309x over previous
#include <cuda_runtime.h>
#include <cuda_fp16.h>
#include <cstdint>

// ---------------- problem constants ----------------
#define N_MI   100000
#define N_DI   50000
#define N_E    500000
#define N_L    200000

static constexpr int NB_DI = (N_DI + 1023) / 1024;   // 49
static constexpr int NB_MI = (N_MI + 1023) / 1024;   // 98

// ---------------- device scratch ----------------
__device__ float g_hA_mi[(size_t)N_MI * 256];
__device__ float g_hB_mi[(size_t)N_MI * 256];
__device__ float g_hA_di[(size_t)N_DI * 256];
__device__ float g_hB_di[(size_t)N_DI * 256];
__device__ float g_t_mi[(size_t)N_MI * 256];
__device__ float g_t_di[(size_t)N_DI * 256];

__device__ int g_rowptr_di[N_DI + 1];
__device__ int g_rowptr_mi[N_MI + 1];
__device__ int g_col_di[N_E];
__device__ int g_col_mi[N_E];
__device__ int g_cnt_di[N_DI];
__device__ int g_cnt_mi[N_MI];
__device__ int g_bsum_di[NB_DI];
__device__ int g_bsum_mi[NB_MI];

// ---------------- helpers ----------------
__device__ __forceinline__ uint32_t smem_u32(const void* p) {
    uint32_t a;
    asm("{ .reg .u64 t; cvta.to.shared.u64 t, %1; cvt.u32.u64 %0, t; }"
        : "=r"(a) : "l"(p));
    return a;
}

__device__ __forceinline__ unsigned pack_f16x2(float x0, float x1) {
    unsigned r;
    asm("cvt.rn.f16x2.f32 %0, %1, %2;" : "=r"(r) : "f"(x1), "f"(x0));
    return r;
}
// split 2 floats into fp16 hi words + fp16 residual words
__device__ __forceinline__ void split2h(float x0, float x1, unsigned& hw, unsigned& lw) {
    hw = pack_f16x2(x0, x1);
    float h0, h1;
    asm("{ .reg .f16 a, b; mov.b32 {a, b}, %2; cvt.f32.f16 %0, a; cvt.f32.f16 %1, b; }"
        : "=f"(h0), "=f"(h1) : "r"(hw));
    lw = pack_f16x2(x0 - h0, x1 - h1);
}

__device__ __forceinline__ void mma_f16(float* c, const unsigned* a, unsigned b0, unsigned b1) {
    asm volatile(
        "mma.sync.aligned.m16n8k16.row.col.f32.f16.f16.f32 "
        "{%0,%1,%2,%3}, {%4,%5,%6,%7}, {%8,%9}, {%0,%1,%2,%3};"
        : "+f"(c[0]), "+f"(c[1]), "+f"(c[2]), "+f"(c[3])
        : "r"(a[0]), "r"(a[1]), "r"(a[2]), "r"(a[3]), "r"(b0), "r"(b1));
}

__device__ __forceinline__ void ldsm_x4(uint32_t addr, unsigned& r0, unsigned& r1,
                                        unsigned& r2, unsigned& r3) {
    asm volatile("ldmatrix.sync.aligned.m8n8.x4.shared.b16 {%0,%1,%2,%3}, [%4];"
                 : "=r"(r0), "=r"(r1), "=r"(r2), "=r"(r3) : "r"(addr));
}

#define STS128(addr, a, b, c, d) \
    asm volatile("st.shared.v4.b32 [%0], {%1,%2,%3,%4};" \
                 :: "r"(addr), "r"(a), "r"(b), "r"(c), "r"(d))

// ---------------- paired fp16 2-pass GEMM, BM=64 x BN=64, KC=64 ---------------------
// acc = fp16(A) @ (fp16hi(B) + fp16lo(B))^T  -> per-product error ~2^-11 (A rounding).
// Two independent GEMM problems per launch (grid.y partitioned at yb0).
// C[M,N](ld=N) = A0@B0^T (+A1@B1^T k-dual) (+bias)(+addend), opt relu.
// nsplit>0 (and !A1): output col < nsplit from B0 (no bias); col >= nsplit from B1
// (bias indexed col-nsplit).
struct GArgs {
    const float *A0, *A1, *B0, *B1;
    int nsplit;
    const float *bias, *addend;
    float* C;
    int M, N, K, relu;
};

static constexpr uint32_t APL = 64 * 128;          // 8 KB plane (64 rows x 128B)
static constexpr uint32_t STAGE = 3 * APL;         // A, Bh, Bl = 24 KB
static constexpr int GSMEM = 2 * (int)STAGE + 128; // 49280 (2 stages)

__global__ void __launch_bounds__(256, 3) mma_gemm2(GArgs g0, GArgs g1, int yb0) {
    const GArgs& g = (blockIdx.y < (unsigned)yb0) ? g0 : g1;
    const int my = (blockIdx.y < (unsigned)yb0) ? blockIdx.y : blockIdx.y - yb0;

    extern __shared__ char smem_raw[];
    const uint32_t base = (smem_u32(smem_raw) + 127u) & ~127u;

    const int tid = threadIdx.x, lane = tid & 31, wid = tid >> 5;
    const int wm = wid & 1, wn = wid >> 1;          // warp tile 32(m) x 16(n)
    const int group = lane >> 2, tig = lane & 3;
    const int m0 = my * 64, n0 = blockIdx.x * 64;
    const int M = g.M, N = g.N, K = g.K;

    float acc[2][2][4];
    #pragma unroll
    for (int i = 0; i < 2; ++i)
        #pragma unroll
        for (int j = 0; j < 2; ++j)
            #pragma unroll
            for (int q = 0; q < 4; ++q) acc[i][j][q] = 0.f;

    const int kch = K >> 6;
    const int nch = g.A1 ? 2 * kch : kch;

    float4 ra[4];                       // A staging: 2 row-sweeps x 8 floats
    const int arow[2] = { tid >> 3, (256 + tid) >> 3 };
    const int ach = tid & 7;

    auto brow_ptr = [&](int r, int p) -> const float* {
        int gcol = n0 + r;
        if (g.A1) return (p ? g.B1 : g.B0) + (size_t)gcol * K;
        if (g.nsplit > 0 && gcol >= g.nsplit) return g.B1 + (size_t)(gcol - g.nsplit) * K;
        return g.B0 + (size_t)gcol * K;
    };

    auto prefetchA = [&](int c) {
        const int p = (c >= kch) ? 1 : 0;
        const int k0 = (c - p * kch) << 6;
        const float* A = p ? g.A1 : g.A0;
        #pragma unroll
        for (int it = 0; it < 2; ++it) {
            int gr = m0 + arow[it];
            const float* ap = A + (size_t)gr * K + k0 + ach * 8;
            if (gr < M) {
                ra[2*it]   = *(const float4*)ap;
                ra[2*it+1] = *(const float4*)(ap + 4);
            } else {
                ra[2*it] = ra[2*it+1] = make_float4(0.f, 0.f, 0.f, 0.f);
            }
        }
    };

    auto store_stage = [&](int st, int c) {
        const uint32_t sa  = base + (uint32_t)st * STAGE;
        const uint32_t sbh = sa + APL;
        const uint32_t sbl = sa + 2 * APL;
        // A: single fp16 plane (8 floats -> 4 packed words -> one STS128)
        #pragma unroll
        for (int it = 0; it < 2; ++it) {
            int r = arow[it];
            uint32_t off = (uint32_t)(r * 128 + ((ach ^ (r & 7)) << 4));
            unsigned w0 = pack_f16x2(ra[2*it].x,   ra[2*it].y);
            unsigned w1 = pack_f16x2(ra[2*it].z,   ra[2*it].w);
            unsigned w2 = pack_f16x2(ra[2*it+1].x, ra[2*it+1].y);
            unsigned w3 = pack_f16x2(ra[2*it+1].z, ra[2*it+1].w);
            STS128(sa + off, w0, w1, w2, w3);
        }
        // B: loaded inline, split into hi/lo fp16 planes
        const int p = (c >= kch) ? 1 : 0;
        const int k0 = (c - p * kch) << 6;
        #pragma unroll
        for (int it = 0; it < 2; ++it) {
            int r = arow[it];
            const float* bp = brow_ptr(r, p) + k0 + ach * 8;
            float4 b0 = *(const float4*)bp;
            float4 b1 = *(const float4*)(bp + 4);
            uint32_t off = (uint32_t)(r * 128 + ((ach ^ (r & 7)) << 4));
            unsigned h0,l0,h1,l1,h2,l2,h3,l3;
            split2h(b0.x, b0.y, h0, l0);
            split2h(b0.z, b0.w, h1, l1);
            split2h(b1.x, b1.y, h2, l2);
            split2h(b1.z, b1.w, h3, l3);
            STS128(sbh + off, h0, h1, h2, h3);
            STS128(sbl + off, l0, l1, l2, l3);
        }
    };

    auto mma_stage = [&](int st) {
        const uint32_t sa  = base + (uint32_t)st * STAGE;
        const uint32_t sbh = sa + APL;
        const uint32_t sbl = sa + 2 * APL;
        const int lrow = lane & 15, lsel = lane >> 4;
        #pragma unroll
        for (int s = 0; s < 4; ++s) {
            const int ch = 2 * s + lsel;
            unsigned bh[4], bl[4];
            {
                int r = wn * 16 + lrow;
                uint32_t off = (uint32_t)(r * 128 + ((ch ^ (r & 7)) << 4));
                ldsm_x4(sbh + off, bh[0], bh[1], bh[2], bh[3]);
                ldsm_x4(sbl + off, bl[0], bl[1], bl[2], bl[3]);
            }
            unsigned ah[2][4];
            #pragma unroll
            for (int i = 0; i < 2; ++i) {
                int r = wm * 32 + i * 16 + lrow;
                uint32_t off = (uint32_t)(r * 128 + ((ch ^ (r & 7)) << 4));
                ldsm_x4(sa + off, ah[i][0], ah[i][1], ah[i][2], ah[i][3]);
            }
            #pragma unroll
            for (int pass = 0; pass < 2; ++pass) {
                const unsigned* bf = pass ? bl : bh;
                #pragma unroll
                for (int i = 0; i < 2; ++i)
                    #pragma unroll
                    for (int j = 0; j < 2; ++j)
                        mma_f16(acc[i][j], ah[i], bf[j], bf[j + 2]);
            }
        }
    };

    prefetchA(0);
    store_stage(0, 0);
    __syncthreads();

    for (int c = 0; c < nch; ++c) {
        if (c + 1 < nch) prefetchA(c + 1);
        mma_stage(c & 1);
        if (c + 1 < nch) store_stage((c + 1) & 1, c + 1);
        __syncthreads();
    }

    // epilogue
    #pragma unroll
    for (int i = 0; i < 2; ++i) {
        int row = m0 + wm * 32 + i * 16 + group;
        #pragma unroll
        for (int j = 0; j < 2; ++j) {
            int colg = n0 + wn * 16 + j * 8 + 2 * tig;
            float b0 = 0.f, b1 = 0.f;
            if (g.bias) {
                if (g.nsplit > 0 && !g.A1) {
                    if (colg >= g.nsplit) {
                        b0 = __ldg(g.bias + colg - g.nsplit);
                        b1 = __ldg(g.bias + colg - g.nsplit + 1);
                    }
                } else {
                    b0 = __ldg(g.bias + colg);
                    b1 = __ldg(g.bias + colg + 1);
                }
            }
            if (row < M) {
                float v0 = acc[i][j][0] + b0, v1 = acc[i][j][1] + b1;
                if (g.addend) {
                    const float* ap = g.addend + (size_t)row * N + colg;
                    v0 += ap[0]; v1 += ap[1];
                }
                if (g.relu) { v0 = fmaxf(v0, 0.f); v1 = fmaxf(v1, 0.f); }
                *(float2*)(g.C + (size_t)row * N + colg) = make_float2(v0, v1);
            }
            int row2 = row + 8;
            if (row2 < M) {
                float v0 = acc[i][j][2] + b0, v1 = acc[i][j][3] + b1;
                if (g.addend) {
                    const float* ap = g.addend + (size_t)row2 * N + colg;
                    v0 += ap[0]; v1 += ap[1];
                }
                if (g.relu) { v0 = fmaxf(v0, 0.f); v1 = fmaxf(v1, 0.f); }
                *(float2*)(g.C + (size_t)row2 * N + colg) = make_float2(v0, v1);
            }
        }
    }
}

// ---------------- CSR build ----------------
__global__ void count_edges(const int* __restrict__ src, const int* __restrict__ dst, int e) {
    int i = blockIdx.x * blockDim.x + threadIdx.x;
    if (i < e) {
        atomicAdd(&g_cnt_mi[src[i]], 1);
        atomicAdd(&g_cnt_di[dst[i]], 1);
    }
}

__global__ void scan_p1() {
    const int* cnt; int* rp; int* bsum; int n, b;
    if (blockIdx.x < NB_DI) {
        cnt = g_cnt_di; rp = g_rowptr_di; bsum = g_bsum_di; n = N_DI; b = blockIdx.x;
    } else {
        cnt = g_cnt_mi; rp = g_rowptr_mi; bsum = g_bsum_mi; n = N_MI; b = blockIdx.x - NB_DI;
    }
    __shared__ int warpsum[32];
    int tid = threadIdx.x, lane = tid & 31, wid = tid >> 5;
    int i = b * 1024 + tid;
    int v = (i < n) ? cnt[i] : 0;
    int x = v;
    #pragma unroll
    for (int off = 1; off < 32; off <<= 1) {
        int t = __shfl_up_sync(0xffffffffu, x, off);
        if (lane >= off) x += t;
    }
    if (lane == 31) warpsum[wid] = x;
    __syncthreads();
    if (wid == 0) {
        int w = warpsum[lane];
        #pragma unroll
        for (int off = 1; off < 32; off <<= 1) {
            int t = __shfl_up_sync(0xffffffffu, w, off);
            if (lane >= off) w += t;
        }
        warpsum[lane] = w;
    }
    __syncthreads();
    int excl = x - v + (wid ? warpsum[wid - 1] : 0);
    if (i < n) rp[i] = excl;
    if (tid == 0) bsum[b] = warpsum[31];
}

__global__ void scan_p2() {
    if (threadIdx.x == 0) {
        int run = 0;
        for (int i = 0; i < NB_DI; ++i) { int t = g_bsum_di[i]; g_bsum_di[i] = run; run += t; }
    }
    if (threadIdx.x == 1) {
        int run = 0;
        for (int i = 0; i < NB_MI; ++i) { int t = g_bsum_mi[i]; g_bsum_mi[i] = run; run += t; }
    }
}

__global__ void scan_p3() {
    int* rp; const int* bsum; int n, b;
    if (blockIdx.x < NB_DI) {
        rp = g_rowptr_di; bsum = g_bsum_di; n = N_DI; b = blockIdx.x;
    } else {
        rp = g_rowptr_mi; bsum = g_bsum_mi; n = N_MI; b = blockIdx.x - NB_DI;
    }
    int i = b * 1024 + threadIdx.x;
    if (i < n) rp[i] += bsum[b];
    if (b == 0 && threadIdx.x == 0) rp[n] = N_E;
}

__global__ void fill_edges(const int* __restrict__ src, const int* __restrict__ dst, int e) {
    int i = blockIdx.x * blockDim.x + threadIdx.x;
    if (i < e) {
        int s = src[i], d = dst[i];
        int pd = g_rowptr_di[d] + atomicAdd(&g_cnt_di[d], 1);
        g_col_di[pd] = s;
        int pm = g_rowptr_mi[s] + atomicAdd(&g_cnt_mi[s], 1);
        g_col_mi[pm] = d;
    }
}

// ---------------- merged aggregation kernels (di blocks first, then mi) ----------------
static constexpr int AG_DI = (N_DI + 7) / 8;
static constexpr int AG_MI = (N_MI + 7) / 8;

__global__ void agg_plain128_2(const float* __restrict__ x_d, float* __restrict__ o_d,
                               const float* __restrict__ x_m, float* __restrict__ o_m) {
    const float* x; float* out; const int* rowptr; const int* col; int n, blk;
    if (blockIdx.x < AG_DI) {
        x = x_d; out = o_d; rowptr = g_rowptr_di; col = g_col_di; n = N_DI; blk = blockIdx.x;
    } else {
        x = x_m; out = o_m; rowptr = g_rowptr_mi; col = g_col_mi; n = N_MI; blk = blockIdx.x - AG_DI;
    }
    int warp = blk * 8 + (threadIdx.x >> 5);
    int lane = threadIdx.x & 31;
    if (warp >= n) return;
    int s = rowptr[warp], e = rowptr[warp + 1];
    float4 acc = make_float4(0.f, 0.f, 0.f, 0.f);
    int i = s;
    for (; i + 1 < e; i += 2) {
        float4 a = __ldg((const float4*)(x + (size_t)col[i] * 128) + lane);
        float4 b = __ldg((const float4*)(x + (size_t)col[i + 1] * 128) + lane);
        acc.x += a.x + b.x; acc.y += a.y + b.y;
        acc.z += a.z + b.z; acc.w += a.w + b.w;
    }
    if (i < e) {
        float4 a = __ldg((const float4*)(x + (size_t)col[i] * 128) + lane);
        acc.x += a.x; acc.y += a.y; acc.z += a.z; acc.w += a.w;
    }
    float inv = 1.f / fmaxf((float)(e - s), 1.f);
    acc.x *= inv; acc.y *= inv; acc.z *= inv; acc.w *= inv;
    ((float4*)(out + (size_t)warp * 128))[lane] = acc;
}

__global__ void agg_fused128_2(const float* __restrict__ s_d, const float* __restrict__ r_d,
                               float* __restrict__ o_d,
                               const float* __restrict__ s_m, const float* __restrict__ r_m,
                               float* __restrict__ o_m) {
    const float *srcC, *rootC; float* out; const int *rowptr, *col; int n, blk;
    if (blockIdx.x < AG_DI) {
        srcC = s_d; rootC = r_d; out = o_d; rowptr = g_rowptr_di; col = g_col_di; n = N_DI; blk = blockIdx.x;
    } else {
        srcC = s_m; rootC = r_m; out = o_m; rowptr = g_rowptr_mi; col = g_col_mi; n = N_MI; blk = blockIdx.x - AG_DI;
    }
    int warp = blk * 8 + (threadIdx.x >> 5);
    int lane = threadIdx.x & 31;
    if (warp >= n) return;
    int s = rowptr[warp], e = rowptr[warp + 1];
    float4 acc = make_float4(0.f, 0.f, 0.f, 0.f);
    int i = s;
    for (; i + 1 < e; i += 2) {
        float4 a = __ldg((const float4*)(srcC + (size_t)col[i] * 256) + lane);
        float4 b = __ldg((const float4*)(srcC + (size_t)col[i + 1] * 256) + lane);
        acc.x += a.x + b.x; acc.y += a.y + b.y;
        acc.z += a.z + b.z; acc.w += a.w + b.w;
    }
    if (i < e) {
        float4 a = __ldg((const float4*)(srcC + (size_t)col[i] * 256) + lane);
        acc.x += a.x; acc.y += a.y; acc.z += a.z; acc.w += a.w;
    }
    float inv = 1.f / fmaxf((float)(e - s), 1.f);
    float4 r = __ldg((const float4*)(rootC + (size_t)warp * 256 + 128) + lane);
    float4 v;
    v.x = fmaxf(acc.x * inv + r.x, 0.f);
    v.y = fmaxf(acc.y * inv + r.y, 0.f);
    v.z = fmaxf(acc.z * inv + r.z, 0.f);
    v.w = fmaxf(acc.w * inv + r.w, 0.f);
    ((float4*)(out + (size_t)warp * 128))[lane] = v;
}

__global__ void agg_fused64_2(const float* __restrict__ s_d, const float* __restrict__ r_d,
                              float* __restrict__ o_d,
                              const float* __restrict__ s_m, const float* __restrict__ r_m,
                              float* __restrict__ o_m) {
    const float *srcC, *rootC; float* out; const int *rowptr, *col; int n, blk;
    if (blockIdx.x < AG_DI) {
        srcC = s_d; rootC = r_d; out = o_d; rowptr = g_rowptr_di; col = g_col_di; n = N_DI; blk = blockIdx.x;
    } else {
        srcC = s_m; rootC = r_m; out = o_m; rowptr = g_rowptr_mi; col = g_col_mi; n = N_MI; blk = blockIdx.x - AG_DI;
    }
    int warp = blk * 8 + (threadIdx.x >> 5);
    int lane = threadIdx.x & 31;
    if (warp >= n) return;
    int s = rowptr[warp], e = rowptr[warp + 1];
    float2 acc = make_float2(0.f, 0.f);
    int i = s;
    for (; i + 1 < e; i += 2) {
        float2 a = __ldg((const float2*)(srcC + (size_t)col[i] * 128) + lane);
        float2 b = __ldg((const float2*)(srcC + (size_t)col[i + 1] * 128) + lane);
        acc.x += a.x + b.x; acc.y += a.y + b.y;
    }
    if (i < e) {
        float2 a = __ldg((const float2*)(srcC + (size_t)col[i] * 128) + lane);
        acc.x += a.x; acc.y += a.y;
    }
    float inv = 1.f / fmaxf((float)(e - s), 1.f);
    float2 r = __ldg((const float2*)(rootC + (size_t)warp * 128 + 64) + lane);
    float2 v = make_float2(acc.x * inv + r.x, acc.y * inv + r.y);
    ((float2*)(out + (size_t)warp * 64))[lane] = v;
}

// ---------------- classifier ----------------
__global__ void dot64(const float* __restrict__ hmi, const float* __restrict__ hdi,
                      const int* __restrict__ lsrc, const int* __restrict__ ldst,
                      float* __restrict__ out, int L) {
    int warp = (blockIdx.x * blockDim.x + threadIdx.x) >> 5;
    int lane = threadIdx.x & 31;
    if (warp >= L) return;
    const float2* a = (const float2*)(hmi + (size_t)lsrc[warp] * 64);
    const float2* b = (const float2*)(hdi + (size_t)ldst[warp] * 64);
    float2 av = a[lane], bv = b[lane];
    float p = av.x * bv.x + av.y * bv.y;
    #pragma unroll
    for (int off = 16; off; off >>= 1) p += __shfl_down_sync(0xffffffffu, p, off);
    if (lane == 0) out[warp] = p;
}

// ---------------- host orchestration ----------------
static inline void gemm_pair(const GArgs& a, const GArgs& b) {
    int yb0 = (a.M + 63) / 64, yb1 = (b.M + 63) / 64;
    mma_gemm2<<<dim3(a.N / 64, yb0 + yb1), 256, GSMEM>>>(a, b, yb0);
}

extern "C" void kernel_launch(void* const* d_in, const int* in_sizes, int n_in,
                              void* d_out, int out_size) {
    const float* x_mi   = (const float*)d_in[0];
    const float* x_di   = (const float*)d_in[1];
    const float* W_mi   = (const float*)d_in[2];
    const float* b_mi   = (const float*)d_in[3];
    const float* W_di   = (const float*)d_in[4];
    const float* b_di   = (const float*)d_in[5];
    const float* emb_mi = (const float*)d_in[6];
    const float* emb_di = (const float*)d_in[7];
    const float *Wl[3][2], *bl[3][2], *Wr[3][2];   // [layer][0=md,1=dm]
    for (int i = 0; i < 3; ++i)
        for (int r = 0; r < 2; ++r) {
            int base = 8 + i * 6 + r * 3;
            Wl[i][r] = (const float*)d_in[base];
            bl[i][r] = (const float*)d_in[base + 1];
            Wr[i][r] = (const float*)d_in[base + 2];
        }
    const int* edge_src  = (const int*)d_in[26];
    const int* edge_dst  = (const int*)d_in[27];
    const int* label_src = (const int*)d_in[28];
    const int* label_dst = (const int*)d_in[29];
    float* out = (float*)d_out;

    cudaFuncSetAttribute(mma_gemm2, cudaFuncAttributeMaxDynamicSharedMemorySize, GSMEM);

    float *hA_mi, *hB_mi, *hA_di, *hB_di, *t_mi, *t_di;
    int *cnt_di, *cnt_mi;
    cudaGetSymbolAddress((void**)&hA_mi, g_hA_mi);
    cudaGetSymbolAddress((void**)&hB_mi, g_hB_mi);
    cudaGetSymbolAddress((void**)&hA_di, g_hA_di);
    cudaGetSymbolAddress((void**)&hB_di, g_hB_di);
    cudaGetSymbolAddress((void**)&t_mi, g_t_mi);
    cudaGetSymbolAddress((void**)&t_di, g_t_di);
    cudaGetSymbolAddress((void**)&cnt_di, g_cnt_di);
    cudaGetSymbolAddress((void**)&cnt_mi, g_cnt_mi);

    const int EB = (N_E + 255) / 256;

    // ---- CSR build (parallel 3-phase scan) ----
    cudaMemsetAsync(cnt_di, 0, N_DI * sizeof(int));
    cudaMemsetAsync(cnt_mi, 0, N_MI * sizeof(int));
    count_edges<<<EB, 256>>>(edge_src, edge_dst, N_E);
    scan_p1<<<NB_DI + NB_MI, 1024>>>();
    scan_p2<<<1, 32>>>();
    scan_p3<<<NB_DI + NB_MI, 1024>>>();
    cudaMemsetAsync(cnt_di, 0, N_DI * sizeof(int));
    cudaMemsetAsync(cnt_mi, 0, N_MI * sizeof(int));
    fill_edges<<<EB, 256>>>(edge_src, edge_dst, N_E);

    // ---- input projections: h = x @ W^T + b + emb ----
    gemm_pair(
        { x_mi, nullptr, W_mi, nullptr, 0, b_mi, emb_mi, hA_mi, N_MI, 128, 256, 0 },
        { x_di, nullptr, W_di, nullptr, 0, b_di, emb_di, hA_di, N_DI, 128, 128, 0 });

    // ---- Layer 1 (agg-first, 128 -> 256, relu), k-dual ----
    agg_plain128_2<<<AG_DI + AG_MI, 256>>>(hA_mi, t_di, hA_di, t_mi);
    gemm_pair(
        { t_di, hA_di, Wl[0][0], Wr[0][0], 0, bl[0][0], nullptr, hB_di, N_DI, 256, 128, 1 },
        { t_mi, hA_mi, Wl[0][1], Wr[0][1], 0, bl[0][1], nullptr, hB_mi, N_MI, 256, 128, 1 });

    // ---- Layer 2 (fused transform+root, 256 -> 128, relu) ----
    gemm_pair(
        { hB_mi, nullptr, Wl[1][0], Wr[1][1], 128, bl[1][1], nullptr, t_mi, N_MI, 256, 256, 0 },
        { hB_di, nullptr, Wl[1][1], Wr[1][0], 128, bl[1][0], nullptr, t_di, N_DI, 256, 256, 0 });
    agg_fused128_2<<<AG_DI + AG_MI, 256>>>(t_mi, t_di, hA_di, t_di, t_mi, hA_mi);

    // ---- Layer 3 (fused transform+root, 128 -> 64, no relu) ----
    gemm_pair(
        { hA_mi, nullptr, Wl[2][0], Wr[2][1], 64, bl[2][1], nullptr, t_mi, N_MI, 128, 128, 0 },
        { hA_di, nullptr, Wl[2][1], Wr[2][0], 64, bl[2][0], nullptr, t_di, N_DI, 128, 128, 0 });
    agg_fused64_2<<<AG_DI + AG_MI, 256>>>(t_mi, t_di, hB_di, t_di, t_mi, hB_mi);

    // ---- classifier ----
    dot64<<<(N_L + 7) / 8, 256>>>(hB_mi, hB_di, label_src, label_dst, out, N_L);
}

// round 11
// speedup vs baseline: 1.3302x; 1.0452x over previous
#include <cuda_runtime.h>
#include <cuda_fp16.h>
#include <cstdint>

// ---------------- problem constants ----------------
#define N_MI   100000
#define N_DI   50000
#define N_E    500000
#define N_L    200000

static constexpr int NB_DI = (N_DI + 1023) / 1024;   // 49
static constexpr int NB_MI = (N_MI + 1023) / 1024;   // 98
static constexpr int WTOT = 344064;                  // total weight elements

// ---------------- device scratch ----------------
__device__ float g_hA_mi[(size_t)N_MI * 256];
__device__ float g_hB_mi[(size_t)N_MI * 256];
__device__ float g_hA_di[(size_t)N_DI * 256];
__device__ float g_hB_di[(size_t)N_DI * 256];
__device__ float g_t_mi[(size_t)N_MI * 256];
__device__ float g_t_di[(size_t)N_DI * 256];

__device__ __half g_whi[WTOT];
__device__ __half g_wlo[WTOT];

__device__ int g_rowptr_di[N_DI + 1];
__device__ int g_rowptr_mi[N_MI + 1];
__device__ int g_col_di[N_E];
__device__ int g_col_mi[N_E];
__device__ int g_cnt_di[N_DI];
__device__ int g_cnt_mi[N_MI];
__device__ int g_bsum_di[NB_DI];
__device__ int g_bsum_mi[NB_MI];

// ---------------- helpers ----------------
__device__ __forceinline__ uint32_t smem_u32(const void* p) {
    uint32_t a;
    asm("{ .reg .u64 t; cvta.to.shared.u64 t, %1; cvt.u32.u64 %0, t; }"
        : "=r"(a) : "l"(p));
    return a;
}

__device__ __forceinline__ unsigned pack_f16x2(float x0, float x1) {
    unsigned r;
    asm("cvt.rn.f16x2.f32 %0, %1, %2;" : "=r"(r) : "f"(x1), "f"(x0));
    return r;
}

__device__ __forceinline__ void mma_f16(float* c, const unsigned* a, unsigned b0, unsigned b1) {
    asm volatile(
        "mma.sync.aligned.m16n8k16.row.col.f32.f16.f16.f32 "
        "{%0,%1,%2,%3}, {%4,%5,%6,%7}, {%8,%9}, {%0,%1,%2,%3};"
        : "+f"(c[0]), "+f"(c[1]), "+f"(c[2]), "+f"(c[3])
        : "r"(a[0]), "r"(a[1]), "r"(a[2]), "r"(a[3]), "r"(b0), "r"(b1));
}

__device__ __forceinline__ void ldsm_x4(uint32_t addr, unsigned& r0, unsigned& r1,
                                        unsigned& r2, unsigned& r3) {
    asm volatile("ldmatrix.sync.aligned.m8n8.x4.shared.b16 {%0,%1,%2,%3}, [%4];"
                 : "=r"(r0), "=r"(r1), "=r"(r2), "=r"(r3) : "r"(addr));
}

#define STS128(addr, a, b, c, d) \
    asm volatile("st.shared.v4.b32 [%0], {%1,%2,%3,%4};" \
                 :: "r"(addr), "r"(a), "r"(b), "r"(c), "r"(d))

// ---------------- weight pre-split: fp32 -> fp16 hi + fp16 residual ----------------
struct WEnt { const float* src; int off; int n; };
struct PSArgs { WEnt e[14]; };

__global__ void presplit(PSArgs a) {
    WEnt w = a.e[blockIdx.y];
    for (int i = blockIdx.x * blockDim.x + threadIdx.x; i < w.n;
         i += gridDim.x * blockDim.x) {
        float x = w.src[i];
        __half h = __float2half_rn(x);
        g_whi[w.off + i] = h;
        g_wlo[w.off + i] = __float2half_rn(x - __half2float(h));
    }
}

// ---------------- paired fp16 2-pass GEMM, BM=64 x BN=64, KC=64 ---------------------
// acc = fp16(A) @ (Bhi + Blo)^T with B pre-split in gmem (fp16 planes).
// Two independent GEMM problems per launch (grid.y partitioned at yb0).
// nsplit>0 (and no k-dual): output col < nsplit from B0 (no bias); col >= nsplit
// from B1 (bias indexed col-nsplit).
struct GArgs {
    const float *A0, *A1;
    const __half *B0h, *B0l, *B1h, *B1l;
    int nsplit;
    const float *bias, *addend;
    float* C;
    int M, N, K, relu;
};

static constexpr uint32_t APL = 64 * 128;          // 8 KB plane (64 rows x 128B)
static constexpr uint32_t STAGE = 3 * APL;         // A, Bh, Bl = 24 KB
static constexpr int GSMEM = 2 * (int)STAGE + 128; // 49280 (2 stages)

__global__ void __launch_bounds__(256, 3) mma_gemm2(GArgs g0, GArgs g1, int yb0) {
    const GArgs& g = (blockIdx.y < (unsigned)yb0) ? g0 : g1;
    const int my = (blockIdx.y < (unsigned)yb0) ? blockIdx.y : blockIdx.y - yb0;

    extern __shared__ char smem_raw[];
    const uint32_t base = (smem_u32(smem_raw) + 127u) & ~127u;

    const int tid = threadIdx.x, lane = tid & 31, wid = tid >> 5;
    const int wm = wid & 1, wn = wid >> 1;          // warp tile 32(m) x 16(n)
    const int group = lane >> 2, tig = lane & 3;
    const int m0 = my * 64, n0 = blockIdx.x * 64;
    const int M = g.M, N = g.N, K = g.K;

    float acc[2][2][4];
    #pragma unroll
    for (int i = 0; i < 2; ++i)
        #pragma unroll
        for (int j = 0; j < 2; ++j)
            #pragma unroll
            for (int q = 0; q < 4; ++q) acc[i][j][q] = 0.f;

    const int kch = K >> 6;
    const bool kdual = (g.A1 != nullptr);
    const int nch = kdual ? 2 * kch : kch;

    float4 ra[4];                       // A staging: 2 row-sweeps x 8 floats
    const int arow[2] = { tid >> 3, (256 + tid) >> 3 };
    const int ach = tid & 7;

    auto prefetchA = [&](int c) {
        const int p = (c >= kch) ? 1 : 0;
        const int k0 = (c - p * kch) << 6;
        const float* A = p ? g.A1 : g.A0;
        #pragma unroll
        for (int it = 0; it < 2; ++it) {
            int gr = m0 + arow[it];
            const float* ap = A + (size_t)gr * K + k0 + ach * 8;
            if (gr < M) {
                ra[2*it]   = *(const float4*)ap;
                ra[2*it+1] = *(const float4*)(ap + 4);
            } else {
                ra[2*it] = ra[2*it+1] = make_float4(0.f, 0.f, 0.f, 0.f);
            }
        }
    };

    auto store_stage = [&](int st, int c) {
        const uint32_t sa  = base + (uint32_t)st * STAGE;
        const uint32_t sbh = sa + APL;
        const uint32_t sbl = sa + 2 * APL;
        // A: pack fp32 -> fp16 plane (one STS128 per row-sweep)
        #pragma unroll
        for (int it = 0; it < 2; ++it) {
            int r = arow[it];
            uint32_t off = (uint32_t)(r * 128 + ((ach ^ (r & 7)) << 4));
            unsigned w0 = pack_f16x2(ra[2*it].x,   ra[2*it].y);
            unsigned w1 = pack_f16x2(ra[2*it].z,   ra[2*it].w);
            unsigned w2 = pack_f16x2(ra[2*it+1].x, ra[2*it+1].y);
            unsigned w3 = pack_f16x2(ra[2*it+1].z, ra[2*it+1].w);
            STS128(sa + off, w0, w1, w2, w3);
        }
        // B: pre-split fp16 hi/lo planes loaded directly (no conversion)
        const int p = (c >= kch) ? 1 : 0;
        const int k0 = (c - p * kch) << 6;
        #pragma unroll
        for (int it = 0; it < 2; ++it) {
            int r = arow[it];
            int gcol = n0 + r;
            const __half *bh, *bl;
            if (kdual) {
                bh = p ? g.B1h : g.B0h;
                bl = p ? g.B1l : g.B0l;
            } else if (g.nsplit > 0 && gcol >= g.nsplit) {
                bh = g.B1h; bl = g.B1l; gcol -= g.nsplit;
            } else {
                bh = g.B0h; bl = g.B0l;
            }
            size_t ro = (size_t)gcol * K + k0 + ach * 8;
            uint4 hv = *(const uint4*)(bh + ro);
            uint4 lv = *(const uint4*)(bl + ro);
            uint32_t off = (uint32_t)(r * 128 + ((ach ^ (r & 7)) << 4));
            STS128(sbh + off, hv.x, hv.y, hv.z, hv.w);
            STS128(sbl + off, lv.x, lv.y, lv.z, lv.w);
        }
    };

    auto mma_stage = [&](int st) {
        const uint32_t sa  = base + (uint32_t)st * STAGE;
        const uint32_t sbh = sa + APL;
        const uint32_t sbl = sa + 2 * APL;
        const int lrow = lane & 15, lsel = lane >> 4;
        #pragma unroll
        for (int s = 0; s < 4; ++s) {
            const int ch = 2 * s + lsel;
            unsigned bh[4], bl[4];
            {
                int r = wn * 16 + lrow;
                uint32_t off = (uint32_t)(r * 128 + ((ch ^ (r & 7)) << 4));
                ldsm_x4(sbh + off, bh[0], bh[1], bh[2], bh[3]);
                ldsm_x4(sbl + off, bl[0], bl[1], bl[2], bl[3]);
            }
            unsigned ah[2][4];
            #pragma unroll
            for (int i = 0; i < 2; ++i) {
                int r = wm * 32 + i * 16 + lrow;
                uint32_t off = (uint32_t)(r * 128 + ((ch ^ (r & 7)) << 4));
                ldsm_x4(sa + off, ah[i][0], ah[i][1], ah[i][2], ah[i][3]);
            }
            #pragma unroll
            for (int pass = 0; pass < 2; ++pass) {
                const unsigned* bf = pass ? bl : bh;
                #pragma unroll
                for (int i = 0; i < 2; ++i)
                    #pragma unroll
                    for (int j = 0; j < 2; ++j)
                        mma_f16(acc[i][j], ah[i], bf[j], bf[j + 2]);
            }
        }
    };

    prefetchA(0);
    store_stage(0, 0);
    __syncthreads();

    for (int c = 0; c < nch; ++c) {
        if (c + 1 < nch) prefetchA(c + 1);
        mma_stage(c & 1);
        if (c + 1 < nch) store_stage((c + 1) & 1, c + 1);
        __syncthreads();
    }

    // epilogue
    #pragma unroll
    for (int i = 0; i < 2; ++i) {
        int row = m0 + wm * 32 + i * 16 + group;
        #pragma unroll
        for (int j = 0; j < 2; ++j) {
            int colg = n0 + wn * 16 + j * 8 + 2 * tig;
            float b0 = 0.f, b1 = 0.f;
            if (g.bias) {
                if (g.nsplit > 0 && !kdual) {
                    if (colg >= g.nsplit) {
                        b0 = __ldg(g.bias + colg - g.nsplit);
                        b1 = __ldg(g.bias + colg - g.nsplit + 1);
                    }
                } else {
                    b0 = __ldg(g.bias + colg);
                    b1 = __ldg(g.bias + colg + 1);
                }
            }
            if (row < M) {
                float v0 = acc[i][j][0] + b0, v1 = acc[i][j][1] + b1;
                if (g.addend) {
                    const float* ap = g.addend + (size_t)row * N + colg;
                    v0 += ap[0]; v1 += ap[1];
                }
                if (g.relu) { v0 = fmaxf(v0, 0.f); v1 = fmaxf(v1, 0.f); }
                *(float2*)(g.C + (size_t)row * N + colg) = make_float2(v0, v1);
            }
            int row2 = row + 8;
            if (row2 < M) {
                float v0 = acc[i][j][2] + b0, v1 = acc[i][j][3] + b1;
                if (g.addend) {
                    const float* ap = g.addend + (size_t)row2 * N + colg;
                    v0 += ap[0]; v1 += ap[1];
                }
                if (g.relu) { v0 = fmaxf(v0, 0.f); v1 = fmaxf(v1, 0.f); }
                *(float2*)(g.C + (size_t)row2 * N + colg) = make_float2(v0, v1);
            }
        }
    }
}

// ---------------- CSR build ----------------
__global__ void count_edges(const int* __restrict__ src, const int* __restrict__ dst, int e) {
    int i = blockIdx.x * blockDim.x + threadIdx.x;
    if (i < e) {
        atomicAdd(&g_cnt_mi[src[i]], 1);
        atomicAdd(&g_cnt_di[dst[i]], 1);
    }
}

__global__ void scan_p1() {
    const int* cnt; int* rp; int* bsum; int n, b;
    if (blockIdx.x < NB_DI) {
        cnt = g_cnt_di; rp = g_rowptr_di; bsum = g_bsum_di; n = N_DI; b = blockIdx.x;
    } else {
        cnt = g_cnt_mi; rp = g_rowptr_mi; bsum = g_bsum_mi; n = N_MI; b = blockIdx.x - NB_DI;
    }
    __shared__ int warpsum[32];
    int tid = threadIdx.x, lane = tid & 31, wid = tid >> 5;
    int i = b * 1024 + tid;
    int v = (i < n) ? cnt[i] : 0;
    int x = v;
    #pragma unroll
    for (int off = 1; off < 32; off <<= 1) {
        int t = __shfl_up_sync(0xffffffffu, x, off);
        if (lane >= off) x += t;
    }
    if (lane == 31) warpsum[wid] = x;
    __syncthreads();
    if (wid == 0) {
        int w = warpsum[lane];
        #pragma unroll
        for (int off = 1; off < 32; off <<= 1) {
            int t = __shfl_up_sync(0xffffffffu, w, off);
            if (lane >= off) w += t;
        }
        warpsum[lane] = w;
    }
    __syncthreads();
    int excl = x - v + (wid ? warpsum[wid - 1] : 0);
    if (i < n) rp[i] = excl;
    if (tid == 0) bsum[b] = warpsum[31];
}

__global__ void scan_p2() {
    if (threadIdx.x == 0) {
        int run = 0;
        for (int i = 0; i < NB_DI; ++i) { int t = g_bsum_di[i]; g_bsum_di[i] = run; run += t; }
    }
    if (threadIdx.x == 1) {
        int run = 0;
        for (int i = 0; i < NB_MI; ++i) { int t = g_bsum_mi[i]; g_bsum_mi[i] = run; run += t; }
    }
}

__global__ void scan_p3() {
    int* rp; const int* bsum; int n, b;
    if (blockIdx.x < NB_DI) {
        rp = g_rowptr_di; bsum = g_bsum_di; n = N_DI; b = blockIdx.x;
    } else {
        rp = g_rowptr_mi; bsum = g_bsum_mi; n = N_MI; b = blockIdx.x - NB_DI;
    }
    int i = b * 1024 + threadIdx.x;
    if (i < n) rp[i] += bsum[b];
    if (b == 0 && threadIdx.x == 0) rp[n] = N_E;
}

__global__ void fill_edges(const int* __restrict__ src, const int* __restrict__ dst, int e) {
    int i = blockIdx.x * blockDim.x + threadIdx.x;
    if (i < e) {
        int s = src[i], d = dst[i];
        int pd = g_rowptr_di[d] + atomicAdd(&g_cnt_di[d], 1);
        g_col_di[pd] = s;
        int pm = g_rowptr_mi[s] + atomicAdd(&g_cnt_mi[s], 1);
        g_col_mi[pm] = d;
    }
}

// ---------------- merged aggregation kernels (di blocks first, then mi) ----------------
static constexpr int AG_DI = (N_DI + 7) / 8;
static constexpr int AG_MI = (N_MI + 7) / 8;

__global__ void agg_plain128_2(const float* __restrict__ x_d, float* __restrict__ o_d,
                               const float* __restrict__ x_m, float* __restrict__ o_m) {
    const float* x; float* out; const int* rowptr; const int* col; int n, blk;
    if (blockIdx.x < AG_DI) {
        x = x_d; out = o_d; rowptr = g_rowptr_di; col = g_col_di; n = N_DI; blk = blockIdx.x;
    } else {
        x = x_m; out = o_m; rowptr = g_rowptr_mi; col = g_col_mi; n = N_MI; blk = blockIdx.x - AG_DI;
    }
    int warp = blk * 8 + (threadIdx.x >> 5);
    int lane = threadIdx.x & 31;
    if (warp >= n) return;
    int s = rowptr[warp], e = rowptr[warp + 1];
    float4 acc = make_float4(0.f, 0.f, 0.f, 0.f);
    int i = s;
    for (; i + 1 < e; i += 2) {
        float4 a = __ldg((const float4*)(x + (size_t)col[i] * 128) + lane);
        float4 b = __ldg((const float4*)(x + (size_t)col[i + 1] * 128) + lane);
        acc.x += a.x + b.x; acc.y += a.y + b.y;
        acc.z += a.z + b.z; acc.w += a.w + b.w;
    }
    if (i < e) {
        float4 a = __ldg((const float4*)(x + (size_t)col[i] * 128) + lane);
        acc.x += a.x; acc.y += a.y; acc.z += a.z; acc.w += a.w;
    }
    float inv = 1.f / fmaxf((float)(e - s), 1.f);
    acc.x *= inv; acc.y *= inv; acc.z *= inv; acc.w *= inv;
    ((float4*)(out + (size_t)warp * 128))[lane] = acc;
}

__global__ void agg_fused128_2(const float* __restrict__ s_d, const float* __restrict__ r_d,
                               float* __restrict__ o_d,
                               const float* __restrict__ s_m, const float* __restrict__ r_m,
                               float* __restrict__ o_m) {
    const float *srcC, *rootC; float* out; const int *rowptr, *col; int n, blk;
    if (blockIdx.x < AG_DI) {
        srcC = s_d; rootC = r_d; out = o_d; rowptr = g_rowptr_di; col = g_col_di; n = N_DI; blk = blockIdx.x;
    } else {
        srcC = s_m; rootC = r_m; out = o_m; rowptr = g_rowptr_mi; col = g_col_mi; n = N_MI; blk = blockIdx.x - AG_DI;
    }
    int warp = blk * 8 + (threadIdx.x >> 5);
    int lane = threadIdx.x & 31;
    if (warp >= n) return;
    int s = rowptr[warp], e = rowptr[warp + 1];
    float4 acc = make_float4(0.f, 0.f, 0.f, 0.f);
    int i = s;
    for (; i + 1 < e; i += 2) {
        float4 a = __ldg((const float4*)(srcC + (size_t)col[i] * 256) + lane);
        float4 b = __ldg((const float4*)(srcC + (size_t)col[i + 1] * 256) + lane);
        acc.x += a.x + b.x; acc.y += a.y + b.y;
        acc.z += a.z + b.z; acc.w += a.w + b.w;
    }
    if (i < e) {
        float4 a = __ldg((const float4*)(srcC + (size_t)col[i] * 256) + lane);
        acc.x += a.x; acc.y += a.y; acc.z += a.z; acc.w += a.w;
    }
    float inv = 1.f / fmaxf((float)(e - s), 1.f);
    float4 r = __ldg((const float4*)(rootC + (size_t)warp * 256 + 128) + lane);
    float4 v;
    v.x = fmaxf(acc.x * inv + r.x, 0.f);
    v.y = fmaxf(acc.y * inv + r.y, 0.f);
    v.z = fmaxf(acc.z * inv + r.z, 0.f);
    v.w = fmaxf(acc.w * inv + r.w, 0.f);
    ((float4*)(out + (size_t)warp * 128))[lane] = v;
}

__global__ void agg_fused64_2(const float* __restrict__ s_d, const float* __restrict__ r_d,
                              float* __restrict__ o_d,
                              const float* __restrict__ s_m, const float* __restrict__ r_m,
                              float* __restrict__ o_m) {
    const float *srcC, *rootC; float* out; const int *rowptr, *col; int n, blk;
    if (blockIdx.x < AG_DI) {
        srcC = s_d; rootC = r_d; out = o_d; rowptr = g_rowptr_di; col = g_col_di; n = N_DI; blk = blockIdx.x;
    } else {
        srcC = s_m; rootC = r_m; out = o_m; rowptr = g_rowptr_mi; col = g_col_mi; n = N_MI; blk = blockIdx.x - AG_DI;
    }
    int warp = blk * 8 + (threadIdx.x >> 5);
    int lane = threadIdx.x & 31;
    if (warp >= n) return;
    int s = rowptr[warp], e = rowptr[warp + 1];
    float2 acc = make_float2(0.f, 0.f);
    int i = s;
    for (; i + 1 < e; i += 2) {
        float2 a = __ldg((const float2*)(srcC + (size_t)col[i] * 128) + lane);
        float2 b = __ldg((const float2*)(srcC + (size_t)col[i + 1] * 128) + lane);
        acc.x += a.x + b.x; acc.y += a.y + b.y;
    }
    if (i < e) {
        float2 a = __ldg((const float2*)(srcC + (size_t)col[i] * 128) + lane);
        acc.x += a.x; acc.y += a.y;
    }
    float inv = 1.f / fmaxf((float)(e - s), 1.f);
    float2 r = __ldg((const float2*)(rootC + (size_t)warp * 128 + 64) + lane);
    float2 v = make_float2(acc.x * inv + r.x, acc.y * inv + r.y);
    ((float2*)(out + (size_t)warp * 64))[lane] = v;
}

// ---------------- classifier ----------------
__global__ void dot64(const float* __restrict__ hmi, const float* __restrict__ hdi,
                      const int* __restrict__ lsrc, const int* __restrict__ ldst,
                      float* __restrict__ out, int L) {
    int warp = (blockIdx.x * blockDim.x + threadIdx.x) >> 5;
    int lane = threadIdx.x & 31;
    if (warp >= L) return;
    const float2* a = (const float2*)(hmi + (size_t)lsrc[warp] * 64);
    const float2* b = (const float2*)(hdi + (size_t)ldst[warp] * 64);
    float2 av = a[lane], bv = b[lane];
    float p = av.x * bv.x + av.y * bv.y;
    #pragma unroll
    for (int off = 16; off; off >>= 1) p += __shfl_down_sync(0xffffffffu, p, off);
    if (lane == 0) out[warp] = p;
}

// ---------------- host orchestration ----------------
static inline void gemm_pair(const GArgs& a, const GArgs& b) {
    int yb0 = (a.M + 63) / 64, yb1 = (b.M + 63) / 64;
    mma_gemm2<<<dim3(a.N / 64, yb0 + yb1), 256, GSMEM>>>(a, b, yb0);
}

extern "C" void kernel_launch(void* const* d_in, const int* in_sizes, int n_in,
                              void* d_out, int out_size) {
    const float* x_mi   = (const float*)d_in[0];
    const float* x_di   = (const float*)d_in[1];
    const float* W_mi   = (const float*)d_in[2];
    const float* b_mi   = (const float*)d_in[3];
    const float* W_di   = (const float*)d_in[4];
    const float* b_di   = (const float*)d_in[5];
    const float* emb_mi = (const float*)d_in[6];
    const float* emb_di = (const float*)d_in[7];
    const float *Wl[3][2], *bl[3][2], *Wr[3][2];   // [layer][0=md,1=dm]
    for (int i = 0; i < 3; ++i)
        for (int r = 0; r < 2; ++r) {
            int base = 8 + i * 6 + r * 3;
            Wl[i][r] = (const float*)d_in[base];
            bl[i][r] = (const float*)d_in[base + 1];
            Wr[i][r] = (const float*)d_in[base + 2];
        }
    const int* edge_src  = (const int*)d_in[26];
    const int* edge_dst  = (const int*)d_in[27];
    const int* label_src = (const int*)d_in[28];
    const int* label_dst = (const int*)d_in[29];
    float* out = (float*)d_out;

    cudaFuncSetAttribute(mma_gemm2, cudaFuncAttributeMaxDynamicSharedMemorySize, GSMEM);

    float *hA_mi, *hB_mi, *hA_di, *hB_di, *t_mi, *t_di;
    __half *whi, *wlo;
    int *cnt_di, *cnt_mi;
    cudaGetSymbolAddress((void**)&hA_mi, g_hA_mi);
    cudaGetSymbolAddress((void**)&hB_mi, g_hB_mi);
    cudaGetSymbolAddress((void**)&hA_di, g_hA_di);
    cudaGetSymbolAddress((void**)&hB_di, g_hB_di);
    cudaGetSymbolAddress((void**)&t_mi, g_t_mi);
    cudaGetSymbolAddress((void**)&t_di, g_t_di);
    cudaGetSymbolAddress((void**)&whi, g_whi);
    cudaGetSymbolAddress((void**)&wlo, g_wlo);
    cudaGetSymbolAddress((void**)&cnt_di, g_cnt_di);
    cudaGetSymbolAddress((void**)&cnt_mi, g_cnt_mi);

    // ---- weight offsets in the pre-split planes ----
    // order: W_mi, W_di, Wl1_md, Wr1_md, Wl1_dm, Wr1_dm,
    //        Wl2_md, Wr2_md, Wl2_dm, Wr2_dm, Wl3_md, Wr3_md, Wl3_dm, Wr3_dm
    PSArgs ps;
    int woff[14];
    {
        const float* srcs[14] = {
            W_mi, W_di,
            Wl[0][0], Wr[0][0], Wl[0][1], Wr[0][1],
            Wl[1][0], Wr[1][0], Wl[1][1], Wr[1][1],
            Wl[2][0], Wr[2][0], Wl[2][1], Wr[2][1] };
        const int sizes[14] = {
            128 * 256, 128 * 128,
            256 * 128, 256 * 128, 256 * 128, 256 * 128,
            128 * 256, 128 * 256, 128 * 256, 128 * 256,
            64 * 128, 64 * 128, 64 * 128, 64 * 128 };
        int off = 0;
        for (int i = 0; i < 14; ++i) {
            ps.e[i] = { srcs[i], off, sizes[i] };
            woff[i] = off;
            off += sizes[i];
        }
    }
    auto WH = [&](int i) { return (const __half*)(whi + woff[i]); };
    auto WL = [&](int i) { return (const __half*)(wlo + woff[i]); };

    const int EB = (N_E + 255) / 256;

    // ---- weight pre-split + CSR build ----
    presplit<<<dim3(64, 14), 256>>>(ps);
    cudaMemsetAsync(cnt_di, 0, N_DI * sizeof(int));
    cudaMemsetAsync(cnt_mi, 0, N_MI * sizeof(int));
    count_edges<<<EB, 256>>>(edge_src, edge_dst, N_E);
    scan_p1<<<NB_DI + NB_MI, 1024>>>();
    scan_p2<<<1, 32>>>();
    scan_p3<<<NB_DI + NB_MI, 1024>>>();
    cudaMemsetAsync(cnt_di, 0, N_DI * sizeof(int));
    cudaMemsetAsync(cnt_mi, 0, N_MI * sizeof(int));
    fill_edges<<<EB, 256>>>(edge_src, edge_dst, N_E);

    // ---- input projections: h = x @ W^T + b + emb ----
    gemm_pair(
        { x_mi, nullptr, WH(0), WL(0), nullptr, nullptr, 0, b_mi, emb_mi, hA_mi, N_MI, 128, 256, 0 },
        { x_di, nullptr, WH(1), WL(1), nullptr, nullptr, 0, b_di, emb_di, hA_di, N_DI, 128, 128, 0 });

    // ---- Layer 1 (agg-first, 128 -> 256, relu), k-dual ----
    agg_plain128_2<<<AG_DI + AG_MI, 256>>>(hA_mi, t_di, hA_di, t_mi);
    gemm_pair(
        { t_di, hA_di, WH(2), WL(2), WH(3), WL(3), 0, bl[0][0], nullptr, hB_di, N_DI, 256, 128, 1 },
        { t_mi, hA_mi, WH(4), WL(4), WH(5), WL(5), 0, bl[0][1], nullptr, hB_mi, N_MI, 256, 128, 1 });

    // ---- Layer 2 (fused transform+root, 256 -> 128, relu) ----
    gemm_pair(
        { hB_mi, nullptr, WH(6), WL(6), WH(9), WL(9), 128, bl[1][1], nullptr, t_mi, N_MI, 256, 256, 0 },
        { hB_di, nullptr, WH(8), WL(8), WH(7), WL(7), 128, bl[1][0], nullptr, t_di, N_DI, 256, 256, 0 });
    agg_fused128_2<<<AG_DI + AG_MI, 256>>>(t_mi, t_di, hA_di, t_di, t_mi, hA_mi);

    // ---- Layer 3 (fused transform+root, 128 -> 64, no relu) ----
    gemm_pair(
        { hA_mi, nullptr, WH(10), WL(10), WH(13), WL(13), 64, bl[2][1], nullptr, t_mi, N_MI, 128, 128, 0 },
        { hA_di, nullptr, WH(12), WL(12), WH(11), WL(11), 64, bl[2][0], nullptr, t_di, N_DI, 128, 128, 0 });
    agg_fused64_2<<<AG_DI + AG_MI, 256>>>(t_mi, t_di, hB_di, t_di, t_mi, hB_mi);

    // ---- classifier ----
    dot64<<<(N_L + 7) / 8, 256>>>(hB_mi, hB_di, label_src, label_dst, out, N_L);
}

// round 12
// speedup vs baseline: 1.3533x; 1.0174x over previous
#include <cuda_runtime.h>
#include <cuda_fp16.h>
#include <cstdint>

// ---------------- problem constants ----------------
#define N_MI   100000
#define N_DI   50000
#define N_E    500000
#define N_L    200000

static constexpr int NB_DI = (N_DI + 1023) / 1024;   // 49
static constexpr int NB_MI = (N_MI + 1023) / 1024;   // 98
static constexpr int WTOT = 344064;                  // total weight elements

// ---------------- device scratch ----------------
__device__ float g_hA_mi[(size_t)N_MI * 128];       // proj out (agg src), fp32
__device__ float g_hA_di[(size_t)N_DI * 128];
__device__ float g_t_mi[(size_t)N_MI * 256];        // L2/L3 GEMM outs, fp32
__device__ float g_t_di[(size_t)N_DI * 256];
__device__ float g_o_mi[(size_t)N_MI * 64];         // final embeddings, fp32
__device__ float g_o_di[(size_t)N_DI * 64];

__device__ __half g_x16_mi[(size_t)N_MI * 256];     // fp16 activation planes
__device__ __half g_x16_di[(size_t)N_DI * 128];
__device__ __half g_a16_mi[(size_t)N_MI * 256];     // proj out / L2-agg out
__device__ __half g_a16_di[(size_t)N_DI * 256];
__device__ __half g_b16_mi[(size_t)N_MI * 256];     // L1 GEMM out
__device__ __half g_b16_di[(size_t)N_DI * 256];
__device__ __half g_t16_mi[(size_t)N_MI * 128];     // L1 agg out
__device__ __half g_t16_di[(size_t)N_DI * 128];

__device__ __half g_whi[WTOT];
__device__ __half g_wlo[WTOT];

__device__ int g_rowptr_di[N_DI + 1];
__device__ int g_rowptr_mi[N_MI + 1];
__device__ int g_col_di[N_E];
__device__ int g_col_mi[N_E];
__device__ int g_cnt_di[N_DI];
__device__ int g_cnt_mi[N_MI];
__device__ int g_bsum_di[NB_DI];
__device__ int g_bsum_mi[NB_MI];

// ---------------- helpers ----------------
__device__ __forceinline__ uint32_t smem_u32(const void* p) {
    uint32_t a;
    asm("{ .reg .u64 t; cvta.to.shared.u64 t, %1; cvt.u32.u64 %0, t; }"
        : "=r"(a) : "l"(p));
    return a;
}

__device__ __forceinline__ unsigned pack_f16x2(float x0, float x1) {
    unsigned r;
    asm("cvt.rn.f16x2.f32 %0, %1, %2;" : "=r"(r) : "f"(x1), "f"(x0));
    return r;
}

__device__ __forceinline__ void mma_f16(float* c, const unsigned* a, unsigned b0, unsigned b1) {
    asm volatile(
        "mma.sync.aligned.m16n8k16.row.col.f32.f16.f16.f32 "
        "{%0,%1,%2,%3}, {%4,%5,%6,%7}, {%8,%9}, {%0,%1,%2,%3};"
        : "+f"(c[0]), "+f"(c[1]), "+f"(c[2]), "+f"(c[3])
        : "r"(a[0]), "r"(a[1]), "r"(a[2]), "r"(a[3]), "r"(b0), "r"(b1));
}

__device__ __forceinline__ void ldsm_x4(uint32_t addr, unsigned& r0, unsigned& r1,
                                        unsigned& r2, unsigned& r3) {
    asm volatile("ldmatrix.sync.aligned.m8n8.x4.shared.b16 {%0,%1,%2,%3}, [%4];"
                 : "=r"(r0), "=r"(r1), "=r"(r2), "=r"(r3) : "r"(addr));
}

#define STS128(addr, a, b, c, d) \
    asm volatile("st.shared.v4.b32 [%0], {%1,%2,%3,%4};" \
                 :: "r"(addr), "r"(a), "r"(b), "r"(c), "r"(d))

// ---------------- weight pre-split + activation convert ----------------
struct WEnt { const float* src; int off; int n; };
struct PSArgs { WEnt e[14]; };

__global__ void presplit(PSArgs a) {
    WEnt w = a.e[blockIdx.y];
    for (int i = blockIdx.x * blockDim.x + threadIdx.x; i < w.n;
         i += gridDim.x * blockDim.x) {
        float x = w.src[i];
        __half h = __float2half_rn(x);
        g_whi[w.off + i] = h;
        g_wlo[w.off + i] = __float2half_rn(x - __half2float(h));
    }
}

__global__ void f32to16(const float* __restrict__ s0, __half* __restrict__ d0, int n0,
                        const float* __restrict__ s1, __half* __restrict__ d1, int n1) {
    const float* s = blockIdx.y ? s1 : s0;
    __half* d      = blockIdx.y ? d1 : d0;
    int n          = blockIdx.y ? n1 : n0;
    int stride = gridDim.x * blockDim.x;
    for (int i = blockIdx.x * blockDim.x + threadIdx.x; i < n / 4; i += stride) {
        float4 v = ((const float4*)s)[i];
        uint2 o;
        o.x = pack_f16x2(v.x, v.y);
        o.y = pack_f16x2(v.z, v.w);
        ((uint2*)d)[i] = o;
    }
}

// ---------------- paired fp16 2-pass GEMM, BM=64 x BN=64, KC=64 ---------------------
// acc = A16 @ (Bhi + Blo)^T, A pre-converted fp16 in gmem, B pre-split fp16.
// Epilogue writes fp32 C and/or fp16 C16 (+bias)(+addend fp32), opt relu.
struct GArgs {
    const __half *A0, *A1;
    const __half *B0h, *B0l, *B1h, *B1l;
    int nsplit;
    const float *bias, *addend;
    float* C;
    __half* C16;
    int M, N, K, relu;
};

static constexpr uint32_t APL = 64 * 128;          // 8 KB plane (64 rows x 128B)
static constexpr uint32_t STAGE = 3 * APL;         // A, Bh, Bl = 24 KB
static constexpr int GSMEM = 2 * (int)STAGE + 128; // 49280 (2 stages)

__global__ void __launch_bounds__(256, 3) mma_gemm2(GArgs g0, GArgs g1, int yb0) {
    const GArgs& g = (blockIdx.y < (unsigned)yb0) ? g0 : g1;
    const int my = (blockIdx.y < (unsigned)yb0) ? blockIdx.y : blockIdx.y - yb0;

    extern __shared__ char smem_raw[];
    const uint32_t base = (smem_u32(smem_raw) + 127u) & ~127u;

    const int tid = threadIdx.x, lane = tid & 31, wid = tid >> 5;
    const int wm = wid & 1, wn = wid >> 1;          // warp tile 32(m) x 16(n)
    const int group = lane >> 2, tig = lane & 3;
    const int m0 = my * 64, n0 = blockIdx.x * 64;
    const int M = g.M, N = g.N, K = g.K;

    float acc[2][2][4];
    #pragma unroll
    for (int i = 0; i < 2; ++i)
        #pragma unroll
        for (int j = 0; j < 2; ++j)
            #pragma unroll
            for (int q = 0; q < 4; ++q) acc[i][j][q] = 0.f;

    const int kch = K >> 6;
    const bool kdual = (g.A1 != nullptr);
    const int nch = kdual ? 2 * kch : kch;

    uint4 ra16[2];                      // A staging: 2 row-sweeps x 8 halves
    const int arow[2] = { tid >> 3, (256 + tid) >> 3 };
    const int ach = tid & 7;

    auto prefetchA = [&](int c) {
        const int p = (c >= kch) ? 1 : 0;
        const int k0 = (c - p * kch) << 6;
        const __half* A = p ? g.A1 : g.A0;
        #pragma unroll
        for (int it = 0; it < 2; ++it) {
            int gr = m0 + arow[it];
            ra16[it] = (gr < M)
                ? *(const uint4*)(A + (size_t)gr * K + k0 + ach * 8)
                : make_uint4(0u, 0u, 0u, 0u);
        }
    };

    auto store_stage = [&](int st, int c) {
        const uint32_t sa  = base + (uint32_t)st * STAGE;
        const uint32_t sbh = sa + APL;
        const uint32_t sbl = sa + 2 * APL;
        #pragma unroll
        for (int it = 0; it < 2; ++it) {
            int r = arow[it];
            uint32_t off = (uint32_t)(r * 128 + ((ach ^ (r & 7)) << 4));
            STS128(sa + off, ra16[it].x, ra16[it].y, ra16[it].z, ra16[it].w);
        }
        const int p = (c >= kch) ? 1 : 0;
        const int k0 = (c - p * kch) << 6;
        #pragma unroll
        for (int it = 0; it < 2; ++it) {
            int r = arow[it];
            int gcol = n0 + r;
            const __half *bh, *bl;
            if (kdual) {
                bh = p ? g.B1h : g.B0h;
                bl = p ? g.B1l : g.B0l;
            } else if (g.nsplit > 0 && gcol >= g.nsplit) {
                bh = g.B1h; bl = g.B1l; gcol -= g.nsplit;
            } else {
                bh = g.B0h; bl = g.B0l;
            }
            size_t ro = (size_t)gcol * K + k0 + ach * 8;
            uint4 hv = *(const uint4*)(bh + ro);
            uint4 lv = *(const uint4*)(bl + ro);
            uint32_t off = (uint32_t)(r * 128 + ((ach ^ (r & 7)) << 4));
            STS128(sbh + off, hv.x, hv.y, hv.z, hv.w);
            STS128(sbl + off, lv.x, lv.y, lv.z, lv.w);
        }
    };

    auto mma_stage = [&](int st) {
        const uint32_t sa  = base + (uint32_t)st * STAGE;
        const uint32_t sbh = sa + APL;
        const uint32_t sbl = sa + 2 * APL;
        const int lrow = lane & 15, lsel = lane >> 4;
        #pragma unroll
        for (int s = 0; s < 4; ++s) {
            const int ch = 2 * s + lsel;
            unsigned bh[4], bl[4];
            {
                int r = wn * 16 + lrow;
                uint32_t off = (uint32_t)(r * 128 + ((ch ^ (r & 7)) << 4));
                ldsm_x4(sbh + off, bh[0], bh[1], bh[2], bh[3]);
                ldsm_x4(sbl + off, bl[0], bl[1], bl[2], bl[3]);
            }
            unsigned ah[2][4];
            #pragma unroll
            for (int i = 0; i < 2; ++i) {
                int r = wm * 32 + i * 16 + lrow;
                uint32_t off = (uint32_t)(r * 128 + ((ch ^ (r & 7)) << 4));
                ldsm_x4(sa + off, ah[i][0], ah[i][1], ah[i][2], ah[i][3]);
            }
            #pragma unroll
            for (int pass = 0; pass < 2; ++pass) {
                const unsigned* bf = pass ? bl : bh;
                #pragma unroll
                for (int i = 0; i < 2; ++i)
                    #pragma unroll
                    for (int j = 0; j < 2; ++j)
                        mma_f16(acc[i][j], ah[i], bf[j], bf[j + 2]);
            }
        }
    };

    prefetchA(0);
    store_stage(0, 0);
    __syncthreads();

    for (int c = 0; c < nch; ++c) {
        if (c + 1 < nch) prefetchA(c + 1);
        mma_stage(c & 1);
        if (c + 1 < nch) store_stage((c + 1) & 1, c + 1);
        __syncthreads();
    }

    // epilogue
    #pragma unroll
    for (int i = 0; i < 2; ++i) {
        int row = m0 + wm * 32 + i * 16 + group;
        #pragma unroll
        for (int j = 0; j < 2; ++j) {
            int colg = n0 + wn * 16 + j * 8 + 2 * tig;
            float b0 = 0.f, b1 = 0.f;
            if (g.bias) {
                if (g.nsplit > 0 && !kdual) {
                    if (colg >= g.nsplit) {
                        b0 = __ldg(g.bias + colg - g.nsplit);
                        b1 = __ldg(g.bias + colg - g.nsplit + 1);
                    }
                } else {
                    b0 = __ldg(g.bias + colg);
                    b1 = __ldg(g.bias + colg + 1);
                }
            }
            #pragma unroll
            for (int h = 0; h < 2; ++h) {
                int r = row + 8 * h;
                if (r < M) {
                    float v0 = acc[i][j][2 * h] + b0, v1 = acc[i][j][2 * h + 1] + b1;
                    if (g.addend) {
                        const float* ap = g.addend + (size_t)r * N + colg;
                        v0 += ap[0]; v1 += ap[1];
                    }
                    if (g.relu) { v0 = fmaxf(v0, 0.f); v1 = fmaxf(v1, 0.f); }
                    if (g.C)
                        *(float2*)(g.C + (size_t)r * N + colg) = make_float2(v0, v1);
                    if (g.C16)
                        *(unsigned*)(g.C16 + (size_t)r * N + colg) = pack_f16x2(v0, v1);
                }
            }
        }
    }
}

// ---------------- CSR build ----------------
__global__ void count_edges(const int* __restrict__ src, const int* __restrict__ dst, int e) {
    int i = blockIdx.x * blockDim.x + threadIdx.x;
    if (i < e) {
        atomicAdd(&g_cnt_mi[src[i]], 1);
        atomicAdd(&g_cnt_di[dst[i]], 1);
    }
}

__global__ void scan_p1() {
    const int* cnt; int* rp; int* bsum; int n, b;
    if (blockIdx.x < NB_DI) {
        cnt = g_cnt_di; rp = g_rowptr_di; bsum = g_bsum_di; n = N_DI; b = blockIdx.x;
    } else {
        cnt = g_cnt_mi; rp = g_rowptr_mi; bsum = g_bsum_mi; n = N_MI; b = blockIdx.x - NB_DI;
    }
    __shared__ int warpsum[32];
    int tid = threadIdx.x, lane = tid & 31, wid = tid >> 5;
    int i = b * 1024 + tid;
    int v = (i < n) ? cnt[i] : 0;
    int x = v;
    #pragma unroll
    for (int off = 1; off < 32; off <<= 1) {
        int t = __shfl_up_sync(0xffffffffu, x, off);
        if (lane >= off) x += t;
    }
    if (lane == 31) warpsum[wid] = x;
    __syncthreads();
    if (wid == 0) {
        int w = warpsum[lane];
        #pragma unroll
        for (int off = 1; off < 32; off <<= 1) {
            int t = __shfl_up_sync(0xffffffffu, w, off);
            if (lane >= off) w += t;
        }
        warpsum[lane] = w;
    }
    __syncthreads();
    int excl = x - v + (wid ? warpsum[wid - 1] : 0);
    if (i < n) rp[i] = excl;
    if (tid == 0) bsum[b] = warpsum[31];
}

__global__ void scan_p2() {
    if (threadIdx.x == 0) {
        int run = 0;
        for (int i = 0; i < NB_DI; ++i) { int t = g_bsum_di[i]; g_bsum_di[i] = run; run += t; }
    }
    if (threadIdx.x == 1) {
        int run = 0;
        for (int i = 0; i < NB_MI; ++i) { int t = g_bsum_mi[i]; g_bsum_mi[i] = run; run += t; }
    }
}

__global__ void scan_p3() {
    int* rp; const int* bsum; int n, b;
    if (blockIdx.x < NB_DI) {
        rp = g_rowptr_di; bsum = g_bsum_di; n = N_DI; b = blockIdx.x;
    } else {
        rp = g_rowptr_mi; bsum = g_bsum_mi; n = N_MI; b = blockIdx.x - NB_DI;
    }
    int i = b * 1024 + threadIdx.x;
    if (i < n) rp[i] += bsum[b];
    if (b == 0 && threadIdx.x == 0) rp[n] = N_E;
}

__global__ void fill_edges(const int* __restrict__ src, const int* __restrict__ dst, int e) {
    int i = blockIdx.x * blockDim.x + threadIdx.x;
    if (i < e) {
        int s = src[i], d = dst[i];
        int pd = g_rowptr_di[d] + atomicAdd(&g_cnt_di[d], 1);
        g_col_di[pd] = s;
        int pm = g_rowptr_mi[s] + atomicAdd(&g_cnt_mi[s], 1);
        g_col_mi[pm] = d;
    }
}

// ---------------- merged aggregation kernels (di blocks first, then mi) ----------------
static constexpr int AG_DI = (N_DI + 7) / 8;
static constexpr int AG_MI = (N_MI + 7) / 8;

// L1: mean over fp32 src (stride 128), write fp16 out (width 128)
__global__ void agg_plain128_h(const float* __restrict__ x_d, __half* __restrict__ o_d,
                               const float* __restrict__ x_m, __half* __restrict__ o_m) {
    const float* x; __half* out; const int* rowptr; const int* col; int n, blk;
    if (blockIdx.x < AG_DI) {
        x = x_d; out = o_d; rowptr = g_rowptr_di; col = g_col_di; n = N_DI; blk = blockIdx.x;
    } else {
        x = x_m; out = o_m; rowptr = g_rowptr_mi; col = g_col_mi; n = N_MI; blk = blockIdx.x - AG_DI;
    }
    int warp = blk * 8 + (threadIdx.x >> 5);
    int lane = threadIdx.x & 31;
    if (warp >= n) return;
    int s = rowptr[warp], e = rowptr[warp + 1];
    float4 acc = make_float4(0.f, 0.f, 0.f, 0.f);
    int i = s;
    for (; i + 1 < e; i += 2) {
        float4 a = __ldg((const float4*)(x + (size_t)col[i] * 128) + lane);
        float4 b = __ldg((const float4*)(x + (size_t)col[i + 1] * 128) + lane);
        acc.x += a.x + b.x; acc.y += a.y + b.y;
        acc.z += a.z + b.z; acc.w += a.w + b.w;
    }
    if (i < e) {
        float4 a = __ldg((const float4*)(x + (size_t)col[i] * 128) + lane);
        acc.x += a.x; acc.y += a.y; acc.z += a.z; acc.w += a.w;
    }
    float inv = 1.f / fmaxf((float)(e - s), 1.f);
    uint2 o;
    o.x = pack_f16x2(acc.x * inv, acc.y * inv);
    o.y = pack_f16x2(acc.z * inv, acc.w * inv);
    ((uint2*)(out + (size_t)warp * 128))[lane] = o;
}

// L2: out16 = fp16(relu(mean(srcC[:,0:128]) + rootC[:,128:256])); src stride 256
__global__ void agg_fused128_h(const float* __restrict__ s_d, const float* __restrict__ r_d,
                               __half* __restrict__ o_d,
                               const float* __restrict__ s_m, const float* __restrict__ r_m,
                               __half* __restrict__ o_m) {
    const float *srcC, *rootC; __half* out; const int *rowptr, *col; int n, blk;
    if (blockIdx.x < AG_DI) {
        srcC = s_d; rootC = r_d; out = o_d; rowptr = g_rowptr_di; col = g_col_di; n = N_DI; blk = blockIdx.x;
    } else {
        srcC = s_m; rootC = r_m; out = o_m; rowptr = g_rowptr_mi; col = g_col_mi; n = N_MI; blk = blockIdx.x - AG_DI;
    }
    int warp = blk * 8 + (threadIdx.x >> 5);
    int lane = threadIdx.x & 31;
    if (warp >= n) return;
    int s = rowptr[warp], e = rowptr[warp + 1];
    float4 acc = make_float4(0.f, 0.f, 0.f, 0.f);
    int i = s;
    for (; i + 1 < e; i += 2) {
        float4 a = __ldg((const float4*)(srcC + (size_t)col[i] * 256) + lane);
        float4 b = __ldg((const float4*)(srcC + (size_t)col[i + 1] * 256) + lane);
        acc.x += a.x + b.x; acc.y += a.y + b.y;
        acc.z += a.z + b.z; acc.w += a.w + b.w;
    }
    if (i < e) {
        float4 a = __ldg((const float4*)(srcC + (size_t)col[i] * 256) + lane);
        acc.x += a.x; acc.y += a.y; acc.z += a.z; acc.w += a.w;
    }
    float inv = 1.f / fmaxf((float)(e - s), 1.f);
    float4 r = __ldg((const float4*)(rootC + (size_t)warp * 256 + 128) + lane);
    float v0 = fmaxf(acc.x * inv + r.x, 0.f);
    float v1 = fmaxf(acc.y * inv + r.y, 0.f);
    float v2 = fmaxf(acc.z * inv + r.z, 0.f);
    float v3 = fmaxf(acc.w * inv + r.w, 0.f);
    uint2 o;
    o.x = pack_f16x2(v0, v1);
    o.y = pack_f16x2(v2, v3);
    ((uint2*)(out + (size_t)warp * 128))[lane] = o;
}

// L3: out = mean(srcC[:,0:64]) + rootC[:,64:128]; fp32 out (width 64)
__global__ void agg_fused64_2(const float* __restrict__ s_d, const float* __restrict__ r_d,
                              float* __restrict__ o_d,
                              const float* __restrict__ s_m, const float* __restrict__ r_m,
                              float* __restrict__ o_m) {
    const float *srcC, *rootC; float* out; const int *rowptr, *col; int n, blk;
    if (blockIdx.x < AG_DI) {
        srcC = s_d; rootC = r_d; out = o_d; rowptr = g_rowptr_di; col = g_col_di; n = N_DI; blk = blockIdx.x;
    } else {
        srcC = s_m; rootC = r_m; out = o_m; rowptr = g_rowptr_mi; col = g_col_mi; n = N_MI; blk = blockIdx.x - AG_DI;
    }
    int warp = blk * 8 + (threadIdx.x >> 5);
    int lane = threadIdx.x & 31;
    if (warp >= n) return;
    int s = rowptr[warp], e = rowptr[warp + 1];
    float2 acc = make_float2(0.f, 0.f);
    int i = s;
    for (; i + 1 < e; i += 2) {
        float2 a = __ldg((const float2*)(srcC + (size_t)col[i] * 128) + lane);
        float2 b = __ldg((const float2*)(srcC + (size_t)col[i + 1] * 128) + lane);
        acc.x += a.x + b.x; acc.y += a.y + b.y;
    }
    if (i < e) {
        float2 a = __ldg((const float2*)(srcC + (size_t)col[i] * 128) + lane);
        acc.x += a.x; acc.y += a.y;
    }
    float inv = 1.f / fmaxf((float)(e - s), 1.f);
    float2 r = __ldg((const float2*)(rootC + (size_t)warp * 128 + 64) + lane);
    float2 v = make_float2(acc.x * inv + r.x, acc.y * inv + r.y);
    ((float2*)(out + (size_t)warp * 64))[lane] = v;
}

// ---------------- classifier ----------------
__global__ void dot64(const float* __restrict__ hmi, const float* __restrict__ hdi,
                      const int* __restrict__ lsrc, const int* __restrict__ ldst,
                      float* __restrict__ out, int L) {
    int warp = (blockIdx.x * blockDim.x + threadIdx.x) >> 5;
    int lane = threadIdx.x & 31;
    if (warp >= L) return;
    const float2* a = (const float2*)(hmi + (size_t)lsrc[warp] * 64);
    const float2* b = (const float2*)(hdi + (size_t)ldst[warp] * 64);
    float2 av = a[lane], bv = b[lane];
    float p = av.x * bv.x + av.y * bv.y;
    #pragma unroll
    for (int off = 16; off; off >>= 1) p += __shfl_down_sync(0xffffffffu, p, off);
    if (lane == 0) out[warp] = p;
}

// ---------------- host orchestration ----------------
static inline void gemm_pair(const GArgs& a, const GArgs& b) {
    int yb0 = (a.M + 63) / 64, yb1 = (b.M + 63) / 64;
    mma_gemm2<<<dim3(a.N / 64, yb0 + yb1), 256, GSMEM>>>(a, b, yb0);
}

extern "C" void kernel_launch(void* const* d_in, const int* in_sizes, int n_in,
                              void* d_out, int out_size) {
    const float* x_mi   = (const float*)d_in[0];
    const float* x_di   = (const float*)d_in[1];
    const float* W_mi   = (const float*)d_in[2];
    const float* b_mi   = (const float*)d_in[3];
    const float* W_di   = (const float*)d_in[4];
    const float* b_di   = (const float*)d_in[5];
    const float* emb_mi = (const float*)d_in[6];
    const float* emb_di = (const float*)d_in[7];
    const float *Wl[3][2], *bl[3][2], *Wr[3][2];   // [layer][0=md,1=dm]
    for (int i = 0; i < 3; ++i)
        for (int r = 0; r < 2; ++r) {
            int base = 8 + i * 6 + r * 3;
            Wl[i][r] = (const float*)d_in[base];
            bl[i][r] = (const float*)d_in[base + 1];
            Wr[i][r] = (const float*)d_in[base + 2];
        }
    const int* edge_src  = (const int*)d_in[26];
    const int* edge_dst  = (const int*)d_in[27];
    const int* label_src = (const int*)d_in[28];
    const int* label_dst = (const int*)d_in[29];
    float* out = (float*)d_out;

    cudaFuncSetAttribute(mma_gemm2, cudaFuncAttributeMaxDynamicSharedMemorySize, GSMEM);

    float *hA_mi, *hA_di, *t_mi, *t_di, *o_mi, *o_di;
    __half *x16_mi, *x16_di, *a16_mi, *a16_di, *b16_mi, *b16_di, *t16_mi, *t16_di;
    __half *whi, *wlo;
    int *cnt_di, *cnt_mi;
    cudaGetSymbolAddress((void**)&hA_mi, g_hA_mi);
    cudaGetSymbolAddress((void**)&hA_di, g_hA_di);
    cudaGetSymbolAddress((void**)&t_mi, g_t_mi);
    cudaGetSymbolAddress((void**)&t_di, g_t_di);
    cudaGetSymbolAddress((void**)&o_mi, g_o_mi);
    cudaGetSymbolAddress((void**)&o_di, g_o_di);
    cudaGetSymbolAddress((void**)&x16_mi, g_x16_mi);
    cudaGetSymbolAddress((void**)&x16_di, g_x16_di);
    cudaGetSymbolAddress((void**)&a16_mi, g_a16_mi);
    cudaGetSymbolAddress((void**)&a16_di, g_a16_di);
    cudaGetSymbolAddress((void**)&b16_mi, g_b16_mi);
    cudaGetSymbolAddress((void**)&b16_di, g_b16_di);
    cudaGetSymbolAddress((void**)&t16_mi, g_t16_mi);
    cudaGetSymbolAddress((void**)&t16_di, g_t16_di);
    cudaGetSymbolAddress((void**)&whi, g_whi);
    cudaGetSymbolAddress((void**)&wlo, g_wlo);
    cudaGetSymbolAddress((void**)&cnt_di, g_cnt_di);
    cudaGetSymbolAddress((void**)&cnt_mi, g_cnt_mi);

    // ---- weight offsets ----
    PSArgs ps;
    int woff[14];
    {
        const float* srcs[14] = {
            W_mi, W_di,
            Wl[0][0], Wr[0][0], Wl[0][1], Wr[0][1],
            Wl[1][0], Wr[1][0], Wl[1][1], Wr[1][1],
            Wl[2][0], Wr[2][0], Wl[2][1], Wr[2][1] };
        const int sizes[14] = {
            128 * 256, 128 * 128,
            256 * 128, 256 * 128, 256 * 128, 256 * 128,
            128 * 256, 128 * 256, 128 * 256, 128 * 256,
            64 * 128, 64 * 128, 64 * 128, 64 * 128 };
        int off = 0;
        for (int i = 0; i < 14; ++i) {
            ps.e[i] = { srcs[i], off, sizes[i] };
            woff[i] = off;
            off += sizes[i];
        }
    }
    auto WH = [&](int i) { return (const __half*)(whi + woff[i]); };
    auto WL = [&](int i) { return (const __half*)(wlo + woff[i]); };

    const int EB = (N_E + 255) / 256;

    // ---- pre-passes: weight split, activation convert, CSR build ----
    presplit<<<dim3(64, 14), 256>>>(ps);
    f32to16<<<dim3(256, 2), 256>>>(x_mi, x16_mi, N_MI * 256, x_di, x16_di, N_DI * 128);
    cudaMemsetAsync(cnt_di, 0, N_DI * sizeof(int));
    cudaMemsetAsync(cnt_mi, 0, N_MI * sizeof(int));
    count_edges<<<EB, 256>>>(edge_src, edge_dst, N_E);
    scan_p1<<<NB_DI + NB_MI, 1024>>>();
    scan_p2<<<1, 32>>>();
    scan_p3<<<NB_DI + NB_MI, 1024>>>();
    cudaMemsetAsync(cnt_di, 0, N_DI * sizeof(int));
    cudaMemsetAsync(cnt_mi, 0, N_MI * sizeof(int));
    fill_edges<<<EB, 256>>>(edge_src, edge_dst, N_E);

    // ---- input projections: hA = x @ W^T + b + emb (fp32 + fp16 shadow) ----
    gemm_pair(
        { x16_mi, nullptr, WH(0), WL(0), nullptr, nullptr, 0, b_mi, emb_mi,
          hA_mi, a16_mi, N_MI, 128, 256, 0 },
        { x16_di, nullptr, WH(1), WL(1), nullptr, nullptr, 0, b_di, emb_di,
          hA_di, a16_di, N_DI, 128, 128, 0 });

    // ---- Layer 1 (agg-first, 128 -> 256, relu), k-dual; out fp16 only ----
    agg_plain128_h<<<AG_DI + AG_MI, 256>>>(hA_mi, t16_di, hA_di, t16_mi);
    gemm_pair(
        { t16_di, a16_di, WH(2), WL(2), WH(3), WL(3), 0, bl[0][0], nullptr,
          nullptr, b16_di, N_DI, 256, 128, 1 },
        { t16_mi, a16_mi, WH(4), WL(4), WH(5), WL(5), 0, bl[0][1], nullptr,
          nullptr, b16_mi, N_MI, 256, 128, 1 });

    // ---- Layer 2 (fused transform+root, 256 -> 128, relu) ----
    gemm_pair(
        { b16_mi, nullptr, WH(6), WL(6), WH(9), WL(9), 128, bl[1][1], nullptr,
          t_mi, nullptr, N_MI, 256, 256, 0 },
        { b16_di, nullptr, WH(8), WL(8), WH(7), WL(7), 128, bl[1][0], nullptr,
          t_di, nullptr, N_DI, 256, 256, 0 });
    agg_fused128_h<<<AG_DI + AG_MI, 256>>>(t_mi, t_di, a16_di, t_di, t_mi, a16_mi);

    // ---- Layer 3 (fused transform+root, 128 -> 64, no relu) ----
    gemm_pair(
        { a16_mi, nullptr, WH(10), WL(10), WH(13), WL(13), 64, bl[2][1], nullptr,
          t_mi, nullptr, N_MI, 128, 128, 0 },
        { a16_di, nullptr, WH(12), WL(12), WH(11), WL(11), 64, bl[2][0], nullptr,
          t_di, nullptr, N_DI, 128, 128, 0 });
    agg_fused64_2<<<AG_DI + AG_MI, 256>>>(t_mi, t_di, o_di, t_di, t_mi, o_mi);

    // ---- classifier ----
    dot64<<<(N_L + 7) / 8, 256>>>(o_mi, o_di, label_src, label_dst, out, N_L);
}

// round 13
// speedup vs baseline: 1.5188x; 1.1223x over previous
#include <cuda_runtime.h>
#include <cuda_fp16.h>
#include <cstdint>

// ---------------- problem constants ----------------
#define N_MI   100000
#define N_DI   50000
#define N_E    500000
#define N_L    200000

static constexpr int NB_DI = (N_DI + 1023) / 1024;   // 49
static constexpr int NB_MI = (N_MI + 1023) / 1024;   // 98
static constexpr int WTOT = 344064;                  // total weight elements

// ---------------- device scratch ----------------
__device__ float g_o_mi[(size_t)N_MI * 64];          // final embeddings (fp32)
__device__ float g_o_di[(size_t)N_DI * 64];

__device__ __half g_x16_mi[(size_t)N_MI * 256];      // inputs, fp16
__device__ __half g_x16_di[(size_t)N_DI * 128];
__device__ __half g_a16_mi[(size_t)N_MI * 128];      // proj out / L2-agg out
__device__ __half g_a16_di[(size_t)N_DI * 128];
__device__ __half g_b16_mi[(size_t)N_MI * 256];      // L1 GEMM out
__device__ __half g_b16_di[(size_t)N_DI * 256];
__device__ __half g_t16_mi[(size_t)N_MI * 128];      // L1 agg out
__device__ __half g_t16_di[(size_t)N_DI * 128];
__device__ __half g_c16_mi[(size_t)N_MI * 256];      // L2/L3 GEMM outs
__device__ __half g_c16_di[(size_t)N_DI * 256];

__device__ __half g_whi[WTOT];
__device__ __half g_wlo[WTOT];

__device__ int g_rowptr_di[N_DI + 1];
__device__ int g_rowptr_mi[N_MI + 1];
__device__ int g_col_di[N_E];
__device__ int g_col_mi[N_E];
__device__ int g_cnt_di[N_DI];
__device__ int g_cnt_mi[N_MI];
__device__ int g_bsum_di[NB_DI];
__device__ int g_bsum_mi[NB_MI];

// ---------------- helpers ----------------
__device__ __forceinline__ uint32_t smem_u32(const void* p) {
    uint32_t a;
    asm("{ .reg .u64 t; cvta.to.shared.u64 t, %1; cvt.u32.u64 %0, t; }"
        : "=r"(a) : "l"(p));
    return a;
}

__device__ __forceinline__ unsigned pack_f16x2(float x0, float x1) {
    unsigned r;
    asm("cvt.rn.f16x2.f32 %0, %1, %2;" : "=r"(r) : "f"(x1), "f"(x0));
    return r;
}

__device__ __forceinline__ float2 h2f2(unsigned w) {
    return __half22float2(*(__half2*)&w);
}

__device__ __forceinline__ void mma_f16(float* c, const unsigned* a, unsigned b0, unsigned b1) {
    asm volatile(
        "mma.sync.aligned.m16n8k16.row.col.f32.f16.f16.f32 "
        "{%0,%1,%2,%3}, {%4,%5,%6,%7}, {%8,%9}, {%0,%1,%2,%3};"
        : "+f"(c[0]), "+f"(c[1]), "+f"(c[2]), "+f"(c[3])
        : "r"(a[0]), "r"(a[1]), "r"(a[2]), "r"(a[3]), "r"(b0), "r"(b1));
}

__device__ __forceinline__ void ldsm_x4(uint32_t addr, unsigned& r0, unsigned& r1,
                                        unsigned& r2, unsigned& r3) {
    asm volatile("ldmatrix.sync.aligned.m8n8.x4.shared.b16 {%0,%1,%2,%3}, [%4];"
                 : "=r"(r0), "=r"(r1), "=r"(r2), "=r"(r3) : "r"(addr));
}

#define STS128(addr, a, b, c, d) \
    asm volatile("st.shared.v4.b32 [%0], {%1,%2,%3,%4};" \
                 :: "r"(addr), "r"(a), "r"(b), "r"(c), "r"(d))

// ---------------- weight pre-split + activation convert ----------------
struct WEnt { const float* src; int off; int n; };
struct PSArgs { WEnt e[14]; };

__global__ void presplit(PSArgs a) {
    WEnt w = a.e[blockIdx.y];
    for (int i = blockIdx.x * blockDim.x + threadIdx.x; i < w.n;
         i += gridDim.x * blockDim.x) {
        float x = w.src[i];
        __half h = __float2half_rn(x);
        g_whi[w.off + i] = h;
        g_wlo[w.off + i] = __float2half_rn(x - __half2float(h));
    }
}

__global__ void f32to16(const float* __restrict__ s0, __half* __restrict__ d0, int n0,
                        const float* __restrict__ s1, __half* __restrict__ d1, int n1) {
    const float* s = blockIdx.y ? s1 : s0;
    __half* d      = blockIdx.y ? d1 : d0;
    int n          = blockIdx.y ? n1 : n0;
    int stride = gridDim.x * blockDim.x;
    for (int i = blockIdx.x * blockDim.x + threadIdx.x; i < n / 4; i += stride) {
        float4 v = ((const float4*)s)[i];
        uint2 o;
        o.x = pack_f16x2(v.x, v.y);
        o.y = pack_f16x2(v.z, v.w);
        ((uint2*)d)[i] = o;
    }
}

// ---------------- paired fp16 2-pass GEMM, BM=64 x BN=64, KC=64 ---------------------
// acc = A16 @ (Bhi + Blo)^T; A fp16 in gmem, B pre-split fp16.
// Epilogue writes fp16 C16 (+bias)(+fp32 addend), opt relu.
struct GArgs {
    const __half *A0, *A1;
    const __half *B0h, *B0l, *B1h, *B1l;
    int nsplit;
    const float *bias, *addend;
    __half* C16;
    int M, N, K, relu;
};

static constexpr uint32_t APL = 64 * 128;          // 8 KB plane (64 rows x 128B)
static constexpr uint32_t STAGE = 3 * APL;         // A, Bh, Bl = 24 KB
static constexpr int GSMEM = 2 * (int)STAGE + 128; // 49280 (2 stages)

__global__ void __launch_bounds__(256, 3) mma_gemm2(GArgs g0, GArgs g1, int yb0) {
    const GArgs& g = (blockIdx.y < (unsigned)yb0) ? g0 : g1;
    const int my = (blockIdx.y < (unsigned)yb0) ? blockIdx.y : blockIdx.y - yb0;

    extern __shared__ char smem_raw[];
    const uint32_t base = (smem_u32(smem_raw) + 127u) & ~127u;

    const int tid = threadIdx.x, lane = tid & 31, wid = tid >> 5;
    const int wm = wid & 1, wn = wid >> 1;          // warp tile 32(m) x 16(n)
    const int group = lane >> 2, tig = lane & 3;
    const int m0 = my * 64, n0 = blockIdx.x * 64;
    const int M = g.M, N = g.N, K = g.K;

    float acc[2][2][4];
    #pragma unroll
    for (int i = 0; i < 2; ++i)
        #pragma unroll
        for (int j = 0; j < 2; ++j)
            #pragma unroll
            for (int q = 0; q < 4; ++q) acc[i][j][q] = 0.f;

    const int kch = K >> 6;
    const bool kdual = (g.A1 != nullptr);
    const int nch = kdual ? 2 * kch : kch;

    uint4 ra16[2];
    const int arow[2] = { tid >> 3, (256 + tid) >> 3 };
    const int ach = tid & 7;

    auto prefetchA = [&](int c) {
        const int p = (c >= kch) ? 1 : 0;
        const int k0 = (c - p * kch) << 6;
        const __half* A = p ? g.A1 : g.A0;
        #pragma unroll
        for (int it = 0; it < 2; ++it) {
            int gr = m0 + arow[it];
            ra16[it] = (gr < M)
                ? *(const uint4*)(A + (size_t)gr * K + k0 + ach * 8)
                : make_uint4(0u, 0u, 0u, 0u);
        }
    };

    auto store_stage = [&](int st, int c) {
        const uint32_t sa  = base + (uint32_t)st * STAGE;
        const uint32_t sbh = sa + APL;
        const uint32_t sbl = sa + 2 * APL;
        #pragma unroll
        for (int it = 0; it < 2; ++it) {
            int r = arow[it];
            uint32_t off = (uint32_t)(r * 128 + ((ach ^ (r & 7)) << 4));
            STS128(sa + off, ra16[it].x, ra16[it].y, ra16[it].z, ra16[it].w);
        }
        const int p = (c >= kch) ? 1 : 0;
        const int k0 = (c - p * kch) << 6;
        #pragma unroll
        for (int it = 0; it < 2; ++it) {
            int r = arow[it];
            int gcol = n0 + r;
            const __half *bh, *bl;
            if (kdual) {
                bh = p ? g.B1h : g.B0h;
                bl = p ? g.B1l : g.B0l;
            } else if (g.nsplit > 0 && gcol >= g.nsplit) {
                bh = g.B1h; bl = g.B1l; gcol -= g.nsplit;
            } else {
                bh = g.B0h; bl = g.B0l;
            }
            size_t ro = (size_t)gcol * K + k0 + ach * 8;
            uint4 hv = *(const uint4*)(bh + ro);
            uint4 lv = *(const uint4*)(bl + ro);
            uint32_t off = (uint32_t)(r * 128 + ((ach ^ (r & 7)) << 4));
            STS128(sbh + off, hv.x, hv.y, hv.z, hv.w);
            STS128(sbl + off, lv.x, lv.y, lv.z, lv.w);
        }
    };

    auto mma_stage = [&](int st) {
        const uint32_t sa  = base + (uint32_t)st * STAGE;
        const uint32_t sbh = sa + APL;
        const uint32_t sbl = sa + 2 * APL;
        const int lrow = lane & 15, lsel = lane >> 4;
        #pragma unroll
        for (int s = 0; s < 4; ++s) {
            const int ch = 2 * s + lsel;
            unsigned bh[4], bl[4];
            {
                int r = wn * 16 + lrow;
                uint32_t off = (uint32_t)(r * 128 + ((ch ^ (r & 7)) << 4));
                ldsm_x4(sbh + off, bh[0], bh[1], bh[2], bh[3]);
                ldsm_x4(sbl + off, bl[0], bl[1], bl[2], bl[3]);
            }
            unsigned ah[2][4];
            #pragma unroll
            for (int i = 0; i < 2; ++i) {
                int r = wm * 32 + i * 16 + lrow;
                uint32_t off = (uint32_t)(r * 128 + ((ch ^ (r & 7)) << 4));
                ldsm_x4(sa + off, ah[i][0], ah[i][1], ah[i][2], ah[i][3]);
            }
            #pragma unroll
            for (int pass = 0; pass < 2; ++pass) {
                const unsigned* bf = pass ? bl : bh;
                #pragma unroll
                for (int i = 0; i < 2; ++i)
                    #pragma unroll
                    for (int j = 0; j < 2; ++j)
                        mma_f16(acc[i][j], ah[i], bf[j], bf[j + 2]);
            }
        }
    };

    prefetchA(0);
    store_stage(0, 0);
    __syncthreads();

    for (int c = 0; c < nch; ++c) {
        if (c + 1 < nch) prefetchA(c + 1);
        mma_stage(c & 1);
        if (c + 1 < nch) store_stage((c + 1) & 1, c + 1);
        __syncthreads();
    }

    // epilogue (fp16 out)
    #pragma unroll
    for (int i = 0; i < 2; ++i) {
        int row = m0 + wm * 32 + i * 16 + group;
        #pragma unroll
        for (int j = 0; j < 2; ++j) {
            int colg = n0 + wn * 16 + j * 8 + 2 * tig;
            float b0 = 0.f, b1 = 0.f;
            if (g.bias) {
                if (g.nsplit > 0 && !kdual) {
                    if (colg >= g.nsplit) {
                        b0 = __ldg(g.bias + colg - g.nsplit);
                        b1 = __ldg(g.bias + colg - g.nsplit + 1);
                    }
                } else {
                    b0 = __ldg(g.bias + colg);
                    b1 = __ldg(g.bias + colg + 1);
                }
            }
            #pragma unroll
            for (int h = 0; h < 2; ++h) {
                int r = row + 8 * h;
                if (r < M) {
                    float v0 = acc[i][j][2 * h] + b0, v1 = acc[i][j][2 * h + 1] + b1;
                    if (g.addend) {
                        const float* ap = g.addend + (size_t)r * N + colg;
                        v0 += ap[0]; v1 += ap[1];
                    }
                    if (g.relu) { v0 = fmaxf(v0, 0.f); v1 = fmaxf(v1, 0.f); }
                    *(unsigned*)(g.C16 + (size_t)r * N + colg) = pack_f16x2(v0, v1);
                }
            }
        }
    }
}

// ---------------- CSR build ----------------
__global__ void count_edges(const int* __restrict__ src, const int* __restrict__ dst, int e) {
    int i = blockIdx.x * blockDim.x + threadIdx.x;
    if (i < e) {
        atomicAdd(&g_cnt_mi[src[i]], 1);
        atomicAdd(&g_cnt_di[dst[i]], 1);
    }
}

__global__ void scan_p1() {
    const int* cnt; int* rp; int* bsum; int n, b;
    if (blockIdx.x < NB_DI) {
        cnt = g_cnt_di; rp = g_rowptr_di; bsum = g_bsum_di; n = N_DI; b = blockIdx.x;
    } else {
        cnt = g_cnt_mi; rp = g_rowptr_mi; bsum = g_bsum_mi; n = N_MI; b = blockIdx.x - NB_DI;
    }
    __shared__ int warpsum[32];
    int tid = threadIdx.x, lane = tid & 31, wid = tid >> 5;
    int i = b * 1024 + tid;
    int v = (i < n) ? cnt[i] : 0;
    int x = v;
    #pragma unroll
    for (int off = 1; off < 32; off <<= 1) {
        int t = __shfl_up_sync(0xffffffffu, x, off);
        if (lane >= off) x += t;
    }
    if (lane == 31) warpsum[wid] = x;
    __syncthreads();
    if (wid == 0) {
        int w = warpsum[lane];
        #pragma unroll
        for (int off = 1; off < 32; off <<= 1) {
            int t = __shfl_up_sync(0xffffffffu, w, off);
            if (lane >= off) w += t;
        }
        warpsum[lane] = w;
    }
    __syncthreads();
    int excl = x - v + (wid ? warpsum[wid - 1] : 0);
    if (i < n) rp[i] = excl;
    if (tid == 0) bsum[b] = warpsum[31];
}

__global__ void scan_p2() {
    if (threadIdx.x == 0) {
        int run = 0;
        for (int i = 0; i < NB_DI; ++i) { int t = g_bsum_di[i]; g_bsum_di[i] = run; run += t; }
    }
    if (threadIdx.x == 1) {
        int run = 0;
        for (int i = 0; i < NB_MI; ++i) { int t = g_bsum_mi[i]; g_bsum_mi[i] = run; run += t; }
    }
}

__global__ void scan_p3() {
    int* rp; const int* bsum; int n, b;
    if (blockIdx.x < NB_DI) {
        rp = g_rowptr_di; bsum = g_bsum_di; n = N_DI; b = blockIdx.x;
    } else {
        rp = g_rowptr_mi; bsum = g_bsum_mi; n = N_MI; b = blockIdx.x - NB_DI;
    }
    int i = b * 1024 + threadIdx.x;
    if (i < n) rp[i] += bsum[b];
    if (b == 0 && threadIdx.x == 0) rp[n] = N_E;
}

__global__ void fill_edges(const int* __restrict__ src, const int* __restrict__ dst, int e) {
    int i = blockIdx.x * blockDim.x + threadIdx.x;
    if (i < e) {
        int s = src[i], d = dst[i];
        int pd = g_rowptr_di[d] + atomicAdd(&g_cnt_di[d], 1);
        g_col_di[pd] = s;
        int pm = g_rowptr_mi[s] + atomicAdd(&g_cnt_mi[s], 1);
        g_col_mi[pm] = d;
    }
}

// ---------------- merged fp16 aggregation kernels (di first, then mi) ----------------
static constexpr int AG_DI = (N_DI + 7) / 8;
static constexpr int AG_MI = (N_MI + 7) / 8;

// accumulate uint2 (4 halves) into float4
__device__ __forceinline__ void acc4h(float4& acc, uint2 w) {
    float2 p0 = h2f2(w.x), p1 = h2f2(w.y);
    acc.x += p0.x; acc.y += p0.y; acc.z += p1.x; acc.w += p1.y;
}

// L1: gather fp16 width 128 stride 128, mean, write fp16 width 128
__global__ void agg_l1(const __half* __restrict__ x_d, __half* __restrict__ o_d,
                       const __half* __restrict__ x_m, __half* __restrict__ o_m) {
    const __half* x; __half* out; const int* rowptr; const int* col; int n, blk;
    if (blockIdx.x < AG_DI) {
        x = x_d; out = o_d; rowptr = g_rowptr_di; col = g_col_di; n = N_DI; blk = blockIdx.x;
    } else {
        x = x_m; out = o_m; rowptr = g_rowptr_mi; col = g_col_mi; n = N_MI; blk = blockIdx.x - AG_DI;
    }
    int warp = blk * 8 + (threadIdx.x >> 5);
    int lane = threadIdx.x & 31;
    if (warp >= n) return;
    int s = rowptr[warp], e = rowptr[warp + 1];
    float4 acc = make_float4(0.f, 0.f, 0.f, 0.f);
    int i = s;
    for (; i + 3 < e; i += 4) {
        uint2 a = __ldg((const uint2*)(x + (size_t)col[i] * 128) + lane);
        uint2 b = __ldg((const uint2*)(x + (size_t)col[i + 1] * 128) + lane);
        uint2 c = __ldg((const uint2*)(x + (size_t)col[i + 2] * 128) + lane);
        uint2 d = __ldg((const uint2*)(x + (size_t)col[i + 3] * 128) + lane);
        acc4h(acc, a); acc4h(acc, b); acc4h(acc, c); acc4h(acc, d);
    }
    for (; i < e; ++i)
        acc4h(acc, __ldg((const uint2*)(x + (size_t)col[i] * 128) + lane));
    float inv = 1.f / fmaxf((float)(e - s), 1.f);
    uint2 o;
    o.x = pack_f16x2(acc.x * inv, acc.y * inv);
    o.y = pack_f16x2(acc.z * inv, acc.w * inv);
    ((uint2*)(out + (size_t)warp * 128))[lane] = o;
}

// L2: gather srcC[:,0:128] (fp16 stride 256), mean + root srcR[:,128:256], relu, fp16 out
__global__ void agg_l2(const __half* __restrict__ s_d, const __half* __restrict__ r_d,
                       __half* __restrict__ o_d,
                       const __half* __restrict__ s_m, const __half* __restrict__ r_m,
                       __half* __restrict__ o_m) {
    const __half *srcC, *rootC; __half* out; const int *rowptr, *col; int n, blk;
    if (blockIdx.x < AG_DI) {
        srcC = s_d; rootC = r_d; out = o_d; rowptr = g_rowptr_di; col = g_col_di; n = N_DI; blk = blockIdx.x;
    } else {
        srcC = s_m; rootC = r_m; out = o_m; rowptr = g_rowptr_mi; col = g_col_mi; n = N_MI; blk = blockIdx.x - AG_DI;
    }
    int warp = blk * 8 + (threadIdx.x >> 5);
    int lane = threadIdx.x & 31;
    if (warp >= n) return;
    int s = rowptr[warp], e = rowptr[warp + 1];
    float4 acc = make_float4(0.f, 0.f, 0.f, 0.f);
    int i = s;
    for (; i + 3 < e; i += 4) {
        uint2 a = __ldg((const uint2*)(srcC + (size_t)col[i] * 256) + lane);
        uint2 b = __ldg((const uint2*)(srcC + (size_t)col[i + 1] * 256) + lane);
        uint2 c = __ldg((const uint2*)(srcC + (size_t)col[i + 2] * 256) + lane);
        uint2 d = __ldg((const uint2*)(srcC + (size_t)col[i + 3] * 256) + lane);
        acc4h(acc, a); acc4h(acc, b); acc4h(acc, c); acc4h(acc, d);
    }
    for (; i < e; ++i)
        acc4h(acc, __ldg((const uint2*)(srcC + (size_t)col[i] * 256) + lane));
    float inv = 1.f / fmaxf((float)(e - s), 1.f);
    uint2 rw = __ldg((const uint2*)(rootC + (size_t)warp * 256 + 128) + lane);
    float2 r0 = h2f2(rw.x), r1 = h2f2(rw.y);
    float v0 = fmaxf(acc.x * inv + r0.x, 0.f);
    float v1 = fmaxf(acc.y * inv + r0.y, 0.f);
    float v2 = fmaxf(acc.z * inv + r1.x, 0.f);
    float v3 = fmaxf(acc.w * inv + r1.y, 0.f);
    uint2 o;
    o.x = pack_f16x2(v0, v1);
    o.y = pack_f16x2(v2, v3);
    ((uint2*)(out + (size_t)warp * 128))[lane] = o;
}

// L3: gather srcC[:,0:64] (fp16 stride 128), mean + root srcR[:,64:128], fp32 out width 64
__global__ void agg_l3(const __half* __restrict__ s_d, const __half* __restrict__ r_d,
                       float* __restrict__ o_d,
                       const __half* __restrict__ s_m, const __half* __restrict__ r_m,
                       float* __restrict__ o_m) {
    const __half *srcC, *rootC; float* out; const int *rowptr, *col; int n, blk;
    if (blockIdx.x < AG_DI) {
        srcC = s_d; rootC = r_d; out = o_d; rowptr = g_rowptr_di; col = g_col_di; n = N_DI; blk = blockIdx.x;
    } else {
        srcC = s_m; rootC = r_m; out = o_m; rowptr = g_rowptr_mi; col = g_col_mi; n = N_MI; blk = blockIdx.x - AG_DI;
    }
    int warp = blk * 8 + (threadIdx.x >> 5);
    int lane = threadIdx.x & 31;
    if (warp >= n) return;
    int s = rowptr[warp], e = rowptr[warp + 1];
    float2 acc = make_float2(0.f, 0.f);
    int i = s;
    for (; i + 3 < e; i += 4) {
        unsigned a = __ldg((const unsigned*)(srcC + (size_t)col[i] * 128) + lane);
        unsigned b = __ldg((const unsigned*)(srcC + (size_t)col[i + 1] * 128) + lane);
        unsigned c = __ldg((const unsigned*)(srcC + (size_t)col[i + 2] * 128) + lane);
        unsigned d = __ldg((const unsigned*)(srcC + (size_t)col[i + 3] * 128) + lane);
        float2 p;
        p = h2f2(a); acc.x += p.x; acc.y += p.y;
        p = h2f2(b); acc.x += p.x; acc.y += p.y;
        p = h2f2(c); acc.x += p.x; acc.y += p.y;
        p = h2f2(d); acc.x += p.x; acc.y += p.y;
    }
    for (; i < e; ++i) {
        float2 p = h2f2(__ldg((const unsigned*)(srcC + (size_t)col[i] * 128) + lane));
        acc.x += p.x; acc.y += p.y;
    }
    float inv = 1.f / fmaxf((float)(e - s), 1.f);
    float2 r = h2f2(__ldg((const unsigned*)(rootC + (size_t)warp * 128 + 64) + lane));
    ((float2*)(out + (size_t)warp * 64))[lane] = make_float2(acc.x * inv + r.x, acc.y * inv + r.y);
}

// ---------------- classifier ----------------
__global__ void dot64(const float* __restrict__ hmi, const float* __restrict__ hdi,
                      const int* __restrict__ lsrc, const int* __restrict__ ldst,
                      float* __restrict__ out, int L) {
    int warp = (blockIdx.x * blockDim.x + threadIdx.x) >> 5;
    int lane = threadIdx.x & 31;
    if (warp >= L) return;
    const float2* a = (const float2*)(hmi + (size_t)lsrc[warp] * 64);
    const float2* b = (const float2*)(hdi + (size_t)ldst[warp] * 64);
    float2 av = a[lane], bv = b[lane];
    float p = av.x * bv.x + av.y * bv.y;
    #pragma unroll
    for (int off = 16; off; off >>= 1) p += __shfl_down_sync(0xffffffffu, p, off);
    if (lane == 0) out[warp] = p;
}

// ---------------- host orchestration ----------------
static inline void gemm_pair(const GArgs& a, const GArgs& b) {
    int yb0 = (a.M + 63) / 64, yb1 = (b.M + 63) / 64;
    mma_gemm2<<<dim3(a.N / 64, yb0 + yb1), 256, GSMEM>>>(a, b, yb0);
}

extern "C" void kernel_launch(void* const* d_in, const int* in_sizes, int n_in,
                              void* d_out, int out_size) {
    const float* x_mi   = (const float*)d_in[0];
    const float* x_di   = (const float*)d_in[1];
    const float* W_mi   = (const float*)d_in[2];
    const float* b_mi   = (const float*)d_in[3];
    const float* W_di   = (const float*)d_in[4];
    const float* b_di   = (const float*)d_in[5];
    const float* emb_mi = (const float*)d_in[6];
    const float* emb_di = (const float*)d_in[7];
    const float *Wl[3][2], *bl[3][2], *Wr[3][2];   // [layer][0=md,1=dm]
    for (int i = 0; i < 3; ++i)
        for (int r = 0; r < 2; ++r) {
            int base = 8 + i * 6 + r * 3;
            Wl[i][r] = (const float*)d_in[base];
            bl[i][r] = (const float*)d_in[base + 1];
            Wr[i][r] = (const float*)d_in[base + 2];
        }
    const int* edge_src  = (const int*)d_in[26];
    const int* edge_dst  = (const int*)d_in[27];
    const int* label_src = (const int*)d_in[28];
    const int* label_dst = (const int*)d_in[29];
    float* out = (float*)d_out;

    cudaFuncSetAttribute(mma_gemm2, cudaFuncAttributeMaxDynamicSharedMemorySize, GSMEM);

    float *o_mi, *o_di;
    __half *x16_mi, *x16_di, *a16_mi, *a16_di, *b16_mi, *b16_di;
    __half *t16_mi, *t16_di, *c16_mi, *c16_di, *whi, *wlo;
    int *cnt_di, *cnt_mi;
    cudaGetSymbolAddress((void**)&o_mi, g_o_mi);
    cudaGetSymbolAddress((void**)&o_di, g_o_di);
    cudaGetSymbolAddress((void**)&x16_mi, g_x16_mi);
    cudaGetSymbolAddress((void**)&x16_di, g_x16_di);
    cudaGetSymbolAddress((void**)&a16_mi, g_a16_mi);
    cudaGetSymbolAddress((void**)&a16_di, g_a16_di);
    cudaGetSymbolAddress((void**)&b16_mi, g_b16_mi);
    cudaGetSymbolAddress((void**)&b16_di, g_b16_di);
    cudaGetSymbolAddress((void**)&t16_mi, g_t16_mi);
    cudaGetSymbolAddress((void**)&t16_di, g_t16_di);
    cudaGetSymbolAddress((void**)&c16_mi, g_c16_mi);
    cudaGetSymbolAddress((void**)&c16_di, g_c16_di);
    cudaGetSymbolAddress((void**)&whi, g_whi);
    cudaGetSymbolAddress((void**)&wlo, g_wlo);
    cudaGetSymbolAddress((void**)&cnt_di, g_cnt_di);
    cudaGetSymbolAddress((void**)&cnt_mi, g_cnt_mi);

    // ---- weight offsets ----
    PSArgs ps;
    int woff[14];
    {
        const float* srcs[14] = {
            W_mi, W_di,
            Wl[0][0], Wr[0][0], Wl[0][1], Wr[0][1],
            Wl[1][0], Wr[1][0], Wl[1][1], Wr[1][1],
            Wl[2][0], Wr[2][0], Wl[2][1], Wr[2][1] };
        const int sizes[14] = {
            128 * 256, 128 * 128,
            256 * 128, 256 * 128, 256 * 128, 256 * 128,
            128 * 256, 128 * 256, 128 * 256, 128 * 256,
            64 * 128, 64 * 128, 64 * 128, 64 * 128 };
        int off = 0;
        for (int i = 0; i < 14; ++i) {
            ps.e[i] = { srcs[i], off, sizes[i] };
            woff[i] = off;
            off += sizes[i];
        }
    }
    auto WH = [&](int i) { return (const __half*)(whi + woff[i]); };
    auto WL = [&](int i) { return (const __half*)(wlo + woff[i]); };

    const int EB = (N_E + 255) / 256;

    // ---- pre-passes ----
    presplit<<<dim3(64, 14), 256>>>(ps);
    f32to16<<<dim3(256, 2), 256>>>(x_mi, x16_mi, N_MI * 256, x_di, x16_di, N_DI * 128);
    cudaMemsetAsync(cnt_di, 0, N_DI * sizeof(int));
    cudaMemsetAsync(cnt_mi, 0, N_MI * sizeof(int));
    count_edges<<<EB, 256>>>(edge_src, edge_dst, N_E);
    scan_p1<<<NB_DI + NB_MI, 1024>>>();
    scan_p2<<<1, 32>>>();
    scan_p3<<<NB_DI + NB_MI, 1024>>>();
    cudaMemsetAsync(cnt_di, 0, N_DI * sizeof(int));
    cudaMemsetAsync(cnt_mi, 0, N_MI * sizeof(int));
    fill_edges<<<EB, 256>>>(edge_src, edge_dst, N_E);

    // ---- input projections: a16 = fp16(x @ W^T + b + emb) ----
    gemm_pair(
        { x16_mi, nullptr, WH(0), WL(0), nullptr, nullptr, 0, b_mi, emb_mi,
          a16_mi, N_MI, 128, 256, 0 },
        { x16_di, nullptr, WH(1), WL(1), nullptr, nullptr, 0, b_di, emb_di,
          a16_di, N_DI, 128, 128, 0 });

    // ---- Layer 1 (agg-first, 128 -> 256, relu), k-dual ----
    agg_l1<<<AG_DI + AG_MI, 256>>>(a16_mi, t16_di, a16_di, t16_mi);
    gemm_pair(
        { t16_di, a16_di, WH(2), WL(2), WH(3), WL(3), 0, bl[0][0], nullptr,
          b16_di, N_DI, 256, 128, 1 },
        { t16_mi, a16_mi, WH(4), WL(4), WH(5), WL(5), 0, bl[0][1], nullptr,
          b16_mi, N_MI, 256, 128, 1 });

    // ---- Layer 2 (fused transform+root, 256 -> 128, relu) ----
    gemm_pair(
        { b16_mi, nullptr, WH(6), WL(6), WH(9), WL(9), 128, bl[1][1], nullptr,
          c16_mi, N_MI, 256, 256, 0 },
        { b16_di, nullptr, WH(8), WL(8), WH(7), WL(7), 128, bl[1][0], nullptr,
          c16_di, N_DI, 256, 256, 0 });
    agg_l2<<<AG_DI + AG_MI, 256>>>(c16_mi, c16_di, a16_di, c16_di, c16_mi, a16_mi);

    // ---- Layer 3 (fused transform+root, 128 -> 64, no relu) ----
    gemm_pair(
        { a16_mi, nullptr, WH(10), WL(10), WH(13), WL(13), 64, bl[2][1], nullptr,
          c16_mi, N_MI, 128, 128, 0 },
        { a16_di, nullptr, WH(12), WL(12), WH(11), WL(11), 64, bl[2][0], nullptr,
          c16_di, N_DI, 128, 128, 0 });
    agg_l3<<<AG_DI + AG_MI, 256>>>(c16_mi, c16_di, o_di, c16_di, c16_mi, o_mi);

    // ---- classifier ----
    dot64<<<(N_L + 7) / 8, 256>>>(o_mi, o_di, label_src, label_dst, out, N_L);
}

// round 14
// speedup vs baseline: 1.5727x; 1.0355x over previous
#include <cuda_runtime.h>
#include <cuda_fp16.h>
#include <cstdint>

// ---------------- problem constants ----------------
#define N_MI   100000
#define N_DI   50000
#define N_E    500000
#define N_L    200000

static constexpr int NB_DI = (N_DI + 1023) / 1024;   // 49
static constexpr int NB_MI = (N_MI + 1023) / 1024;   // 98
static constexpr int WTOT = 344064;                  // total weight elements
static constexpr int EB = (N_E + 255) / 256;         // edge blocks

// ---------------- device scratch ----------------
__device__ float g_o_mi[(size_t)N_MI * 64];          // final embeddings (fp32)
__device__ float g_o_di[(size_t)N_DI * 64];

__device__ __half g_x16_mi[(size_t)N_MI * 256];      // inputs, fp16
__device__ __half g_x16_di[(size_t)N_DI * 128];
__device__ __half g_a16_mi[(size_t)N_MI * 128];      // proj out / L2-agg out
__device__ __half g_a16_di[(size_t)N_DI * 128];
__device__ __half g_b16_mi[(size_t)N_MI * 256];      // L1 GEMM out
__device__ __half g_b16_di[(size_t)N_DI * 256];
__device__ __half g_t16_mi[(size_t)N_MI * 128];      // L1 agg out
__device__ __half g_t16_di[(size_t)N_DI * 128];
__device__ __half g_c16_mi[(size_t)N_MI * 256];      // L2/L3 GEMM outs
__device__ __half g_c16_di[(size_t)N_DI * 256];

__device__ __half g_whi[WTOT];
__device__ __half g_wlo[WTOT];

__device__ int g_rowptr_di[N_DI + 1];
__device__ int g_rowptr_mi[N_MI + 1];
__device__ int g_col_di[N_E];
__device__ int g_col_mi[N_E];
__device__ int g_cnt_di[N_DI];
__device__ int g_cnt_mi[N_MI];
__device__ int g_bsum_di[NB_DI];
__device__ int g_bsum_mi[NB_MI];

// ---------------- helpers ----------------
__device__ __forceinline__ uint32_t smem_u32(const void* p) {
    uint32_t a;
    asm("{ .reg .u64 t; cvta.to.shared.u64 t, %1; cvt.u32.u64 %0, t; }"
        : "=r"(a) : "l"(p));
    return a;
}

__device__ __forceinline__ unsigned pack_f16x2(float x0, float x1) {
    unsigned r;
    asm("cvt.rn.f16x2.f32 %0, %1, %2;" : "=r"(r) : "f"(x1), "f"(x0));
    return r;
}

__device__ __forceinline__ float2 h2f2(unsigned w) {
    return __half22float2(*(__half2*)&w);
}

__device__ __forceinline__ void mma_f16(float* c, const unsigned* a, unsigned b0, unsigned b1) {
    asm volatile(
        "mma.sync.aligned.m16n8k16.row.col.f32.f16.f16.f32 "
        "{%0,%1,%2,%3}, {%4,%5,%6,%7}, {%8,%9}, {%0,%1,%2,%3};"
        : "+f"(c[0]), "+f"(c[1]), "+f"(c[2]), "+f"(c[3])
        : "r"(a[0]), "r"(a[1]), "r"(a[2]), "r"(a[3]), "r"(b0), "r"(b1));
}

__device__ __forceinline__ void ldsm_x4(uint32_t addr, unsigned& r0, unsigned& r1,
                                        unsigned& r2, unsigned& r3) {
    asm volatile("ldmatrix.sync.aligned.m8n8.x4.shared.b16 {%0,%1,%2,%3}, [%4];"
                 : "=r"(r0), "=r"(r1), "=r"(r2), "=r"(r3) : "r"(addr));
}

#define STS128(addr, a, b, c, d) \
    asm volatile("st.shared.v4.b32 [%0], {%1,%2,%3,%4};" \
                 :: "r"(addr), "r"(a), "r"(b), "r"(c), "r"(d))

// ---------------- merged prep: presplit || f32to16 || count_edges ----------------
struct WEnt { const float* src; int off; int n; };
struct PSArgs { WEnt e[14]; };

__global__ void prep(PSArgs ps, const float* __restrict__ x_mi,
                     const float* __restrict__ x_di,
                     const int* __restrict__ esrc, const int* __restrict__ edst) {
    const int blk = blockIdx.x, tid = threadIdx.x;
    if (blk < 56) {
        // weight pre-split: 4 blocks per entry
        WEnt w = ps.e[blk >> 2];
        for (int i = (blk & 3) * 256 + tid; i < w.n; i += 1024) {
            float x = w.src[i];
            __half h = __float2half_rn(x);
            g_whi[w.off + i] = h;
            g_wlo[w.off + i] = __float2half_rn(x - __half2float(h));
        }
    } else if (blk < 56 + 512) {
        // activation fp32 -> fp16: 256 blocks per tensor
        int r = blk - 56;
        const float* s = (r < 256) ? x_mi : x_di;
        __half* d      = (r < 256) ? g_x16_mi : g_x16_di;
        int n4         = ((r < 256) ? N_MI * 256 : N_DI * 128) >> 2;
        for (int i = (r & 255) * 256 + tid; i < n4; i += 256 * 256) {
            float4 v = ((const float4*)s)[i];
            uint2 o;
            o.x = pack_f16x2(v.x, v.y);
            o.y = pack_f16x2(v.z, v.w);
            ((uint2*)d)[i] = o;
        }
    } else {
        // edge degree count
        int i = (blk - 568) * 256 + tid;
        if (i < N_E) {
            atomicAdd(&g_cnt_mi[esrc[i]], 1);
            atomicAdd(&g_cnt_di[edst[i]], 1);
        }
    }
}

// ---------------- CSR scans ----------------
__global__ void scan_p1() {
    const int* cnt; int* rp; int* bsum; int n, b;
    if (blockIdx.x < NB_DI) {
        cnt = g_cnt_di; rp = g_rowptr_di; bsum = g_bsum_di; n = N_DI; b = blockIdx.x;
    } else {
        cnt = g_cnt_mi; rp = g_rowptr_mi; bsum = g_bsum_mi; n = N_MI; b = blockIdx.x - NB_DI;
    }
    __shared__ int warpsum[32];
    int tid = threadIdx.x, lane = tid & 31, wid = tid >> 5;
    int i = b * 1024 + tid;
    int v = (i < n) ? cnt[i] : 0;
    int x = v;
    #pragma unroll
    for (int off = 1; off < 32; off <<= 1) {
        int t = __shfl_up_sync(0xffffffffu, x, off);
        if (lane >= off) x += t;
    }
    if (lane == 31) warpsum[wid] = x;
    __syncthreads();
    if (wid == 0) {
        int w = warpsum[lane];
        #pragma unroll
        for (int off = 1; off < 32; off <<= 1) {
            int t = __shfl_up_sync(0xffffffffu, w, off);
            if (lane >= off) w += t;
        }
        warpsum[lane] = w;
    }
    __syncthreads();
    int excl = x - v + (wid ? warpsum[wid - 1] : 0);
    if (i < n) rp[i] = excl;
    if (tid == 0) bsum[b] = warpsum[31];
}

// parallel exclusive scan of both block-sum arrays (<=128 each), 1 block x 128 thr
__global__ void scan_p2() {
    __shared__ int buf[2][128];
    int tid = threadIdx.x;
    int cur = 0;
    // di
    int v = (tid < NB_DI) ? g_bsum_di[tid] : 0;
    buf[cur][tid] = v;
    __syncthreads();
    #pragma unroll
    for (int off = 1; off < 128; off <<= 1) {
        int t = buf[cur][tid] + ((tid >= off) ? buf[cur][tid - off] : 0);
        buf[cur ^ 1][tid] = t;
        __syncthreads();
        cur ^= 1;
    }
    if (tid < NB_DI) g_bsum_di[tid] = buf[cur][tid] - v;
    __syncthreads();
    // mi
    int v2 = (tid < NB_MI) ? g_bsum_mi[tid] : 0;
    buf[cur][tid] = v2;
    __syncthreads();
    #pragma unroll
    for (int off = 1; off < 128; off <<= 1) {
        int t = buf[cur][tid] + ((tid >= off) ? buf[cur][tid - off] : 0);
        buf[cur ^ 1][tid] = t;
        __syncthreads();
        cur ^= 1;
    }
    if (tid < NB_MI) g_bsum_mi[tid] = buf[cur][tid] - v2;
}

// add block offsets; also re-zero cnt for the fill pass; set rowptr[n] = E
__global__ void scan_p3() {
    int* rp; const int* bsum; int* cnt; int n, b;
    if (blockIdx.x < NB_DI) {
        rp = g_rowptr_di; bsum = g_bsum_di; cnt = g_cnt_di; n = N_DI; b = blockIdx.x;
    } else {
        rp = g_rowptr_mi; bsum = g_bsum_mi; cnt = g_cnt_mi; n = N_MI; b = blockIdx.x - NB_DI;
    }
    int i = b * 1024 + threadIdx.x;
    if (i < n) {
        rp[i] += bsum[b];
        cnt[i] = 0;
    }
    if (b == 0 && threadIdx.x == 0) rp[n] = N_E;
}

// ---------------- paired fp16 2-pass GEMM (+ optional co-launched edge fill) -------
// acc = A16 @ (Bhi + Blo)^T; A fp16 in gmem, B pre-split fp16.
// Blocks with blockIdx.y >= ybTot perform fill_edges work instead (proj launch).
struct GArgs {
    const __half *A0, *A1;
    const __half *B0h, *B0l, *B1h, *B1l;
    int nsplit;
    const float *bias, *addend;
    __half* C16;
    int M, N, K, relu;
};

static constexpr uint32_t APL = 64 * 128;          // 8 KB plane (64 rows x 128B)
static constexpr uint32_t STAGE = 3 * APL;         // A, Bh, Bl = 24 KB
static constexpr int GSMEM = 2 * (int)STAGE + 128; // 49280 (2 stages)

__global__ void __launch_bounds__(256, 3) mma_gemm2(
    GArgs g0, GArgs g1, int yb0, int ybTot,
    const int* __restrict__ esrc, const int* __restrict__ edst, int fill_n) {

    // co-launched fill blocks
    if ((int)blockIdx.y >= ybTot) {
        int b = (blockIdx.y - ybTot) * gridDim.x + blockIdx.x;
        int i = b * 256 + threadIdx.x;
        if (i < fill_n) {
            int s = esrc[i], d = edst[i];
            int pd = g_rowptr_di[d] + atomicAdd(&g_cnt_di[d], 1);
            g_col_di[pd] = s;
            int pm = g_rowptr_mi[s] + atomicAdd(&g_cnt_mi[s], 1);
            g_col_mi[pm] = d;
        }
        return;
    }

    const GArgs& g = (blockIdx.y < (unsigned)yb0) ? g0 : g1;
    const int my = (blockIdx.y < (unsigned)yb0) ? blockIdx.y : blockIdx.y - yb0;

    extern __shared__ char smem_raw[];
    const uint32_t base = (smem_u32(smem_raw) + 127u) & ~127u;

    const int tid = threadIdx.x, lane = tid & 31, wid = tid >> 5;
    const int wm = wid & 1, wn = wid >> 1;          // warp tile 32(m) x 16(n)
    const int group = lane >> 2, tig = lane & 3;
    const int m0 = my * 64, n0 = blockIdx.x * 64;
    const int M = g.M, N = g.N, K = g.K;

    float acc[2][2][4];
    #pragma unroll
    for (int i = 0; i < 2; ++i)
        #pragma unroll
        for (int j = 0; j < 2; ++j)
            #pragma unroll
            for (int q = 0; q < 4; ++q) acc[i][j][q] = 0.f;

    const int kch = K >> 6;
    const bool kdual = (g.A1 != nullptr);
    const int nch = kdual ? 2 * kch : kch;

    uint4 ra16[2];
    const int arow[2] = { tid >> 3, (256 + tid) >> 3 };
    const int ach = tid & 7;

    auto prefetchA = [&](int c) {
        const int p = (c >= kch) ? 1 : 0;
        const int k0 = (c - p * kch) << 6;
        const __half* A = p ? g.A1 : g.A0;
        #pragma unroll
        for (int it = 0; it < 2; ++it) {
            int gr = m0 + arow[it];
            ra16[it] = (gr < M)
                ? *(const uint4*)(A + (size_t)gr * K + k0 + ach * 8)
                : make_uint4(0u, 0u, 0u, 0u);
        }
    };

    auto store_stage = [&](int st, int c) {
        const uint32_t sa  = base + (uint32_t)st * STAGE;
        const uint32_t sbh = sa + APL;
        const uint32_t sbl = sa + 2 * APL;
        #pragma unroll
        for (int it = 0; it < 2; ++it) {
            int r = arow[it];
            uint32_t off = (uint32_t)(r * 128 + ((ach ^ (r & 7)) << 4));
            STS128(sa + off, ra16[it].x, ra16[it].y, ra16[it].z, ra16[it].w);
        }
        const int p = (c >= kch) ? 1 : 0;
        const int k0 = (c - p * kch) << 6;
        #pragma unroll
        for (int it = 0; it < 2; ++it) {
            int r = arow[it];
            int gcol = n0 + r;
            const __half *bh, *bl;
            if (kdual) {
                bh = p ? g.B1h : g.B0h;
                bl = p ? g.B1l : g.B0l;
            } else if (g.nsplit > 0 && gcol >= g.nsplit) {
                bh = g.B1h; bl = g.B1l; gcol -= g.nsplit;
            } else {
                bh = g.B0h; bl = g.B0l;
            }
            size_t ro = (size_t)gcol * K + k0 + ach * 8;
            uint4 hv = *(const uint4*)(bh + ro);
            uint4 lv = *(const uint4*)(bl + ro);
            uint32_t off = (uint32_t)(r * 128 + ((ach ^ (r & 7)) << 4));
            STS128(sbh + off, hv.x, hv.y, hv.z, hv.w);
            STS128(sbl + off, lv.x, lv.y, lv.z, lv.w);
        }
    };

    auto mma_stage = [&](int st) {
        const uint32_t sa  = base + (uint32_t)st * STAGE;
        const uint32_t sbh = sa + APL;
        const uint32_t sbl = sa + 2 * APL;
        const int lrow = lane & 15, lsel = lane >> 4;
        #pragma unroll
        for (int s = 0; s < 4; ++s) {
            const int ch = 2 * s + lsel;
            unsigned bh[4], bl[4];
            {
                int r = wn * 16 + lrow;
                uint32_t off = (uint32_t)(r * 128 + ((ch ^ (r & 7)) << 4));
                ldsm_x4(sbh + off, bh[0], bh[1], bh[2], bh[3]);
                ldsm_x4(sbl + off, bl[0], bl[1], bl[2], bl[3]);
            }
            unsigned ah[2][4];
            #pragma unroll
            for (int i = 0; i < 2; ++i) {
                int r = wm * 32 + i * 16 + lrow;
                uint32_t off = (uint32_t)(r * 128 + ((ch ^ (r & 7)) << 4));
                ldsm_x4(sa + off, ah[i][0], ah[i][1], ah[i][2], ah[i][3]);
            }
            #pragma unroll
            for (int pass = 0; pass < 2; ++pass) {
                const unsigned* bf = pass ? bl : bh;
                #pragma unroll
                for (int i = 0; i < 2; ++i)
                    #pragma unroll
                    for (int j = 0; j < 2; ++j)
                        mma_f16(acc[i][j], ah[i], bf[j], bf[j + 2]);
            }
        }
    };

    prefetchA(0);
    store_stage(0, 0);
    __syncthreads();

    for (int c = 0; c < nch; ++c) {
        if (c + 1 < nch) prefetchA(c + 1);
        mma_stage(c & 1);
        if (c + 1 < nch) store_stage((c + 1) & 1, c + 1);
        __syncthreads();
    }

    // epilogue (fp16 out)
    #pragma unroll
    for (int i = 0; i < 2; ++i) {
        int row = m0 + wm * 32 + i * 16 + group;
        #pragma unroll
        for (int j = 0; j < 2; ++j) {
            int colg = n0 + wn * 16 + j * 8 + 2 * tig;
            float b0 = 0.f, b1 = 0.f;
            if (g.bias) {
                if (g.nsplit > 0 && !kdual) {
                    if (colg >= g.nsplit) {
                        b0 = __ldg(g.bias + colg - g.nsplit);
                        b1 = __ldg(g.bias + colg - g.nsplit + 1);
                    }
                } else {
                    b0 = __ldg(g.bias + colg);
                    b1 = __ldg(g.bias + colg + 1);
                }
            }
            #pragma unroll
            for (int h = 0; h < 2; ++h) {
                int r = row + 8 * h;
                if (r < M) {
                    float v0 = acc[i][j][2 * h] + b0, v1 = acc[i][j][2 * h + 1] + b1;
                    if (g.addend) {
                        const float* ap = g.addend + (size_t)r * N + colg;
                        v0 += ap[0]; v1 += ap[1];
                    }
                    if (g.relu) { v0 = fmaxf(v0, 0.f); v1 = fmaxf(v1, 0.f); }
                    *(unsigned*)(g.C16 + (size_t)r * N + colg) = pack_f16x2(v0, v1);
                }
            }
        }
    }
}

// ---------------- merged fp16 aggregation kernels (di first, then mi) ----------------
static constexpr int AG_DI = (N_DI + 7) / 8;
static constexpr int AG_MI = (N_MI + 7) / 8;

__device__ __forceinline__ void acc4h(float4& acc, uint2 w) {
    float2 p0 = h2f2(w.x), p1 = h2f2(w.y);
    acc.x += p0.x; acc.y += p0.y; acc.z += p1.x; acc.w += p1.y;
}

__global__ void agg_l1(const __half* __restrict__ x_d, __half* __restrict__ o_d,
                       const __half* __restrict__ x_m, __half* __restrict__ o_m) {
    const __half* x; __half* out; const int* rowptr; const int* col; int n, blk;
    if (blockIdx.x < AG_DI) {
        x = x_d; out = o_d; rowptr = g_rowptr_di; col = g_col_di; n = N_DI; blk = blockIdx.x;
    } else {
        x = x_m; out = o_m; rowptr = g_rowptr_mi; col = g_col_mi; n = N_MI; blk = blockIdx.x - AG_DI;
    }
    int warp = blk * 8 + (threadIdx.x >> 5);
    int lane = threadIdx.x & 31;
    if (warp >= n) return;
    int s = rowptr[warp], e = rowptr[warp + 1];
    float4 acc = make_float4(0.f, 0.f, 0.f, 0.f);
    int i = s;
    for (; i + 3 < e; i += 4) {
        uint2 a = __ldg((const uint2*)(x + (size_t)col[i] * 128) + lane);
        uint2 b = __ldg((const uint2*)(x + (size_t)col[i + 1] * 128) + lane);
        uint2 c = __ldg((const uint2*)(x + (size_t)col[i + 2] * 128) + lane);
        uint2 d = __ldg((const uint2*)(x + (size_t)col[i + 3] * 128) + lane);
        acc4h(acc, a); acc4h(acc, b); acc4h(acc, c); acc4h(acc, d);
    }
    for (; i < e; ++i)
        acc4h(acc, __ldg((const uint2*)(x + (size_t)col[i] * 128) + lane));
    float inv = 1.f / fmaxf((float)(e - s), 1.f);
    uint2 o;
    o.x = pack_f16x2(acc.x * inv, acc.y * inv);
    o.y = pack_f16x2(acc.z * inv, acc.w * inv);
    ((uint2*)(out + (size_t)warp * 128))[lane] = o;
}

__global__ void agg_l2(const __half* __restrict__ s_d, const __half* __restrict__ r_d,
                       __half* __restrict__ o_d,
                       const __half* __restrict__ s_m, const __half* __restrict__ r_m,
                       __half* __restrict__ o_m) {
    const __half *srcC, *rootC; __half* out; const int *rowptr, *col; int n, blk;
    if (blockIdx.x < AG_DI) {
        srcC = s_d; rootC = r_d; out = o_d; rowptr = g_rowptr_di; col = g_col_di; n = N_DI; blk = blockIdx.x;
    } else {
        srcC = s_m; rootC = r_m; out = o_m; rowptr = g_rowptr_mi; col = g_col_mi; n = N_MI; blk = blockIdx.x - AG_DI;
    }
    int warp = blk * 8 + (threadIdx.x >> 5);
    int lane = threadIdx.x & 31;
    if (warp >= n) return;
    int s = rowptr[warp], e = rowptr[warp + 1];
    float4 acc = make_float4(0.f, 0.f, 0.f, 0.f);
    int i = s;
    for (; i + 3 < e; i += 4) {
        uint2 a = __ldg((const uint2*)(srcC + (size_t)col[i] * 256) + lane);
        uint2 b = __ldg((const uint2*)(srcC + (size_t)col[i + 1] * 256) + lane);
        uint2 c = __ldg((const uint2*)(srcC + (size_t)col[i + 2] * 256) + lane);
        uint2 d = __ldg((const uint2*)(srcC + (size_t)col[i + 3] * 256) + lane);
        acc4h(acc, a); acc4h(acc, b); acc4h(acc, c); acc4h(acc, d);
    }
    for (; i < e; ++i)
        acc4h(acc, __ldg((const uint2*)(srcC + (size_t)col[i] * 256) + lane));
    float inv = 1.f / fmaxf((float)(e - s), 1.f);
    uint2 rw = __ldg((const uint2*)(rootC + (size_t)warp * 256 + 128) + lane);
    float2 r0 = h2f2(rw.x), r1 = h2f2(rw.y);
    float v0 = fmaxf(acc.x * inv + r0.x, 0.f);
    float v1 = fmaxf(acc.y * inv + r0.y, 0.f);
    float v2 = fmaxf(acc.z * inv + r1.x, 0.f);
    float v3 = fmaxf(acc.w * inv + r1.y, 0.f);
    uint2 o;
    o.x = pack_f16x2(v0, v1);
    o.y = pack_f16x2(v2, v3);
    ((uint2*)(out + (size_t)warp * 128))[lane] = o;
}

__global__ void agg_l3(const __half* __restrict__ s_d, const __half* __restrict__ r_d,
                       float* __restrict__ o_d,
                       const __half* __restrict__ s_m, const __half* __restrict__ r_m,
                       float* __restrict__ o_m) {
    const __half *srcC, *rootC; float* out; const int *rowptr, *col; int n, blk;
    if (blockIdx.x < AG_DI) {
        srcC = s_d; rootC = r_d; out = o_d; rowptr = g_rowptr_di; col = g_col_di; n = N_DI; blk = blockIdx.x;
    } else {
        srcC = s_m; rootC = r_m; out = o_m; rowptr = g_rowptr_mi; col = g_col_mi; n = N_MI; blk = blockIdx.x - AG_DI;
    }
    int warp = blk * 8 + (threadIdx.x >> 5);
    int lane = threadIdx.x & 31;
    if (warp >= n) return;
    int s = rowptr[warp], e = rowptr[warp + 1];
    float2 acc = make_float2(0.f, 0.f);
    int i = s;
    for (; i + 3 < e; i += 4) {
        unsigned a = __ldg((const unsigned*)(srcC + (size_t)col[i] * 128) + lane);
        unsigned b = __ldg((const unsigned*)(srcC + (size_t)col[i + 1] * 128) + lane);
        unsigned c = __ldg((const unsigned*)(srcC + (size_t)col[i + 2] * 128) + lane);
        unsigned d = __ldg((const unsigned*)(srcC + (size_t)col[i + 3] * 128) + lane);
        float2 p;
        p = h2f2(a); acc.x += p.x; acc.y += p.y;
        p = h2f2(b); acc.x += p.x; acc.y += p.y;
        p = h2f2(c); acc.x += p.x; acc.y += p.y;
        p = h2f2(d); acc.x += p.x; acc.y += p.y;
    }
    for (; i < e; ++i) {
        float2 p = h2f2(__ldg((const unsigned*)(srcC + (size_t)col[i] * 128) + lane));
        acc.x += p.x; acc.y += p.y;
    }
    float inv = 1.f / fmaxf((float)(e - s), 1.f);
    float2 r = h2f2(__ldg((const unsigned*)(rootC + (size_t)warp * 128 + 64) + lane));
    ((float2*)(out + (size_t)warp * 64))[lane] = make_float2(acc.x * inv + r.x, acc.y * inv + r.y);
}

// ---------------- classifier ----------------
__global__ void dot64(const float* __restrict__ hmi, const float* __restrict__ hdi,
                      const int* __restrict__ lsrc, const int* __restrict__ ldst,
                      float* __restrict__ out, int L) {
    int warp = (blockIdx.x * blockDim.x + threadIdx.x) >> 5;
    int lane = threadIdx.x & 31;
    if (warp >= L) return;
    const float2* a = (const float2*)(hmi + (size_t)lsrc[warp] * 64);
    const float2* b = (const float2*)(hdi + (size_t)ldst[warp] * 64);
    float2 av = a[lane], bv = b[lane];
    float p = av.x * bv.x + av.y * bv.y;
    #pragma unroll
    for (int off = 16; off; off >>= 1) p += __shfl_down_sync(0xffffffffu, p, off);
    if (lane == 0) out[warp] = p;
}

// ---------------- host orchestration ----------------
static inline void gemm_pair(const GArgs& a, const GArgs& b,
                             const int* esrc = nullptr, const int* edst = nullptr,
                             int fill_n = 0) {
    int yb0 = (a.M + 63) / 64, yb1 = (b.M + 63) / 64;
    int ybTot = yb0 + yb1;
    int gx = a.N / 64;
    int fy = fill_n ? (fill_n + gx * 256 - 1) / (gx * 256) : 0;
    mma_gemm2<<<dim3(gx, ybTot + fy), 256, GSMEM>>>(a, b, yb0, ybTot, esrc, edst, fill_n);
}

extern "C" void kernel_launch(void* const* d_in, const int* in_sizes, int n_in,
                              void* d_out, int out_size) {
    const float* x_mi   = (const float*)d_in[0];
    const float* x_di   = (const float*)d_in[1];
    const float* W_mi   = (const float*)d_in[2];
    const float* b_mi   = (const float*)d_in[3];
    const float* W_di   = (const float*)d_in[4];
    const float* b_di   = (const float*)d_in[5];
    const float* emb_mi = (const float*)d_in[6];
    const float* emb_di = (const float*)d_in[7];
    const float *Wl[3][2], *bl[3][2], *Wr[3][2];   // [layer][0=md,1=dm]
    for (int i = 0; i < 3; ++i)
        for (int r = 0; r < 2; ++r) {
            int base = 8 + i * 6 + r * 3;
            Wl[i][r] = (const float*)d_in[base];
            bl[i][r] = (const float*)d_in[base + 1];
            Wr[i][r] = (const float*)d_in[base + 2];
        }
    const int* edge_src  = (const int*)d_in[26];
    const int* edge_dst  = (const int*)d_in[27];
    const int* label_src = (const int*)d_in[28];
    const int* label_dst = (const int*)d_in[29];
    float* out = (float*)d_out;

    cudaFuncSetAttribute(mma_gemm2, cudaFuncAttributeMaxDynamicSharedMemorySize, GSMEM);

    float *o_mi, *o_di;
    __half *x16_mi, *x16_di, *a16_mi, *a16_di, *b16_mi, *b16_di;
    __half *t16_mi, *t16_di, *c16_mi, *c16_di, *whi, *wlo;
    int *cnt_di, *cnt_mi;
    cudaGetSymbolAddress((void**)&o_mi, g_o_mi);
    cudaGetSymbolAddress((void**)&o_di, g_o_di);
    cudaGetSymbolAddress((void**)&x16_mi, g_x16_mi);
    cudaGetSymbolAddress((void**)&x16_di, g_x16_di);
    cudaGetSymbolAddress((void**)&a16_mi, g_a16_mi);
    cudaGetSymbolAddress((void**)&a16_di, g_a16_di);
    cudaGetSymbolAddress((void**)&b16_mi, g_b16_mi);
    cudaGetSymbolAddress((void**)&b16_di, g_b16_di);
    cudaGetSymbolAddress((void**)&t16_mi, g_t16_mi);
    cudaGetSymbolAddress((void**)&t16_di, g_t16_di);
    cudaGetSymbolAddress((void**)&c16_mi, g_c16_mi);
    cudaGetSymbolAddress((void**)&c16_di, g_c16_di);
    cudaGetSymbolAddress((void**)&whi, g_whi);
    cudaGetSymbolAddress((void**)&wlo, g_wlo);
    cudaGetSymbolAddress((void**)&cnt_di, g_cnt_di);
    cudaGetSymbolAddress((void**)&cnt_mi, g_cnt_mi);

    // ---- weight offsets ----
    PSArgs ps;
    int woff[14];
    {
        const float* srcs[14] = {
            W_mi, W_di,
            Wl[0][0], Wr[0][0], Wl[0][1], Wr[0][1],
            Wl[1][0], Wr[1][0], Wl[1][1], Wr[1][1],
            Wl[2][0], Wr[2][0], Wl[2][1], Wr[2][1] };
        const int sizes[14] = {
            128 * 256, 128 * 128,
            256 * 128, 256 * 128, 256 * 128, 256 * 128,
            128 * 256, 128 * 256, 128 * 256, 128 * 256,
            64 * 128, 64 * 128, 64 * 128, 64 * 128 };
        int off = 0;
        for (int i = 0; i < 14; ++i) {
            ps.e[i] = { srcs[i], off, sizes[i] };
            woff[i] = off;
            off += sizes[i];
        }
    }
    auto WH = [&](int i) { return (const __half*)(whi + woff[i]); };
    auto WL = [&](int i) { return (const __half*)(wlo + woff[i]); };

    // ---- pre-passes: zero counts; merged presplit || f32to16 || count; scans ----
    cudaMemsetAsync(cnt_di, 0, N_DI * sizeof(int));
    cudaMemsetAsync(cnt_mi, 0, N_MI * sizeof(int));
    prep<<<568 + EB, 256>>>(ps, x_mi, x_di, edge_src, edge_dst);
    scan_p1<<<NB_DI + NB_MI, 1024>>>();
    scan_p2<<<1, 128>>>();
    scan_p3<<<NB_DI + NB_MI, 1024>>>();   // also re-zeros cnt for fill

    // ---- input projections (co-launched with edge fill) ----
    gemm_pair(
        { x16_mi, nullptr, WH(0), WL(0), nullptr, nullptr, 0, b_mi, emb_mi,
          a16_mi, N_MI, 128, 256, 0 },
        { x16_di, nullptr, WH(1), WL(1), nullptr, nullptr, 0, b_di, emb_di,
          a16_di, N_DI, 128, 128, 0 },
        edge_src, edge_dst, N_E);

    // ---- Layer 1 (agg-first, 128 -> 256, relu), k-dual ----
    agg_l1<<<AG_DI + AG_MI, 256>>>(a16_mi, t16_di, a16_di, t16_mi);
    gemm_pair(
        { t16_di, a16_di, WH(2), WL(2), WH(3), WL(3), 0, bl[0][0], nullptr,
          b16_di, N_DI, 256, 128, 1 },
        { t16_mi, a16_mi, WH(4), WL(4), WH(5), WL(5), 0, bl[0][1], nullptr,
          b16_mi, N_MI, 256, 128, 1 });

    // ---- Layer 2 (fused transform+root, 256 -> 128, relu) ----
    gemm_pair(
        { b16_mi, nullptr, WH(6), WL(6), WH(9), WL(9), 128, bl[1][1], nullptr,
          c16_mi, N_MI, 256, 256, 0 },
        { b16_di, nullptr, WH(8), WL(8), WH(7), WL(7), 128, bl[1][0], nullptr,
          c16_di, N_DI, 256, 256, 0 });
    agg_l2<<<AG_DI + AG_MI, 256>>>(c16_mi, c16_di, a16_di, c16_di, c16_mi, a16_mi);

    // ---- Layer 3 (fused transform+root, 128 -> 64, no relu) ----
    gemm_pair(
        { a16_mi, nullptr, WH(10), WL(10), WH(13), WL(13), 64, bl[2][1], nullptr,
          c16_mi, N_MI, 128, 128, 0 },
        { a16_di, nullptr, WH(12), WL(12), WH(11), WL(11), 64, bl[2][0], nullptr,
          c16_di, N_DI, 128, 128, 0 });
    agg_l3<<<AG_DI + AG_MI, 256>>>(c16_mi, c16_di, o_di, c16_di, c16_mi, o_mi);

    // ---- classifier ----
    dot64<<<(N_L + 7) / 8, 256>>>(o_mi, o_di, label_src, label_dst, out, N_L);
}